// round 9
// baseline (speedup 1.0000x reference)
#include <cuda_runtime.h>
#include <math.h>
#include <stdint.h>

// ---------------- problem constants ----------------
#define Bb   8
#define Cc   8
#define Ll   96000
#define Nfft 512
#define Winl 320
#define Hop  160
#define Fq   257
#define Tt   601
#define NS   64            // B*C sequences
#define ROWS (NS*Tt)       // 38464
#define KF   320           // nonzero window support
#define DD   514           // 2F
#define DDp  516           // padded (16B-aligned rows)
#define GG   512           // 4H
#define HH   128
#define NM   1028          // 2*DD     (mask1|mask2)
#define BT   (Bb*Tt)       // 4808
#define TWO_PI 6.28318530717958647692f
#define MAXCTA 296         // 148 SMs x 2 CTAs

typedef unsigned long long u64;

// ---------------- device scratch ----------------
__device__ float  d_win[Nfft];
__device__ float  d_xT[(size_t)Bb * Cc * Ll];   // channel-major input
__device__ float  d_Bspec[KF * DDp];            // windowed DFT matrix [320][514(+2)]
__device__ float  d_BW[KF * GG];                // Bspec @ W_ih^T  [320][512]
__device__ float  d_WihT[DD * GG];
__device__ float  d_biasxw[GG];
__device__ float  d_Wmask[HH * NM];
__device__ float  d_bmask[NM];
__device__ float  d_Emat[DD * Nfft];
__device__ float  d_frames[(size_t)ROWS * KF];
__device__ float  d_specT[(size_t)DD * ROWS];   // f-major spectra
__device__ float  d_xw[(size_t)ROWS * GG];      // LSTM input projections
__device__ float  d_h[(size_t)ROWS * HH];
__device__ float  d_masksT[(size_t)NM * ROWS];  // f-major masks
__device__ float2 d_psd_s[Bb * Fq * 64];
__device__ float2 d_psd_n[Bb * Fq * 64];
__device__ float2 d_wbeam[Bb * Fq * Cc];
__device__ float  d_enhT[(size_t)DD * BT];      // f-major beamformed spectrum
__device__ float  d_fout[(size_t)BT * Nfft];

__device__ __forceinline__ float2 cmulf(float2 a, float2 b) {
    return make_float2(a.x * b.x - a.y * b.y, a.x * b.y + a.y * b.x);
}
__device__ __forceinline__ float sigmf(float x) { return 1.0f / (1.0f + expf(-x)); }

// packed f32x2 helpers (sm_103a FFMA2 path)
__device__ __forceinline__ u64 pk2(float lo, float hi) {
    u64 r; asm("mov.b64 %0, {%1, %2};" : "=l"(r) : "f"(lo), "f"(hi)); return r;
}
__device__ __forceinline__ u64 fma2(u64 a, u64 b, u64 c) {
    u64 d; asm("fma.rn.f32x2 %0, %1, %2, %3;" : "=l"(d) : "l"(a), "l"(b), "l"(c)); return d;
}
__device__ __forceinline__ void upk2(u64 v, float& lo, float& hi) {
    asm("mov.b64 {%0, %1}, %2;" : "=f"(lo), "=f"(hi) : "l"(v));
}
union F4U { float4 f; u64 u[2]; };

// ---------------- input transpose: x[b][l][c] -> xT[b][c][l] ----------------
__global__ void __launch_bounds__(256)
k_xpose(const float* __restrict__ x)
{
    __shared__ float tile[8][257];
    int b = blockIdx.y;
    int l0 = blockIdx.x * 256;
    int tid = threadIdx.x;
    const float* p = x + ((size_t)b * Ll + l0 + tid) * Cc;
    float4 v0 = *(const float4*)p;
    float4 v1 = *(const float4*)(p + 4);
    tile[0][tid] = v0.x; tile[1][tid] = v0.y; tile[2][tid] = v0.z; tile[3][tid] = v0.w;
    tile[4][tid] = v1.x; tile[5][tid] = v1.y; tile[6][tid] = v1.z; tile[7][tid] = v1.w;
    __syncthreads();
#pragma unroll
    for (int c = 0; c < 8; c++)
        d_xT[((size_t)b * Cc + c) * Ll + l0 + tid] = tile[c][tid];
}

// ---------------- frame gather (reflect pad), coalesced from xT -------------
__global__ void k_frames()
{
    int m = blockIdx.x;           // n*T + t
    int n = m / Tt, t = m - n * Tt;
    int r = threadIdx.x;          // 0..319
    int q = t * Hop + r - 160;    // sample index before reflect
    if (q < 0) q = -q;
    else if (q >= Ll) q = 2 * Ll - 2 - q;
    d_frames[(size_t)m * KF + r] = d_xT[(size_t)n * Ll + q];
}

// Bspec: windowed DFT (window computed inline; rows always inside support)
__global__ void k_bspec() {
    int r = blockIdx.x;         // 0..319
    int c = threadIdx.x;        // 0..513
    if (c >= DD) return;
    int n = 96 + r;
    float w = 0.5f - 0.5f * cosf(TWO_PI * (float)r / (float)Winl);
    int k = (c < Fq) ? c : c - Fq;
    int m = (n * k) & (Nfft - 1);
    float th = (float)m * (TWO_PI / (float)Nfft);
    d_Bspec[r * DDp + c] = (c < Fq) ? w * cosf(th) : -w * sinf(th);
}

// ---------------- init kernels ----------------
__global__ void k_win() {
    int i = threadIdx.x;
    float v = 0.f;
    if (i >= 96 && i < 96 + Winl)
        v = 0.5f - 0.5f * cosf(TWO_PI * (float)(i - 96) / (float)Winl);
    d_win[i] = v;
}

__global__ void k_pack_wih(const float* __restrict__ W_ih,
                           const float* __restrict__ b_ih,
                           const float* __restrict__ b_hh) {
    int idx = blockIdx.x * blockDim.x + threadIdx.x;
    if (idx < GG) d_biasxw[idx] = b_ih[idx] + b_hh[idx];
    if (idx >= DD * GG) return;
    int d = idx >> 9, g = idx & 511;
    d_WihT[idx] = W_ih[g * DD + d];
}

__global__ void k_pack_wmask(const float* __restrict__ W1, const float* __restrict__ b1,
                             const float* __restrict__ W2, const float* __restrict__ b2) {
    int j = blockIdx.x;    // 0..1027
    int k = threadIdx.x;   // 0..127
    float v = (j < DD) ? W1[j * HH + k] : W2[(j - DD) * HH + k];
    d_Wmask[k * NM + j] = v;
    if (k == 0) d_bmask[j] = (j < DD) ? b1[j] : b2[j - DD];
}

// iRFFT matrix with synthesis window folded in. imag of DC/Nyquist ignored (c2r).
__global__ void k_emat() {
    int row = blockIdx.x;   // 0..513
    int n   = threadIdx.x;  // 0..511
    float w = d_win[n];
    float val;
    if (row < Fq) {
        int k = row;
        float ck = (k == 0 || k == Nfft / 2) ? 1.0f : 2.0f;
        int m = (k * n) & (Nfft - 1);
        val = ck * (1.0f / (float)Nfft) * cosf((float)m * (TWO_PI / (float)Nfft)) * w;
    } else {
        int k = row - Fq;
        if (k == 0 || k == Nfft / 2) val = 0.f;
        else {
            int m = (k * n) & (Nfft - 1);
            val = -(2.0f / (float)Nfft) * sinf((float)m * (TWO_PI / (float)Nfft)) * w;
        }
    }
    d_Emat[row * Nfft + n] = val;
}

// ---------------- SGEMM: 128x128 tile, dup-A smem, FFMA2, persistent --------
// TA=0: A[M][K] lda=k-stride.  TA=1: A stored [K][M], lda=m-stride.
// TC=0: C[M][N] row-major.     TC=1: C stored [N][M] (C^T), ldc=m-stride.
// smem: As2 duplicated [2][16][256] (value v at cols 2r,2r+1), Bs [2][16][128].
struct Frag { float4 a[2]; float4 b[2]; };

template <int TA>
__device__ __forceinline__ void gload(Frag& f, int tid, int M, int N, int K,
                                      const float* __restrict__ A, int lda,
                                      const float* __restrict__ B, int ldb,
                                      int by, int bx, int k0)
{
#pragma unroll
    for (int l = 0; l < 2; l++) {
        int idx = tid + l * 256;
        if (TA == 0) {
            int arow = idx & 127, ak = (idx >> 7) << 2;
            int gr = by * 128 + arow, gk = k0 + ak;
            const float* pA = A + (size_t)gr * lda + gk;
            if (gr < M && gk + 3 < K) {
                f.a[l] = *(const float4*)pA;
            } else {
                f.a[l].x = (gr < M && gk     < K) ? pA[0] : 0.f;
                f.a[l].y = (gr < M && gk + 1 < K) ? pA[1] : 0.f;
                f.a[l].z = (gr < M && gk + 2 < K) ? pA[2] : 0.f;
                f.a[l].w = (gr < M && gk + 3 < K) ? pA[3] : 0.f;
            }
        } else {
            int ak = idx >> 5, ar4 = (idx & 31) << 2;
            int gk = k0 + ak, gr = by * 128 + ar4;
            const float* pA = A + (size_t)gk * lda + gr;
            if (gk < K && gr + 3 < M) {
                f.a[l] = *(const float4*)pA;
            } else {
                f.a[l].x = (gk < K && gr     < M) ? pA[0] : 0.f;
                f.a[l].y = (gk < K && gr + 1 < M) ? pA[1] : 0.f;
                f.a[l].z = (gk < K && gr + 2 < M) ? pA[2] : 0.f;
                f.a[l].w = (gk < K && gr + 3 < M) ? pA[3] : 0.f;
            }
        }
        int bkk = idx >> 5, bc = (idx & 31) << 2;
        int gc = bx * 128 + bc, gkb = k0 + bkk;
        const float* pB = B + (size_t)gkb * ldb + gc;
        if (gkb < K && gc + 3 < N) {
            f.b[l] = *(const float4*)pB;
        } else {
            f.b[l].x = (gkb < K && gc     < N) ? pB[0] : 0.f;
            f.b[l].y = (gkb < K && gc + 1 < N) ? pB[1] : 0.f;
            f.b[l].z = (gkb < K && gc + 2 < N) ? pB[2] : 0.f;
            f.b[l].w = (gkb < K && gc + 3 < N) ? pB[3] : 0.f;
        }
    }
}

// As2 layout: (buf*16+k)*256 + col ; Bs layout: (buf*16+k)*128 + col
template <int TA>
__device__ __forceinline__ void sstore(const Frag& f, int tid, int buf,
                                       float* As2, float* Bsf)
{
#pragma unroll
    for (int l = 0; l < 2; l++) {
        int idx = tid + l * 256;
        if (TA == 0) {
            int arow = idx & 127, ak = (idx >> 7) << 2;
            float* base = As2 + (size_t)(buf * 16) * 256 + 2 * arow;
            *(float2*)(base + (ak + 0) * 256) = make_float2(f.a[l].x, f.a[l].x);
            *(float2*)(base + (ak + 1) * 256) = make_float2(f.a[l].y, f.a[l].y);
            *(float2*)(base + (ak + 2) * 256) = make_float2(f.a[l].z, f.a[l].z);
            *(float2*)(base + (ak + 3) * 256) = make_float2(f.a[l].w, f.a[l].w);
        } else {
            int ak = idx >> 5, ar4 = (idx & 31) << 2;
            float* base = As2 + (size_t)(buf * 16 + ak) * 256 + 2 * ar4;
            *(float2*)(base + 0) = make_float2(f.a[l].x, f.a[l].x);
            *(float2*)(base + 2) = make_float2(f.a[l].y, f.a[l].y);
            *(float2*)(base + 4) = make_float2(f.a[l].z, f.a[l].z);
            *(float2*)(base + 6) = make_float2(f.a[l].w, f.a[l].w);
        }
        int bkk = idx >> 5, bc = (idx & 31) << 2;
        *(float4*)(Bsf + (size_t)(buf * 16 + bkk) * 128 + bc) = f.b[l];
    }
}

template <int TA, int TC>
__global__ void __launch_bounds__(256, 2)
sgemm_t(int M, int N, int K,
        const float* __restrict__ A, int lda,
        const float* __restrict__ B, int ldb,
        float* __restrict__ C, int ldc,
        const float* __restrict__ bias)
{
    extern __shared__ float smembuf[];
    float* As2 = smembuf;                 // 2*16*256 = 8192 floats
    float* Bsf = smembuf + 8192;          // 2*16*128 = 4096 floats
    int tid = threadIdx.x;
    int tx = tid & 15, ty = tid >> 4;

    int ntx = (N + 127) >> 7, nty = (M + 127) >> 7;
    int ntiles = ntx * nty;
    int nk = (K + 15) >> 4;

    for (int tile = blockIdx.x; tile < ntiles; tile += gridDim.x) {
        int bx = tile % ntx, by = tile / ntx;
        __syncthreads();   // protect smem reuse across tiles

        u64 acc[8][4];
#pragma unroll
        for (int a = 0; a < 8; a++)
#pragma unroll
            for (int j = 0; j < 4; j++) acc[a][j] = pk2(0.f, 0.f);

        Frag f;
        gload<TA>(f, tid, M, N, K, A, lda, B, ldb, by, bx, 0);
        sstore<TA>(f, tid, 0, As2, Bsf);
        __syncthreads();

        for (int kt = 0; kt < nk; kt++) {
            int cur = kt & 1;
            if (kt + 1 < nk)
                gload<TA>(f, tid, M, N, K, A, lda, B, ldb, by, bx, (kt + 1) << 4);
#pragma unroll
            for (int k = 0; k < 16; k++) {
                const float* Ar = As2 + (size_t)(cur * 16 + k) * 256;
                const float* Br = Bsf + (size_t)(cur * 16 + k) * 128;
                F4U A0, A1, A2, A3, B0, B1;
                A0.f = *(const float4*)(Ar + ty * 8);
                A1.f = *(const float4*)(Ar + ty * 8 + 4);
                A2.f = *(const float4*)(Ar + 128 + ty * 8);
                A3.f = *(const float4*)(Ar + 128 + ty * 8 + 4);
                B0.f = *(const float4*)(Br + tx * 4);
                B1.f = *(const float4*)(Br + 64 + tx * 4);
                u64 pa[8] = {A0.u[0], A0.u[1], A1.u[0], A1.u[1],
                             A2.u[0], A2.u[1], A3.u[0], A3.u[1]};
#pragma unroll
                for (int a = 0; a < 8; a++) {
                    acc[a][0] = fma2(pa[a], B0.u[0], acc[a][0]);
                    acc[a][1] = fma2(pa[a], B0.u[1], acc[a][1]);
                    acc[a][2] = fma2(pa[a], B1.u[0], acc[a][2]);
                    acc[a][3] = fma2(pa[a], B1.u[1], acc[a][3]);
                }
            }
            if (kt + 1 < nk) {
                sstore<TA>(f, tid, 1 - cur, As2, Bsf);
                __syncthreads();
            }
        }

        if (TC == 0) {
#pragma unroll
            for (int a = 0; a < 8; a++) {
                int row = by * 128 + ((a & 4) << 4) + ty * 4 + (a & 3);
                if (row >= M) continue;
#pragma unroll
                for (int j = 0; j < 4; j++) {
                    float lo, hi;
                    upk2(acc[a][j], lo, hi);
                    int colb = bx * 128 + ((j >= 2) ? 64 : 0) + tx * 4 + (j & 1) * 2;
                    if (colb < N)     C[(size_t)row * ldc + colb]     = lo + (bias ? bias[colb]     : 0.f);
                    if (colb + 1 < N) C[(size_t)row * ldc + colb + 1] = hi + (bias ? bias[colb + 1] : 0.f);
                }
            }
        } else {
            // transposed-C epilogue: stage 128x64 halves in smem, write coalesced
            float* S = smembuf;   // 64*129 floats
            __syncthreads();
#pragma unroll
            for (int hh = 0; hh < 2; hh++) {
#pragma unroll
                for (int a = 0; a < 8; a++) {
                    int row = ((a & 4) << 4) + ty * 4 + (a & 3);
#pragma unroll
                    for (int jj = 0; jj < 2; jj++) {
                        int j = hh * 2 + jj;
                        float lo, hi;
                        upk2(acc[a][j], lo, hi);
                        int col = tx * 4 + jj * 2;
                        S[col * 129 + row]       = lo;
                        S[(col + 1) * 129 + row] = hi;
                    }
                }
                __syncthreads();
#pragma unroll
                for (int i = 0; i < 32; i++) {
                    int idx = tid + i * 256;
                    int col = idx >> 7, row = idx & 127;
                    int gcol = bx * 128 + hh * 64 + col;
                    int grow = by * 128 + row;
                    if (gcol < N && grow < M)
                        C[(size_t)gcol * ldc + grow] = S[col * 129 + row] + (bias ? bias[gcol] : 0.f);
                }
                __syncthreads();
            }
        }
    }
}

static inline int pgrid(int M, int N) {
    int t = ((M + 127) >> 7) * ((N + 127) >> 7);
    return t < MAXCTA ? t : MAXCTA;
}

// ---------------- LSTM: 64 persistent blocks, 512 threads, FFMA2 -------------
__global__ void __launch_bounds__(512, 1)
lstm_k(const float* __restrict__ W_hh)
{
    extern __shared__ float4 Wv2[];   // [16][512]: Wv2[i*512+g] = W_hh[g][64+4i..]
    __shared__ __align__(16) float h_s[128];
    __shared__ float g_s[512];
    int n = blockIdx.x, g = threadIdx.x;

    u64 wp[32];
#pragma unroll
    for (int i = 0; i < 16; i++) {
        float4 w4 = *(const float4*)(W_hh + (size_t)g * 128 + 4 * i);
        wp[2 * i]     = pk2(w4.x, w4.y);
        wp[2 * i + 1] = pk2(w4.z, w4.w);
    }
    for (int j = g; j < 16 * 512; j += 512) {
        int i = j >> 9, gg = j & 511;
        Wv2[j] = *(const float4*)(W_hh + (size_t)gg * 128 + 64 + 4 * i);
    }
    float cst = 0.f;
    if (g < 128) h_s[g] = 0.f;
    __syncthreads();

    const float* xwb  = d_xw + (size_t)n * Tt * GG;
    float*       hout = d_h  + (size_t)n * Tt * HH;
    const u64*   h2   = (const u64*)h_s;
    const u64*   wv2u = (const u64*)Wv2;

    float xnext = xwb[g];
    for (int t = 0; t < Tt; t++) {
        float xcur = xnext;
        if (t + 1 < Tt) xnext = xwb[(size_t)(t + 1) * GG + g];  // prefetch next step
        u64 c0 = pk2(xcur, 0.f);
        u64 c1 = pk2(0.f, 0.f), c2 = pk2(0.f, 0.f), c3 = pk2(0.f, 0.f);
#pragma unroll
        for (int i = 0; i < 32; i += 4) {
            c0 = fma2(wp[i],     h2[i],     c0);
            c1 = fma2(wp[i + 1], h2[i + 1], c1);
            c2 = fma2(wp[i + 2], h2[i + 2], c2);
            c3 = fma2(wp[i + 3], h2[i + 3], c3);
        }
#pragma unroll
        for (int i = 0; i < 16; i += 2) {
            c0 = fma2(wv2u[2 * (i * 512 + g)],           h2[32 + 2 * i],     c0);
            c1 = fma2(wv2u[2 * (i * 512 + g) + 1],       h2[32 + 2 * i + 1], c1);
            c2 = fma2(wv2u[2 * ((i + 1) * 512 + g)],     h2[32 + 2 * i + 2], c2);
            c3 = fma2(wv2u[2 * ((i + 1) * 512 + g) + 1], h2[32 + 2 * i + 3], c3);
        }
        float s0, s1, s2, s3, s4, s5, s6, s7;
        upk2(c0, s0, s1); upk2(c1, s2, s3); upk2(c2, s4, s5); upk2(c3, s6, s7);
        g_s[g] = ((s0 + s1) + (s2 + s3)) + ((s4 + s5) + (s6 + s7));
        __syncthreads();
        if (g < 128) {
            float iv = sigmf(g_s[g]);
            float fv = sigmf(g_s[128 + g]);
            float gv = tanhf(g_s[256 + g]);
            float ov = sigmf(g_s[384 + g]);
            cst = fv * cst + iv * gv;
            float hv = ov * tanhf(cst);
            h_s[g] = hv;
            hout[(size_t)t * HH + g] = hv;
        }
        __syncthreads();
    }
}

// ---------------- PSD: one block per (b,f), f-major coalesced loads ----------
__global__ void __launch_bounds__(256)
psd_k()
{
    int bf = blockIdx.x;
    int b = bf / Fq, f = bf - b * Fq;
    __shared__ float2 sv[8][33];
    __shared__ float2 nv[8][33];
    int tid = threadIdx.x;
    int cl = tid >> 5, ts = tid & 31;   // staging role
    int p = tid >> 2, sub = tid & 3;    // accumulate role
    int cc = p >> 3, ee = p & 7;
    float2 as = make_float2(0.f, 0.f), an = make_float2(0.f, 0.f);

    const float* sre  = d_specT  + (size_t)f * ROWS;
    const float* sim  = d_specT  + (size_t)(Fq + f) * ROWS;
    const float* m1re = d_masksT + (size_t)f * ROWS;
    const float* m1im = d_masksT + (size_t)(Fq + f) * ROWS;
    const float* m2re = d_masksT + (size_t)(DD + f) * ROWS;
    const float* m2im = d_masksT + (size_t)(DD + Fq + f) * ROWS;

    for (int t0 = 0; t0 < Tt; t0 += 32) {
        int t = t0 + ts;
        float2 svv = make_float2(0.f, 0.f), nvv = make_float2(0.f, 0.f);
        if (t < Tt) {
            size_t row = (size_t)(b * 8 + cl) * Tt + t;
            float2 s  = make_float2(sre[row],  sim[row]);
            float2 m1 = make_float2(m1re[row], m1im[row]);
            float2 m2 = make_float2(m2re[row], m2im[row]);
            svv = cmulf(m1, s);
            nvv = cmulf(m2, s);
        }
        sv[cl][ts] = svv;
        nv[cl][ts] = nvv;
        __syncthreads();
#pragma unroll
        for (int j = 0; j < 8; j++) {
            int q = sub * 8 + j;
            float2 a = sv[cc][q], bq = sv[ee][q];
            as.x += a.x * bq.x + a.y * bq.y;
            as.y += a.y * bq.x - a.x * bq.y;
            a = nv[cc][q]; bq = nv[ee][q];
            an.x += a.x * bq.x + a.y * bq.y;
            an.y += a.y * bq.x - a.x * bq.y;
        }
        __syncthreads();
    }
#pragma unroll
    for (int o = 2; o >= 1; o >>= 1) {
        as.x += __shfl_down_sync(0xffffffffu, as.x, o);
        as.y += __shfl_down_sync(0xffffffffu, as.y, o);
        an.x += __shfl_down_sync(0xffffffffu, an.x, o);
        an.y += __shfl_down_sync(0xffffffffu, an.y, o);
    }
    if (sub == 0) {
        float invT = 1.0f / (float)Tt;
        d_psd_s[(size_t)bf * 64 + p] = make_float2(as.x * invT, as.y * invT);
        d_psd_n[(size_t)bf * 64 + p] = make_float2(an.x * invT, an.y * invT);
    }
}

// ---------------- solve: 8x8 complex Gauss-Jordan, 32 systems/block -----------
#define ANm(i,j) mem[((i)*8+(j))*32 + tid]
#define ASm(i,j) mem[(64+(i)*8+(j))*32 + tid]
__global__ void __launch_bounds__(32)
solve_k()
{
    __shared__ float2 mem[128 * 32];
    int tid = threadIdx.x;
    int sys = blockIdx.x * 32 + tid;
    if (sys >= Bb * Fq) return;

    for (int e = 0; e < 64; e++) {
        mem[e * 32 + tid]        = d_psd_n[(size_t)sys * 64 + e];
        mem[(64 + e) * 32 + tid] = d_psd_s[(size_t)sys * 64 + e];
    }
    float tr = 0.f;
    for (int i = 0; i < 8; i++) tr += ANm(i, i).x;
    float lam = 1e-6f * tr / 8.0f + 1e-8f;
    for (int i = 0; i < 8; i++) ANm(i, i).x += lam;
    for (int p = 0; p < 8; p++) {
        float2 piv = ANm(p, p);
        float dinv = 1.0f / (piv.x * piv.x + piv.y * piv.y);
        float2 ip = make_float2(piv.x * dinv, -piv.y * dinv);
        for (int j = 0; j < 8; j++) {
            ANm(p, j) = cmulf(ANm(p, j), ip);
            ASm(p, j) = cmulf(ASm(p, j), ip);
        }
        for (int r = 0; r < 8; r++) {
            if (r == p) continue;
            float2 fct = ANm(r, p);
            for (int j = 0; j < 8; j++) {
                float2 t1 = cmulf(fct, ANm(p, j));
                float2 t2 = cmulf(fct, ASm(p, j));
                ANm(r, j).x -= t1.x; ANm(r, j).y -= t1.y;
                ASm(r, j).x -= t2.x; ASm(r, j).y -= t2.y;
            }
        }
    }
    float2 tr2 = make_float2(1e-8f, 0.f);
    for (int i = 0; i < 8; i++) {
        tr2.x += ASm(i, i).x;
        tr2.y += ASm(i, i).y;
    }
    float dinv = 1.0f / (tr2.x * tr2.x + tr2.y * tr2.y);
    float2 itr = make_float2(tr2.x * dinv, -tr2.y * dinv);
    for (int c = 0; c < 8; c++) {
        float2 wv = cmulf(ASm(c, 0), itr);
        d_wbeam[(size_t)sys * 8 + c] = make_float2(wv.x, -wv.y);   // store conj(w)
    }
}

// ---------------- beamform: block per (b,f), coalesced over t ----------------
__global__ void __launch_bounds__(256)
beam_k()
{
    int bf = blockIdx.x;
    int b = bf / Fq, f = bf - b * Fq;
    const float2* w = d_wbeam + (size_t)bf * 8;
    float2 wc[8];
#pragma unroll
    for (int c = 0; c < 8; c++) wc[c] = w[c];
    const float* sre = d_specT + (size_t)f * ROWS;
    const float* sim = d_specT + (size_t)(Fq + f) * ROWS;
    for (int t = threadIdx.x; t < Tt; t += 256) {
        float2 acc = make_float2(0.f, 0.f);
#pragma unroll
        for (int c = 0; c < 8; c++) {
            size_t row = (size_t)(b * 8 + c) * Tt + t;
            float2 s = make_float2(sre[row], sim[row]);
            acc.x += wc[c].x * s.x - wc[c].y * s.y;
            acc.y += wc[c].x * s.y + wc[c].y * s.x;
        }
        d_enhT[(size_t)f * BT + b * Tt + t]        = acc.x;
        d_enhT[(size_t)(Fq + f) * BT + b * Tt + t] = acc.y;
    }
}

// ---------------- overlap-add + normalization + crop ----------------
__global__ void k_ola(float* __restrict__ out)
{
    int idx = blockIdx.x * blockDim.x + threadIdx.x;
    if (idx >= Bb * Ll) return;
    int b = idx / Ll, l = idx - b * Ll;
    int p = l + 256;
    int tmin = (p >= Nfft) ? (p - Nfft) / Hop + 1 : 0;
    int tmax = p / Hop; if (tmax > Tt - 1) tmax = Tt - 1;
    float acc = 0.f, wsq = 0.f;
    for (int t = tmin; t <= tmax; t++) {
        int n = p - t * Hop;     // 0..511
        float wv = d_win[n];
        acc += d_fout[((size_t)b * Tt + t) * Nfft + n];
        wsq += wv * wv;
    }
    out[idx] = acc / fmaxf(wsq, 1e-11f);
}

// ---------------- launch ----------------
extern "C" void kernel_launch(void* const* d_in, const int* in_sizes, int n_in,
                              void* d_out, int out_size)
{
    const float* x    = (const float*)d_in[0];
    const float* W_ih = (const float*)d_in[1];
    const float* W_hh = (const float*)d_in[2];
    const float* b_ih = (const float*)d_in[3];
    const float* b_hh = (const float*)d_in[4];
    const float* W1   = (const float*)d_in[5];
    const float* b1   = (const float*)d_in[6];
    const float* W2   = (const float*)d_in[7];
    const float* b2   = (const float*)d_in[8];
    float* out = (float*)d_out;

    cudaFuncSetAttribute(lstm_k, cudaFuncAttributeMaxDynamicSharedMemorySize, 131072);
    const int GS = 12288 * 4;   // 49152 B dyn smem (dup-A + B, double-buffered)

    float *pBspec, *pBW, *pWihT, *pBiasxw, *pWmask, *pBmask, *pEmat;
    float *pFrames, *pSpecT, *pXw, *pH, *pMasksT, *pEnhT, *pFout;
    cudaGetSymbolAddress((void**)&pBspec,  d_Bspec);
    cudaGetSymbolAddress((void**)&pBW,     d_BW);
    cudaGetSymbolAddress((void**)&pWihT,   d_WihT);
    cudaGetSymbolAddress((void**)&pBiasxw, d_biasxw);
    cudaGetSymbolAddress((void**)&pWmask,  d_Wmask);
    cudaGetSymbolAddress((void**)&pBmask,  d_bmask);
    cudaGetSymbolAddress((void**)&pEmat,   d_Emat);
    cudaGetSymbolAddress((void**)&pFrames, d_frames);
    cudaGetSymbolAddress((void**)&pSpecT,  d_specT);
    cudaGetSymbolAddress((void**)&pXw,     d_xw);
    cudaGetSymbolAddress((void**)&pH,      d_h);
    cudaGetSymbolAddress((void**)&pMasksT, d_masksT);
    cudaGetSymbolAddress((void**)&pEnhT,   d_enhT);
    cudaGetSymbolAddress((void**)&pFout,   d_fout);

    {   // 0: input transpose
        dim3 grid(Ll / 256, Bb);
        k_xpose<<<grid, 256>>>(x);
    }
    k_frames<<<ROWS, KF>>>();                                  // 1
    k_bspec<<<KF, DD>>>();                                     // 2
    // 3: GEMM1a: specT[514][ROWS] = (frames @ Bspec)^T   (in ncu capture slot)
    sgemm_t<0, 1><<<pgrid(ROWS, DD), 256, GS>>>(ROWS, DD, KF, pFrames, KF, pBspec, DDp, pSpecT, ROWS, nullptr);
    k_pack_wih<<<(DD * GG + 255) / 256, 256>>>(W_ih, b_ih, b_hh);   // 4
    // 5: GEMM0: BW[320,512] = Bspec[320,514] @ WihT[514,512]
    sgemm_t<0, 0><<<pgrid(KF, GG), 256, GS>>>(KF, GG, DD, pBspec, DDp, pWihT, GG, pBW, GG, nullptr);
    // 6: GEMM1b: xw[ROWS][512] = frames @ BW + bias
    sgemm_t<0, 0><<<pgrid(ROWS, GG), 256, GS>>>(ROWS, GG, KF, pFrames, KF, pBW, GG, pXw, GG, pBiasxw);
    lstm_k<<<NS, 512, 131072>>>(W_hh);                         // 7
    k_win<<<1, Nfft>>>();                                      // 8
    k_pack_wmask<<<NM, HH>>>(W1, b1, W2, b2);                  // 9
    // 10: GEMM2: masksT[1028][ROWS] = (h @ Wmask + bmask)^T
    sgemm_t<0, 1><<<pgrid(ROWS, NM), 256, GS>>>(ROWS, NM, HH, pH, HH, pWmask, NM, pMasksT, ROWS, pBmask);
    k_emat<<<DD, Nfft>>>();                                    // 11
    psd_k<<<Bb * Fq, 256>>>();                                 // 12
    solve_k<<<(Bb * Fq + 31) / 32, 32>>>();                    // 13
    beam_k<<<Bb * Fq, 256>>>();                                // 14
    // 15: GEMM3: fout[4808,512] = enhT^T[4808,514] @ Emat[514,512]
    sgemm_t<1, 0><<<pgrid(BT, Nfft), 256, GS>>>(BT, Nfft, DD, pEnhT, BT, pEmat, Nfft, pFout, Nfft, nullptr);
    k_ola<<<(Bb * Ll + 255) / 256, 256>>>(out);                // 16
}

// round 11
// speedup vs baseline: 1.0261x; 1.0261x over previous
#include <cuda_runtime.h>
#include <math.h>
#include <stdint.h>

// ---------------- problem constants ----------------
#define Bb   8
#define Cc   8
#define Ll   96000
#define Nfft 512
#define Winl 320
#define Hop  160
#define Fq   257
#define Tt   601
#define NS   64            // B*C sequences
#define ROWS (NS*Tt)       // 38464
#define KF   320           // nonzero window support
#define DD   514           // 2F
#define DDp  516           // padded (16B-aligned rows)
#define GG   512           // 4H
#define HH   128
#define NM   1028          // 2*DD     (mask1|mask2)
#define BT   (Bb*Tt)       // 4808
#define TWO_PI 6.28318530717958647692f
#define MAXCTA 148         // 1 CTA/SM (high-reg GEMM)

typedef unsigned long long u64;

// ---------------- device scratch ----------------
__device__ float  d_win[Nfft];
__device__ float  d_xT[(size_t)Bb * Cc * Ll];   // channel-major input
__device__ float  d_Bspec[KF * DDp];            // windowed DFT matrix [320][514(+2)]
__device__ float  d_BW[KF * GG];                // Bspec @ W_ih^T  [320][512]
__device__ float  d_WihT[DD * GG];
__device__ float  d_biasxw[GG];
__device__ float  d_Wmask[HH * NM];
__device__ float  d_bmask[NM];
__device__ float  d_Emat[DD * Nfft];
__device__ float  d_frames[(size_t)ROWS * KF];
__device__ float  d_specT[(size_t)DD * ROWS];   // f-major spectra
__device__ float  d_xw[(size_t)ROWS * GG];      // LSTM input projections
__device__ float  d_h[(size_t)ROWS * HH];
__device__ float  d_masksT[(size_t)NM * ROWS];  // f-major masks
__device__ float2 d_psd_s[Bb * Fq * 64];
__device__ float2 d_psd_n[Bb * Fq * 64];
__device__ float2 d_wbeam[Bb * Fq * Cc];
__device__ float  d_enhT[(size_t)DD * BT];      // f-major beamformed spectrum
__device__ float  d_fout[(size_t)BT * Nfft];

__device__ __forceinline__ float2 cmulf(float2 a, float2 b) {
    return make_float2(a.x * b.x - a.y * b.y, a.x * b.y + a.y * b.x);
}
__device__ __forceinline__ float sigmf(float x) { return 1.0f / (1.0f + expf(-x)); }

// packed f32x2 helpers (sm_103a FFMA2 path)
__device__ __forceinline__ u64 pk2(float lo, float hi) {
    u64 r; asm("mov.b64 %0, {%1, %2};" : "=l"(r) : "f"(lo), "f"(hi)); return r;
}
__device__ __forceinline__ u64 fma2(u64 a, u64 b, u64 c) {
    u64 d; asm("fma.rn.f32x2 %0, %1, %2, %3;" : "=l"(d) : "l"(a), "l"(b), "l"(c)); return d;
}
__device__ __forceinline__ void upk2(u64 v, float& lo, float& hi) {
    asm("mov.b64 {%0, %1}, %2;" : "=f"(lo), "=f"(hi) : "l"(v));
}
union F4U { float4 f; u64 u[2]; };

// ---------------- input transpose: x[b][l][c] -> xT[b][c][l] ----------------
__global__ void __launch_bounds__(256)
k_xpose(const float* __restrict__ x)
{
    __shared__ float tile[8][257];
    int b = blockIdx.y;
    int l0 = blockIdx.x * 256;
    int tid = threadIdx.x;
    const float* p = x + ((size_t)b * Ll + l0 + tid) * Cc;
    float4 v0 = *(const float4*)p;
    float4 v1 = *(const float4*)(p + 4);
    tile[0][tid] = v0.x; tile[1][tid] = v0.y; tile[2][tid] = v0.z; tile[3][tid] = v0.w;
    tile[4][tid] = v1.x; tile[5][tid] = v1.y; tile[6][tid] = v1.z; tile[7][tid] = v1.w;
    __syncthreads();
#pragma unroll
    for (int c = 0; c < 8; c++)
        d_xT[((size_t)b * Cc + c) * Ll + l0 + tid] = tile[c][tid];
}

// ---------------- frame gather (reflect pad), coalesced from xT -------------
__global__ void k_frames()
{
    int m = blockIdx.x;           // n*T + t
    int n = m / Tt, t = m - n * Tt;
    int r = threadIdx.x;          // 0..319
    int q = t * Hop + r - 160;    // sample index before reflect
    if (q < 0) q = -q;
    else if (q >= Ll) q = 2 * Ll - 2 - q;
    d_frames[(size_t)m * KF + r] = d_xT[(size_t)n * Ll + q];
}

// Bspec: windowed DFT (window computed inline)
__global__ void k_bspec() {
    int r = blockIdx.x;         // 0..319
    int c = threadIdx.x;        // 0..513
    if (c >= DD) return;
    int n = 96 + r;
    float w = 0.5f - 0.5f * cosf(TWO_PI * (float)r / (float)Winl);
    int k = (c < Fq) ? c : c - Fq;
    int m = (n * k) & (Nfft - 1);
    float th = (float)m * (TWO_PI / (float)Nfft);
    d_Bspec[r * DDp + c] = (c < Fq) ? w * cosf(th) : -w * sinf(th);
}

__global__ void k_win() {
    int i = threadIdx.x;
    float v = 0.f;
    if (i >= 96 && i < 96 + Winl)
        v = 0.5f - 0.5f * cosf(TWO_PI * (float)(i - 96) / (float)Winl);
    d_win[i] = v;
}

__global__ void k_pack_wih(const float* __restrict__ W_ih,
                           const float* __restrict__ b_ih,
                           const float* __restrict__ b_hh) {
    int idx = blockIdx.x * blockDim.x + threadIdx.x;
    if (idx < GG) d_biasxw[idx] = b_ih[idx] + b_hh[idx];
    if (idx >= DD * GG) return;
    int d = idx >> 9, g = idx & 511;
    d_WihT[idx] = W_ih[g * DD + d];
}

__global__ void k_pack_wmask(const float* __restrict__ W1, const float* __restrict__ b1,
                             const float* __restrict__ W2, const float* __restrict__ b2) {
    int j = blockIdx.x;    // 0..1027
    int k = threadIdx.x;   // 0..127
    float v = (j < DD) ? W1[j * HH + k] : W2[(j - DD) * HH + k];
    d_Wmask[k * NM + j] = v;
    if (k == 0) d_bmask[j] = (j < DD) ? b1[j] : b2[j - DD];
}

// iRFFT matrix with synthesis window folded in. imag of DC/Nyquist ignored (c2r).
__global__ void k_emat() {
    int row = blockIdx.x;   // 0..513
    int n   = threadIdx.x;  // 0..511
    float w = d_win[n];
    float val;
    if (row < Fq) {
        int k = row;
        float ck = (k == 0 || k == Nfft / 2) ? 1.0f : 2.0f;
        int m = (k * n) & (Nfft - 1);
        val = ck * (1.0f / (float)Nfft) * cosf((float)m * (TWO_PI / (float)Nfft)) * w;
    } else {
        int k = row - Fq;
        if (k == 0 || k == Nfft / 2) val = 0.f;
        else {
            int m = (k * n) & (Nfft - 1);
            val = -(2.0f / (float)Nfft) * sinf((float)m * (TWO_PI / (float)Nfft)) * w;
        }
    }
    d_Emat[row * Nfft + n] = val;
}

// ---------------- SGEMM: 256x128 tile, 16x8/thread, FFMA2, persistent --------
// TA=0: A[M][K] lda=k-stride.  TA=1: A stored [K][M], lda=m-stride.
// TC=0: C[M][N] row-major.     TC=1: C stored [N][M] (C^T), ldc=m-stride.
// smem: As [2][16][256], Bs [2][16][128]  (12288 floats = 48 KB)
struct Frag { float4 a[4]; float4 b[2]; };

template <int TA>
__device__ __forceinline__ void gload(Frag& f, int tid, int M, int N, int K,
                                      const float* __restrict__ A, int lda,
                                      const float* __restrict__ B, int ldb,
                                      int by, int bx, int k0)
{
    if (TA == 0) {
        int gr = by * 256 + tid;
        bool mv = (gr < M);
        const float* pA = A + (size_t)gr * lda + k0;
#pragma unroll
        for (int l = 0; l < 4; l++) {
            int gk = k0 + l * 4;
            float4 v = make_float4(0.f, 0.f, 0.f, 0.f);
            if (mv) {
                if (gk + 4 <= K) v = *(const float4*)(pA + l * 4);
                else {
                    if (gk     < K) v.x = pA[l * 4];
                    if (gk + 1 < K) v.y = pA[l * 4 + 1];
                    if (gk + 2 < K) v.z = pA[l * 4 + 2];
                }
            }
            f.a[l] = v;
        }
    } else {
#pragma unroll
        for (int l = 0; l < 4; l++) {
            int idx = tid + l * 256;
            int ak = idx >> 6, ar4 = (idx & 63) << 2;
            int gk = k0 + ak, gr = by * 256 + ar4;
            const float* pA = A + (size_t)gk * lda + gr;
            float4 v = make_float4(0.f, 0.f, 0.f, 0.f);
            if (gk < K) {
                if (gr + 4 <= M) v = *(const float4*)pA;
                else {
                    if (gr     < M) v.x = pA[0];
                    if (gr + 1 < M) v.y = pA[1];
                    if (gr + 2 < M) v.z = pA[2];
                }
            }
            f.a[l] = v;
        }
    }
#pragma unroll
    for (int l = 0; l < 2; l++) {
        int idx = tid + l * 256;
        int bkk = idx >> 5, bc = (idx & 31) << 2;
        int gc = bx * 128 + bc, gkb = k0 + bkk;
        const float* pB = B + (size_t)gkb * ldb + gc;
        float4 v = make_float4(0.f, 0.f, 0.f, 0.f);
        if (gkb < K) {
            if (gc + 4 <= N) v = *(const float4*)pB;
            else {
                if (gc     < N) v.x = pB[0];
                if (gc + 1 < N) v.y = pB[1];
                if (gc + 2 < N) v.z = pB[2];
            }
        }
        f.b[l] = v;
    }
}

template <int TA>
__device__ __forceinline__ void sstore(const Frag& f, int tid, int buf,
                                       float* As, float* Bs)
{
    if (TA == 0) {
#pragma unroll
        for (int l = 0; l < 4; l++) {
            float* base = As + (size_t)(buf * 16 + l * 4) * 256 + tid;
            base[0]   = f.a[l].x;
            base[256] = f.a[l].y;
            base[512] = f.a[l].z;
            base[768] = f.a[l].w;
        }
    } else {
#pragma unroll
        for (int l = 0; l < 4; l++) {
            int idx = tid + l * 256;
            int ak = idx >> 6, ar4 = (idx & 63) << 2;
            *(float4*)(As + (size_t)(buf * 16 + ak) * 256 + ar4) = f.a[l];
        }
    }
#pragma unroll
    for (int l = 0; l < 2; l++) {
        int idx = tid + l * 256;
        int bkk = idx >> 5, bc = (idx & 31) << 2;
        *(float4*)(Bs + (size_t)(buf * 16 + bkk) * 128 + bc) = f.b[l];
    }
}

template <int TA, int TC>
__global__ void __launch_bounds__(256, 1)
sgemm_t(int M, int N, int K,
        const float* __restrict__ A, int lda,
        const float* __restrict__ B, int ldb,
        float* __restrict__ C, int ldc,
        const float* __restrict__ bias)
{
    extern __shared__ float smembuf[];
    float* As = smembuf;           // 2*16*256 = 8192 floats
    float* Bs = smembuf + 8192;    // 2*16*128 = 4096 floats
    int tid = threadIdx.x;
    int tx = tid & 15, ty = tid >> 4;

    int ntx = (N + 127) >> 7, nty = (M + 255) >> 8;
    int ntiles = ntx * nty;
    int nk = (K + 15) >> 4;

    for (int tile = blockIdx.x; tile < ntiles; tile += gridDim.x) {
        int bx = tile % ntx, by = tile / ntx;
        int m0 = by * 256, n0 = bx * 128;
        __syncthreads();   // protect smem reuse across tiles

        u64 acc[16][4];
#pragma unroll
        for (int a = 0; a < 16; a++)
#pragma unroll
            for (int j = 0; j < 4; j++) acc[a][j] = pk2(0.f, 0.f);

        Frag f;
        gload<TA>(f, tid, M, N, K, A, lda, B, ldb, by, bx, 0);
        sstore<TA>(f, tid, 0, As, Bs);
        __syncthreads();

        for (int kt = 0; kt < nk; kt++) {
            int cur = kt & 1;
            if (kt + 1 < nk)
                gload<TA>(f, tid, M, N, K, A, lda, B, ldb, by, bx, (kt + 1) << 4);
#pragma unroll
            for (int k = 0; k < 16; k++) {
                const float* Ar = As + (size_t)(cur * 16 + k) * 256;
                const float* Br = Bs + (size_t)(cur * 16 + k) * 128;
                float4 a0 = *(const float4*)(Ar + ty * 4);
                float4 a1 = *(const float4*)(Ar + 64 + ty * 4);
                float4 a2 = *(const float4*)(Ar + 128 + ty * 4);
                float4 a3 = *(const float4*)(Ar + 192 + ty * 4);
                F4U B0, B1;
                B0.f = *(const float4*)(Br + tx * 4);
                B1.f = *(const float4*)(Br + 64 + tx * 4);
                float av[16] = {a0.x, a0.y, a0.z, a0.w, a1.x, a1.y, a1.z, a1.w,
                                a2.x, a2.y, a2.z, a2.w, a3.x, a3.y, a3.z, a3.w};
#pragma unroll
                for (int a = 0; a < 16; a++) {
                    u64 pa = pk2(av[a], av[a]);
                    acc[a][0] = fma2(pa, B0.u[0], acc[a][0]);
                    acc[a][1] = fma2(pa, B0.u[1], acc[a][1]);
                    acc[a][2] = fma2(pa, B1.u[0], acc[a][2]);
                    acc[a][3] = fma2(pa, B1.u[1], acc[a][3]);
                }
            }
            if (kt + 1 < nk) {
                sstore<TA>(f, tid, 1 - cur, As, Bs);
                __syncthreads();
            }
        }

        if (TC == 0) {
#pragma unroll
            for (int a = 0; a < 16; a++) {
                int row = m0 + ((a >> 2) << 6) + ty * 4 + (a & 3);
                if (row >= M) continue;
#pragma unroll
                for (int j = 0; j < 4; j++) {
                    float lo, hi;
                    upk2(acc[a][j], lo, hi);
                    int colb = n0 + ((j >= 2) ? 64 : 0) + tx * 4 + (j & 1) * 2;
                    if (colb < N)     C[(size_t)row * ldc + colb]     = lo + (bias ? bias[colb]     : 0.f);
                    if (colb + 1 < N) C[(size_t)row * ldc + colb + 1] = hi + (bias ? bias[colb + 1] : 0.f);
                }
            }
        } else {
            // transposed-C epilogue: 4 chunks of 32 cols staged in smem, coalesced out
            float* S = smembuf;   // 32*257 floats, reuses tile buffers
#pragma unroll
            for (int cc2 = 0; cc2 < 4; cc2++) {
                __syncthreads();
                int txlo = (cc2 & 1) * 8;           // tx range [txlo, txlo+8)
                int jbase = (cc2 & 2);              // j in {jbase, jbase+1}
                if (tx >= txlo && tx < txlo + 8) {
#pragma unroll
                    for (int a = 0; a < 16; a++) {
                        int r = ((a >> 2) << 6) + ty * 4 + (a & 3);
#pragma unroll
                        for (int jj = 0; jj < 2; jj++) {
                            int j = jbase + jj;
                            float lo, hi;
                            upk2(acc[a][j], lo, hi);
                            int cloc = (tx - txlo) * 4 + jj * 2;
                            S[cloc * 257 + r]       = lo;
                            S[(cloc + 1) * 257 + r] = hi;
                        }
                    }
                }
                __syncthreads();
#pragma unroll
                for (int c2 = 0; c2 < 32; c2++) {
                    int gcol = n0 + cc2 * 32 + c2;
                    int grow = m0 + tid;
                    if (gcol < N && grow < M)
                        C[(size_t)gcol * ldc + grow] = S[c2 * 257 + tid] + (bias ? bias[gcol] : 0.f);
                }
            }
        }
    }
}

static inline int pgrid(int M, int N) {
    int t = ((M + 255) >> 8) * ((N + 127) >> 7);
    return t < MAXCTA ? t : MAXCTA;
}

// ---------------- LSTM: 64 persistent blocks, 512 threads, FFMA2 -------------
__global__ void __launch_bounds__(512, 1)
lstm_k(const float* __restrict__ W_hh)
{
    extern __shared__ float4 Wv2[];
    __shared__ __align__(16) float h_s[128];
    __shared__ float g_s[512];
    int n = blockIdx.x, g = threadIdx.x;

    u64 wp[32];
#pragma unroll
    for (int i = 0; i < 16; i++) {
        float4 w4 = *(const float4*)(W_hh + (size_t)g * 128 + 4 * i);
        wp[2 * i]     = pk2(w4.x, w4.y);
        wp[2 * i + 1] = pk2(w4.z, w4.w);
    }
    for (int j = g; j < 16 * 512; j += 512) {
        int i = j >> 9, gg = j & 511;
        Wv2[j] = *(const float4*)(W_hh + (size_t)gg * 128 + 64 + 4 * i);
    }
    float cst = 0.f;
    if (g < 128) h_s[g] = 0.f;
    __syncthreads();

    const float* xwb  = d_xw + (size_t)n * Tt * GG;
    float*       hout = d_h  + (size_t)n * Tt * HH;
    const u64*   h2   = (const u64*)h_s;
    const u64*   wv2u = (const u64*)Wv2;

    float xnext = xwb[g];
    for (int t = 0; t < Tt; t++) {
        float xcur = xnext;
        if (t + 1 < Tt) xnext = xwb[(size_t)(t + 1) * GG + g];
        u64 c0 = pk2(xcur, 0.f);
        u64 c1 = pk2(0.f, 0.f), c2 = pk2(0.f, 0.f), c3 = pk2(0.f, 0.f);
#pragma unroll
        for (int i = 0; i < 32; i += 4) {
            c0 = fma2(wp[i],     h2[i],     c0);
            c1 = fma2(wp[i + 1], h2[i + 1], c1);
            c2 = fma2(wp[i + 2], h2[i + 2], c2);
            c3 = fma2(wp[i + 3], h2[i + 3], c3);
        }
#pragma unroll
        for (int i = 0; i < 16; i += 2) {
            c0 = fma2(wv2u[2 * (i * 512 + g)],           h2[32 + 2 * i],     c0);
            c1 = fma2(wv2u[2 * (i * 512 + g) + 1],       h2[32 + 2 * i + 1], c1);
            c2 = fma2(wv2u[2 * ((i + 1) * 512 + g)],     h2[32 + 2 * i + 2], c2);
            c3 = fma2(wv2u[2 * ((i + 1) * 512 + g) + 1], h2[32 + 2 * i + 3], c3);
        }
        float s0, s1, s2, s3, s4, s5, s6, s7;
        upk2(c0, s0, s1); upk2(c1, s2, s3); upk2(c2, s4, s5); upk2(c3, s6, s7);
        g_s[g] = ((s0 + s1) + (s2 + s3)) + ((s4 + s5) + (s6 + s7));
        __syncthreads();
        if (g < 128) {
            float iv = sigmf(g_s[g]);
            float fv = sigmf(g_s[128 + g]);
            float gv = tanhf(g_s[256 + g]);
            float ov = sigmf(g_s[384 + g]);
            cst = fv * cst + iv * gv;
            float hv = ov * tanhf(cst);
            h_s[g] = hv;
            hout[(size_t)t * HH + g] = hv;
        }
        __syncthreads();
    }
}

// ---------------- PSD: one block per (b,f), f-major coalesced loads ----------
__global__ void __launch_bounds__(256)
psd_k()
{
    int bf = blockIdx.x;
    int b = bf / Fq, f = bf - b * Fq;
    __shared__ float2 sv[8][33];
    __shared__ float2 nv[8][33];
    int tid = threadIdx.x;
    int cl = tid >> 5, ts = tid & 31;
    int p = tid >> 2, sub = tid & 3;
    int cc = p >> 3, ee = p & 7;
    float2 as = make_float2(0.f, 0.f), an = make_float2(0.f, 0.f);

    const float* sre  = d_specT  + (size_t)f * ROWS;
    const float* sim  = d_specT  + (size_t)(Fq + f) * ROWS;
    const float* m1re = d_masksT + (size_t)f * ROWS;
    const float* m1im = d_masksT + (size_t)(Fq + f) * ROWS;
    const float* m2re = d_masksT + (size_t)(DD + f) * ROWS;
    const float* m2im = d_masksT + (size_t)(DD + Fq + f) * ROWS;

    for (int t0 = 0; t0 < Tt; t0 += 32) {
        int t = t0 + ts;
        float2 svv = make_float2(0.f, 0.f), nvv = make_float2(0.f, 0.f);
        if (t < Tt) {
            size_t row = (size_t)(b * 8 + cl) * Tt + t;
            float2 s  = make_float2(sre[row],  sim[row]);
            float2 m1 = make_float2(m1re[row], m1im[row]);
            float2 m2 = make_float2(m2re[row], m2im[row]);
            svv = cmulf(m1, s);
            nvv = cmulf(m2, s);
        }
        sv[cl][ts] = svv;
        nv[cl][ts] = nvv;
        __syncthreads();
#pragma unroll
        for (int j = 0; j < 8; j++) {
            int q = sub * 8 + j;
            float2 a = sv[cc][q], bq = sv[ee][q];
            as.x += a.x * bq.x + a.y * bq.y;
            as.y += a.y * bq.x - a.x * bq.y;
            a = nv[cc][q]; bq = nv[ee][q];
            an.x += a.x * bq.x + a.y * bq.y;
            an.y += a.y * bq.x - a.x * bq.y;
        }
        __syncthreads();
    }
#pragma unroll
    for (int o = 2; o >= 1; o >>= 1) {
        as.x += __shfl_down_sync(0xffffffffu, as.x, o);
        as.y += __shfl_down_sync(0xffffffffu, as.y, o);
        an.x += __shfl_down_sync(0xffffffffu, an.x, o);
        an.y += __shfl_down_sync(0xffffffffu, an.y, o);
    }
    if (sub == 0) {
        float invT = 1.0f / (float)Tt;
        d_psd_s[(size_t)bf * 64 + p] = make_float2(as.x * invT, as.y * invT);
        d_psd_n[(size_t)bf * 64 + p] = make_float2(an.x * invT, an.y * invT);
    }
}

// ---------------- solve: 8x8 complex Gauss-Jordan, 32 systems/block ----------
#define ANm(i,j) mem[((i)*8+(j))*32 + tid]
#define ASm(i,j) mem[(64+(i)*8+(j))*32 + tid]
__global__ void __launch_bounds__(32)
solve_k()
{
    __shared__ float2 mem[128 * 32];
    int tid = threadIdx.x;
    int sys = blockIdx.x * 32 + tid;
    if (sys >= Bb * Fq) return;

    for (int e = 0; e < 64; e++) {
        mem[e * 32 + tid]        = d_psd_n[(size_t)sys * 64 + e];
        mem[(64 + e) * 32 + tid] = d_psd_s[(size_t)sys * 64 + e];
    }
    float tr = 0.f;
    for (int i = 0; i < 8; i++) tr += ANm(i, i).x;
    float lam = 1e-6f * tr / 8.0f + 1e-8f;
    for (int i = 0; i < 8; i++) ANm(i, i).x += lam;
    for (int p = 0; p < 8; p++) {
        float2 piv = ANm(p, p);
        float dinv = 1.0f / (piv.x * piv.x + piv.y * piv.y);
        float2 ip = make_float2(piv.x * dinv, -piv.y * dinv);
        for (int j = 0; j < 8; j++) {
            ANm(p, j) = cmulf(ANm(p, j), ip);
            ASm(p, j) = cmulf(ASm(p, j), ip);
        }
        for (int r = 0; r < 8; r++) {
            if (r == p) continue;
            float2 fct = ANm(r, p);
            for (int j = 0; j < 8; j++) {
                float2 t1 = cmulf(fct, ANm(p, j));
                float2 t2 = cmulf(fct, ASm(p, j));
                ANm(r, j).x -= t1.x; ANm(r, j).y -= t1.y;
                ASm(r, j).x -= t2.x; ASm(r, j).y -= t2.y;
            }
        }
    }
    float2 tr2 = make_float2(1e-8f, 0.f);
    for (int i = 0; i < 8; i++) {
        tr2.x += ASm(i, i).x;
        tr2.y += ASm(i, i).y;
    }
    float dinv = 1.0f / (tr2.x * tr2.x + tr2.y * tr2.y);
    float2 itr = make_float2(tr2.x * dinv, -tr2.y * dinv);
    for (int c = 0; c < 8; c++) {
        float2 wv = cmulf(ASm(c, 0), itr);
        d_wbeam[(size_t)sys * 8 + c] = make_float2(wv.x, -wv.y);   // store conj(w)
    }
}

// ---------------- beamform: block per (b,f), coalesced over t ----------------
__global__ void __launch_bounds__(256)
beam_k()
{
    int bf = blockIdx.x;
    int b = bf / Fq, f = bf - b * Fq;
    const float2* w = d_wbeam + (size_t)bf * 8;
    float2 wc[8];
#pragma unroll
    for (int c = 0; c < 8; c++) wc[c] = w[c];
    const float* sre = d_specT + (size_t)f * ROWS;
    const float* sim = d_specT + (size_t)(Fq + f) * ROWS;
    for (int t = threadIdx.x; t < Tt; t += 256) {
        float2 acc = make_float2(0.f, 0.f);
#pragma unroll
        for (int c = 0; c < 8; c++) {
            size_t row = (size_t)(b * 8 + c) * Tt + t;
            float2 s = make_float2(sre[row], sim[row]);
            acc.x += wc[c].x * s.x - wc[c].y * s.y;
            acc.y += wc[c].x * s.y + wc[c].y * s.x;
        }
        d_enhT[(size_t)f * BT + b * Tt + t]        = acc.x;
        d_enhT[(size_t)(Fq + f) * BT + b * Tt + t] = acc.y;
    }
}

// ---------------- overlap-add + normalization + crop ----------------
__global__ void k_ola(float* __restrict__ out)
{
    int idx = blockIdx.x * blockDim.x + threadIdx.x;
    if (idx >= Bb * Ll) return;
    int b = idx / Ll, l = idx - b * Ll;
    int p = l + 256;
    int tmin = (p >= Nfft) ? (p - Nfft) / Hop + 1 : 0;
    int tmax = p / Hop; if (tmax > Tt - 1) tmax = Tt - 1;
    float acc = 0.f, wsq = 0.f;
    for (int t = tmin; t <= tmax; t++) {
        int n = p - t * Hop;
        float wv = d_win[n];
        acc += d_fout[((size_t)b * Tt + t) * Nfft + n];
        wsq += wv * wv;
    }
    out[idx] = acc / fmaxf(wsq, 1e-11f);
}

// ---------------- launch ----------------
extern "C" void kernel_launch(void* const* d_in, const int* in_sizes, int n_in,
                              void* d_out, int out_size)
{
    const float* x    = (const float*)d_in[0];
    const float* W_ih = (const float*)d_in[1];
    const float* W_hh = (const float*)d_in[2];
    const float* b_ih = (const float*)d_in[3];
    const float* b_hh = (const float*)d_in[4];
    const float* W1   = (const float*)d_in[5];
    const float* b1   = (const float*)d_in[6];
    const float* W2   = (const float*)d_in[7];
    const float* b2   = (const float*)d_in[8];
    float* out = (float*)d_out;

    cudaFuncSetAttribute(lstm_k, cudaFuncAttributeMaxDynamicSharedMemorySize, 131072);
    const int GS = 12288 * 4;   // 48 KB dyn smem (As+Bs double-buffered; TC=1 stage reuses)

    float *pBspec, *pBW, *pWihT, *pBiasxw, *pWmask, *pBmask, *pEmat;
    float *pFrames, *pSpecT, *pXw, *pH, *pMasksT, *pEnhT, *pFout;
    cudaGetSymbolAddress((void**)&pBspec,  d_Bspec);
    cudaGetSymbolAddress((void**)&pBW,     d_BW);
    cudaGetSymbolAddress((void**)&pWihT,   d_WihT);
    cudaGetSymbolAddress((void**)&pBiasxw, d_biasxw);
    cudaGetSymbolAddress((void**)&pWmask,  d_Wmask);
    cudaGetSymbolAddress((void**)&pBmask,  d_bmask);
    cudaGetSymbolAddress((void**)&pEmat,   d_Emat);
    cudaGetSymbolAddress((void**)&pFrames, d_frames);
    cudaGetSymbolAddress((void**)&pSpecT,  d_specT);
    cudaGetSymbolAddress((void**)&pXw,     d_xw);
    cudaGetSymbolAddress((void**)&pH,      d_h);
    cudaGetSymbolAddress((void**)&pMasksT, d_masksT);
    cudaGetSymbolAddress((void**)&pEnhT,   d_enhT);
    cudaGetSymbolAddress((void**)&pFout,   d_fout);

    {   // input transpose
        dim3 grid(Ll / 256, Bb);
        k_xpose<<<grid, 256>>>(x);
    }
    k_frames<<<ROWS, KF>>>();
    k_bspec<<<KF, DD>>>();
    // GEMM1a: specT[514][ROWS] = (frames @ Bspec)^T   (ncu capture slot)
    sgemm_t<0, 1><<<pgrid(ROWS, DD), 256, GS>>>(ROWS, DD, KF, pFrames, KF, pBspec, DDp, pSpecT, ROWS, nullptr);
    k_pack_wih<<<(DD * GG + 255) / 256, 256>>>(W_ih, b_ih, b_hh);
    // GEMM0: BW[320,512] = Bspec[320,514] @ WihT[514,512]
    sgemm_t<0, 0><<<pgrid(KF, GG), 256, GS>>>(KF, GG, DD, pBspec, DDp, pWihT, GG, pBW, GG, nullptr);
    // GEMM1b: xw[ROWS][512] = frames @ BW + bias
    sgemm_t<0, 0><<<pgrid(ROWS, GG), 256, GS>>>(ROWS, GG, KF, pFrames, KF, pBW, GG, pXw, GG, pBiasxw);
    lstm_k<<<NS, 512, 131072>>>(W_hh);
    k_win<<<1, Nfft>>>();
    k_pack_wmask<<<NM, HH>>>(W1, b1, W2, b2);
    // GEMM2: masksT[1028][ROWS] = (h @ Wmask + bmask)^T
    sgemm_t<0, 1><<<pgrid(ROWS, NM), 256, GS>>>(ROWS, NM, HH, pH, HH, pWmask, NM, pMasksT, ROWS, pBmask);
    k_emat<<<DD, Nfft>>>();
    psd_k<<<Bb * Fq, 256>>>();
    solve_k<<<(Bb * Fq + 31) / 32, 32>>>();
    beam_k<<<Bb * Fq, 256>>>();
    // GEMM3: fout[4808,512] = enhT^T[4808,514] @ Emat[514,512]
    sgemm_t<1, 0><<<pgrid(BT, Nfft), 256, GS>>>(BT, Nfft, DD, pEnhT, BT, pEmat, Nfft, pFout, Nfft, nullptr);
    k_ola<<<(Bb * Ll + 255) / 256, 256>>>(out);
}

// round 12
// speedup vs baseline: 1.1204x; 1.0919x over previous
#include <cuda_runtime.h>
#include <math.h>
#include <stdint.h>

// ---------------- problem constants ----------------
#define Bb   8
#define Cc   8
#define Ll   96000
#define Nfft 512
#define Winl 320
#define Hop  160
#define Fq   257
#define Tt   601
#define NS   64            // B*C sequences
#define ROWS (NS*Tt)       // 38464
#define KF   320           // nonzero window support
#define DD   514           // 2F
#define DDp  516           // padded (16B-aligned rows)
#define GG   512           // 4H
#define HH   128
#define NM   1028          // 2*DD     (mask1|mask2)
#define BT   (Bb*Tt)       // 4808
#define TWO_PI 6.28318530717958647692f
#define MAXCTA 296         // 148 SMs x 2 CTAs

typedef unsigned long long u64;

// ---------------- device scratch ----------------
__device__ float  d_win[Nfft];
__device__ float  d_xT[(size_t)Bb * Cc * Ll];   // channel-major input
__device__ float  d_Bspec[KF * DDp];            // windowed DFT matrix [320][514(+2)]
__device__ float  d_BW[KF * GG];                // Bspec @ W_ih^T  [320][512]
__device__ float  d_WihT[DD * GG];
__device__ float  d_biasxw[GG];
__device__ float  d_Wmask[HH * NM];
__device__ float  d_bmask[NM];
__device__ float  d_Emat[DD * Nfft];
__device__ float  d_frames[(size_t)ROWS * KF];
__device__ float  d_specT[(size_t)DD * ROWS];   // f-major spectra
__device__ float  d_xw[(size_t)ROWS * GG];      // LSTM input projections
__device__ float  d_h[(size_t)ROWS * HH];
__device__ float  d_masksT[(size_t)NM * ROWS];  // f-major masks
__device__ float2 d_psd_s[Bb * Fq * 64];
__device__ float2 d_psd_n[Bb * Fq * 64];
__device__ float2 d_wbeam[Bb * Fq * Cc];
__device__ float  d_enhT[(size_t)DD * BT];      // f-major beamformed spectrum
__device__ float  d_fout[(size_t)BT * Nfft];

__device__ __forceinline__ float2 cmulf(float2 a, float2 b) {
    return make_float2(a.x * b.x - a.y * b.y, a.x * b.y + a.y * b.x);
}
__device__ __forceinline__ float sigmf(float x) { return 1.0f / (1.0f + expf(-x)); }

// packed f32x2 helpers (sm_103a FFMA2 path)
__device__ __forceinline__ u64 pk2(float lo, float hi) {
    u64 r; asm("mov.b64 %0, {%1, %2};" : "=l"(r) : "f"(lo), "f"(hi)); return r;
}
__device__ __forceinline__ u64 fma2(u64 a, u64 b, u64 c) {
    u64 d; asm("fma.rn.f32x2 %0, %1, %2, %3;" : "=l"(d) : "l"(a), "l"(b), "l"(c)); return d;
}
__device__ __forceinline__ void upk2(u64 v, float& lo, float& hi) {
    asm("mov.b64 {%0, %1}, %2;" : "=f"(lo), "=f"(hi) : "l"(v));
}
union F4U { float4 f; u64 u[2]; };

// ---------------- input transpose: x[b][l][c] -> xT[b][c][l] ----------------
__global__ void __launch_bounds__(256)
k_xpose(const float* __restrict__ x)
{
    __shared__ float tile[8][257];
    int b = blockIdx.y;
    int l0 = blockIdx.x * 256;
    int tid = threadIdx.x;
    const float* p = x + ((size_t)b * Ll + l0 + tid) * Cc;
    float4 v0 = *(const float4*)p;
    float4 v1 = *(const float4*)(p + 4);
    tile[0][tid] = v0.x; tile[1][tid] = v0.y; tile[2][tid] = v0.z; tile[3][tid] = v0.w;
    tile[4][tid] = v1.x; tile[5][tid] = v1.y; tile[6][tid] = v1.z; tile[7][tid] = v1.w;
    __syncthreads();
#pragma unroll
    for (int c = 0; c < 8; c++)
        d_xT[((size_t)b * Cc + c) * Ll + l0 + tid] = tile[c][tid];
}

// ---------------- frame gather (reflect pad), coalesced from xT -------------
__global__ void k_frames()
{
    int m = blockIdx.x;           // n*T + t
    int n = m / Tt, t = m - n * Tt;
    int r = threadIdx.x;          // 0..319
    int q = t * Hop + r - 160;    // sample index before reflect
    if (q < 0) q = -q;
    else if (q >= Ll) q = 2 * Ll - 2 - q;
    d_frames[(size_t)m * KF + r] = d_xT[(size_t)n * Ll + q];
}

// Bspec: windowed DFT (window computed inline)
__global__ void k_bspec() {
    int r = blockIdx.x;         // 0..319
    int c = threadIdx.x;        // 0..513
    if (c >= DD) return;
    int n = 96 + r;
    float w = 0.5f - 0.5f * cosf(TWO_PI * (float)r / (float)Winl);
    int k = (c < Fq) ? c : c - Fq;
    int m = (n * k) & (Nfft - 1);
    float th = (float)m * (TWO_PI / (float)Nfft);
    d_Bspec[r * DDp + c] = (c < Fq) ? w * cosf(th) : -w * sinf(th);
}

__global__ void k_win() {
    int i = threadIdx.x;
    float v = 0.f;
    if (i >= 96 && i < 96 + Winl)
        v = 0.5f - 0.5f * cosf(TWO_PI * (float)(i - 96) / (float)Winl);
    d_win[i] = v;
}

__global__ void k_pack_wih(const float* __restrict__ W_ih,
                           const float* __restrict__ b_ih,
                           const float* __restrict__ b_hh) {
    int idx = blockIdx.x * blockDim.x + threadIdx.x;
    if (idx < GG) d_biasxw[idx] = b_ih[idx] + b_hh[idx];
    if (idx >= DD * GG) return;
    int d = idx >> 9, g = idx & 511;
    d_WihT[idx] = W_ih[g * DD + d];
}

__global__ void k_pack_wmask(const float* __restrict__ W1, const float* __restrict__ b1,
                             const float* __restrict__ W2, const float* __restrict__ b2) {
    int j = blockIdx.x;    // 0..1027
    int k = threadIdx.x;   // 0..127
    float v = (j < DD) ? W1[j * HH + k] : W2[(j - DD) * HH + k];
    d_Wmask[k * NM + j] = v;
    if (k == 0) d_bmask[j] = (j < DD) ? b1[j] : b2[j - DD];
}

// iRFFT matrix with synthesis window folded in. imag of DC/Nyquist ignored (c2r).
__global__ void k_emat() {
    int row = blockIdx.x;   // 0..513
    int n   = threadIdx.x;  // 0..511
    float w = d_win[n];
    float val;
    if (row < Fq) {
        int k = row;
        float ck = (k == 0 || k == Nfft / 2) ? 1.0f : 2.0f;
        int m = (k * n) & (Nfft - 1);
        val = ck * (1.0f / (float)Nfft) * cosf((float)m * (TWO_PI / (float)Nfft)) * w;
    } else {
        int k = row - Fq;
        if (k == 0 || k == Nfft / 2) val = 0.f;
        else {
            int m = (k * n) & (Nfft - 1);
            val = -(2.0f / (float)Nfft) * sinf((float)m * (TWO_PI / (float)Nfft)) * w;
        }
    }
    d_Emat[row * Nfft + n] = val;
}

// ---------------- SGEMM: 128x128 tile, double-buffered, FFMA2, persistent ----
// TA=0: A[M][K] lda=k-stride.  TA=1: A stored [K][M], lda=m-stride.
// TC=0: C[M][N] row-major.     TC=1: C stored [N][M] (C^T), ldc=m-stride.
struct Frag { float4 a[2]; float4 b[2]; };

template <int TA>
__device__ __forceinline__ void gload(Frag& f, int tid, int M, int N, int K,
                                      const float* __restrict__ A, int lda,
                                      const float* __restrict__ B, int ldb,
                                      int by, int bx, int k0)
{
#pragma unroll
    for (int l = 0; l < 2; l++) {
        int idx = tid + l * 256;
        if (TA == 0) {
            int arow = idx & 127, ak = (idx >> 7) << 2;
            int gr = by * 128 + arow, gk = k0 + ak;
            const float* pA = A + (size_t)gr * lda + gk;
            if (gr < M && gk + 3 < K) {
                f.a[l] = *(const float4*)pA;
            } else {
                f.a[l].x = (gr < M && gk     < K) ? pA[0] : 0.f;
                f.a[l].y = (gr < M && gk + 1 < K) ? pA[1] : 0.f;
                f.a[l].z = (gr < M && gk + 2 < K) ? pA[2] : 0.f;
                f.a[l].w = (gr < M && gk + 3 < K) ? pA[3] : 0.f;
            }
        } else {
            int ak = idx >> 5, ar4 = (idx & 31) << 2;
            int gk = k0 + ak, gr = by * 128 + ar4;
            const float* pA = A + (size_t)gk * lda + gr;
            if (gk < K && gr + 3 < M) {
                f.a[l] = *(const float4*)pA;
            } else {
                f.a[l].x = (gk < K && gr     < M) ? pA[0] : 0.f;
                f.a[l].y = (gk < K && gr + 1 < M) ? pA[1] : 0.f;
                f.a[l].z = (gk < K && gr + 2 < M) ? pA[2] : 0.f;
                f.a[l].w = (gk < K && gr + 3 < M) ? pA[3] : 0.f;
            }
        }
        int bkk = idx >> 5, bc = (idx & 31) << 2;
        int gc = bx * 128 + bc, gkb = k0 + bkk;
        const float* pB = B + (size_t)gkb * ldb + gc;
        if (gkb < K && gc + 3 < N) {
            f.b[l] = *(const float4*)pB;
        } else {
            f.b[l].x = (gkb < K && gc     < N) ? pB[0] : 0.f;
            f.b[l].y = (gkb < K && gc + 1 < N) ? pB[1] : 0.f;
            f.b[l].z = (gkb < K && gc + 2 < N) ? pB[2] : 0.f;
            f.b[l].w = (gkb < K && gc + 3 < N) ? pB[3] : 0.f;
        }
    }
}

template <int TA>
__device__ __forceinline__ void sstore(const Frag& f, int tid, int buf,
                                       float (*As)[16][128], float (*Bs)[16][128])
{
#pragma unroll
    for (int l = 0; l < 2; l++) {
        int idx = tid + l * 256;
        if (TA == 0) {
            int arow = idx & 127, ak = (idx >> 7) << 2;
            As[buf][ak + 0][arow] = f.a[l].x;
            As[buf][ak + 1][arow] = f.a[l].y;
            As[buf][ak + 2][arow] = f.a[l].z;
            As[buf][ak + 3][arow] = f.a[l].w;
        } else {
            int ak = idx >> 5, ar4 = (idx & 31) << 2;
            *(float4*)&As[buf][ak][ar4] = f.a[l];
        }
        int bkk = idx >> 5, bc = (idx & 31) << 2;
        *(float4*)&Bs[buf][bkk][bc] = f.b[l];
    }
}

template <int TA, int TC>
__global__ void __launch_bounds__(256, 2)
sgemm_t(int M, int N, int K,
        const float* __restrict__ A, int lda,
        const float* __restrict__ B, int ldb,
        float* __restrict__ C, int ldc,
        const float* __restrict__ bias)
{
    extern __shared__ float smembuf[];
    float (*As)[16][128] = (float(*)[16][128])smembuf;
    float (*Bs)[16][128] = (float(*)[16][128])(smembuf + 4096);
    int tid = threadIdx.x;
    int tx = tid & 15, ty = tid >> 4;

    int ntx = (N + 127) >> 7, nty = (M + 127) >> 7;
    int ntiles = ntx * nty;
    int nk = (K + 15) >> 4;

    for (int tile = blockIdx.x; tile < ntiles; tile += gridDim.x) {
        int bx = tile % ntx, by = tile / ntx;
        __syncthreads();   // protect smem reuse across tiles

        u64 acc[8][4];
#pragma unroll
        for (int a = 0; a < 8; a++)
#pragma unroll
            for (int j = 0; j < 4; j++) acc[a][j] = pk2(0.f, 0.f);

        Frag f;
        gload<TA>(f, tid, M, N, K, A, lda, B, ldb, by, bx, 0);
        sstore<TA>(f, tid, 0, As, Bs);
        __syncthreads();

        for (int kt = 0; kt < nk; kt++) {
            int cur = kt & 1;
            if (kt + 1 < nk)
                gload<TA>(f, tid, M, N, K, A, lda, B, ldb, by, bx, (kt + 1) << 4);
#pragma unroll
            for (int k = 0; k < 16; k++) {
                float4 a0 = *(const float4*)&As[cur][k][ty * 4];
                float4 a1 = *(const float4*)&As[cur][k][64 + ty * 4];
                F4U B0, B1;
                B0.f = *(const float4*)&Bs[cur][k][tx * 4];
                B1.f = *(const float4*)&Bs[cur][k][64 + tx * 4];
                float av[8] = {a0.x, a0.y, a0.z, a0.w, a1.x, a1.y, a1.z, a1.w};
#pragma unroll
                for (int a = 0; a < 8; a++) {
                    u64 pa = pk2(av[a], av[a]);
                    acc[a][0] = fma2(pa, B0.u[0], acc[a][0]);
                    acc[a][1] = fma2(pa, B0.u[1], acc[a][1]);
                    acc[a][2] = fma2(pa, B1.u[0], acc[a][2]);
                    acc[a][3] = fma2(pa, B1.u[1], acc[a][3]);
                }
            }
            if (kt + 1 < nk) {
                int nxt = 1 - cur;
                sstore<TA>(f, tid, nxt, As, Bs);
                __syncthreads();
            }
        }

        if (TC == 0) {
#pragma unroll
            for (int a = 0; a < 8; a++) {
                int row = by * 128 + ((a & 4) << 4) + ty * 4 + (a & 3);
                if (row >= M) continue;
#pragma unroll
                for (int j = 0; j < 4; j++) {
                    float lo, hi;
                    upk2(acc[a][j], lo, hi);
                    int colb = bx * 128 + ((j >= 2) ? 64 : 0) + tx * 4 + (j & 1) * 2;
                    if (colb < N)     C[(size_t)row * ldc + colb]     = lo + (bias ? bias[colb]     : 0.f);
                    if (colb + 1 < N) C[(size_t)row * ldc + colb + 1] = hi + (bias ? bias[colb + 1] : 0.f);
                }
            }
        } else {
            // transposed-C epilogue: stage 128x64 halves in smem, write coalesced
            float* S = smembuf;   // 64*129 floats
            __syncthreads();
#pragma unroll
            for (int hh = 0; hh < 2; hh++) {
#pragma unroll
                for (int a = 0; a < 8; a++) {
                    int row = ((a & 4) << 4) + ty * 4 + (a & 3);
#pragma unroll
                    for (int jj = 0; jj < 2; jj++) {
                        int j = hh * 2 + jj;
                        float lo, hi;
                        upk2(acc[a][j], lo, hi);
                        int col = tx * 4 + jj * 2;
                        S[col * 129 + row]       = lo;
                        S[(col + 1) * 129 + row] = hi;
                    }
                }
                __syncthreads();
#pragma unroll
                for (int i = 0; i < 32; i++) {
                    int idx = tid + i * 256;
                    int col = idx >> 7, row = idx & 127;
                    int gcol = bx * 128 + hh * 64 + col;
                    int grow = by * 128 + row;
                    if (gcol < N && grow < M)
                        C[(size_t)gcol * ldc + grow] = S[col * 129 + row] + (bias ? bias[gcol] : 0.f);
                }
                __syncthreads();
            }
        }
    }
}

static inline int pgrid(int M, int N) {
    int t = ((M + 127) >> 7) * ((N + 127) >> 7);
    return t < MAXCTA ? t : MAXCTA;
}

// ---------------- LSTM: 64 persistent blocks, 512 threads, FFMA2 -------------
__global__ void __launch_bounds__(512, 1)
lstm_k(const float* __restrict__ W_hh)
{
    extern __shared__ float4 Wv2[];
    __shared__ __align__(16) float h_s[128];
    __shared__ float g_s[512];
    int n = blockIdx.x, g = threadIdx.x;

    u64 wp[32];
#pragma unroll
    for (int i = 0; i < 16; i++) {
        float4 w4 = *(const float4*)(W_hh + (size_t)g * 128 + 4 * i);
        wp[2 * i]     = pk2(w4.x, w4.y);
        wp[2 * i + 1] = pk2(w4.z, w4.w);
    }
    for (int j = g; j < 16 * 512; j += 512) {
        int i = j >> 9, gg = j & 511;
        Wv2[j] = *(const float4*)(W_hh + (size_t)gg * 128 + 64 + 4 * i);
    }
    float cst = 0.f;
    if (g < 128) h_s[g] = 0.f;
    __syncthreads();

    const float* xwb  = d_xw + (size_t)n * Tt * GG;
    float*       hout = d_h  + (size_t)n * Tt * HH;
    const u64*   h2   = (const u64*)h_s;
    const u64*   wv2u = (const u64*)Wv2;

    float xnext = xwb[g];
    for (int t = 0; t < Tt; t++) {
        float xcur = xnext;
        if (t + 1 < Tt) xnext = xwb[(size_t)(t + 1) * GG + g];
        u64 c0 = pk2(xcur, 0.f);
        u64 c1 = pk2(0.f, 0.f), c2 = pk2(0.f, 0.f), c3 = pk2(0.f, 0.f);
#pragma unroll
        for (int i = 0; i < 32; i += 4) {
            c0 = fma2(wp[i],     h2[i],     c0);
            c1 = fma2(wp[i + 1], h2[i + 1], c1);
            c2 = fma2(wp[i + 2], h2[i + 2], c2);
            c3 = fma2(wp[i + 3], h2[i + 3], c3);
        }
#pragma unroll
        for (int i = 0; i < 16; i += 2) {
            c0 = fma2(wv2u[2 * (i * 512 + g)],           h2[32 + 2 * i],     c0);
            c1 = fma2(wv2u[2 * (i * 512 + g) + 1],       h2[32 + 2 * i + 1], c1);
            c2 = fma2(wv2u[2 * ((i + 1) * 512 + g)],     h2[32 + 2 * i + 2], c2);
            c3 = fma2(wv2u[2 * ((i + 1) * 512 + g) + 1], h2[32 + 2 * i + 3], c3);
        }
        float s0, s1, s2, s3, s4, s5, s6, s7;
        upk2(c0, s0, s1); upk2(c1, s2, s3); upk2(c2, s4, s5); upk2(c3, s6, s7);
        g_s[g] = ((s0 + s1) + (s2 + s3)) + ((s4 + s5) + (s6 + s7));
        __syncthreads();
        if (g < 128) {
            float iv = sigmf(g_s[g]);
            float fv = sigmf(g_s[128 + g]);
            float gv = tanhf(g_s[256 + g]);
            float ov = sigmf(g_s[384 + g]);
            cst = fv * cst + iv * gv;
            float hv = ov * tanhf(cst);
            h_s[g] = hv;
            hout[(size_t)t * HH + g] = hv;
        }
        __syncthreads();
    }
}

// ---------------- PSD: one block per (b,f), f-major coalesced loads ----------
__global__ void __launch_bounds__(256)
psd_k()
{
    int bf = blockIdx.x;
    int b = bf / Fq, f = bf - b * Fq;
    __shared__ float2 sv[8][33];
    __shared__ float2 nv[8][33];
    int tid = threadIdx.x;
    int cl = tid >> 5, ts = tid & 31;
    int p = tid >> 2, sub = tid & 3;
    int cc = p >> 3, ee = p & 7;
    float2 as = make_float2(0.f, 0.f), an = make_float2(0.f, 0.f);

    const float* sre  = d_specT  + (size_t)f * ROWS;
    const float* sim  = d_specT  + (size_t)(Fq + f) * ROWS;
    const float* m1re = d_masksT + (size_t)f * ROWS;
    const float* m1im = d_masksT + (size_t)(Fq + f) * ROWS;
    const float* m2re = d_masksT + (size_t)(DD + f) * ROWS;
    const float* m2im = d_masksT + (size_t)(DD + Fq + f) * ROWS;

    for (int t0 = 0; t0 < Tt; t0 += 32) {
        int t = t0 + ts;
        float2 svv = make_float2(0.f, 0.f), nvv = make_float2(0.f, 0.f);
        if (t < Tt) {
            size_t row = (size_t)(b * 8 + cl) * Tt + t;
            float2 s  = make_float2(sre[row],  sim[row]);
            float2 m1 = make_float2(m1re[row], m1im[row]);
            float2 m2 = make_float2(m2re[row], m2im[row]);
            svv = cmulf(m1, s);
            nvv = cmulf(m2, s);
        }
        sv[cl][ts] = svv;
        nv[cl][ts] = nvv;
        __syncthreads();
#pragma unroll
        for (int j = 0; j < 8; j++) {
            int q = sub * 8 + j;
            float2 a = sv[cc][q], bq = sv[ee][q];
            as.x += a.x * bq.x + a.y * bq.y;
            as.y += a.y * bq.x - a.x * bq.y;
            a = nv[cc][q]; bq = nv[ee][q];
            an.x += a.x * bq.x + a.y * bq.y;
            an.y += a.y * bq.x - a.x * bq.y;
        }
        __syncthreads();
    }
#pragma unroll
    for (int o = 2; o >= 1; o >>= 1) {
        as.x += __shfl_down_sync(0xffffffffu, as.x, o);
        as.y += __shfl_down_sync(0xffffffffu, as.y, o);
        an.x += __shfl_down_sync(0xffffffffu, an.x, o);
        an.y += __shfl_down_sync(0xffffffffu, an.y, o);
    }
    if (sub == 0) {
        float invT = 1.0f / (float)Tt;
        d_psd_s[(size_t)bf * 64 + p] = make_float2(as.x * invT, as.y * invT);
        d_psd_n[(size_t)bf * 64 + p] = make_float2(an.x * invT, an.y * invT);
    }
}

// ---------------- solve: 8x8 complex Gauss-Jordan, 32 systems/block ----------
#define ANm(i,j) mem[((i)*8+(j))*32 + tid]
#define ASm(i,j) mem[(64+(i)*8+(j))*32 + tid]
__global__ void __launch_bounds__(32)
solve_k()
{
    __shared__ float2 mem[128 * 32];
    int tid = threadIdx.x;
    int sys = blockIdx.x * 32 + tid;
    if (sys >= Bb * Fq) return;

    for (int e = 0; e < 64; e++) {
        mem[e * 32 + tid]        = d_psd_n[(size_t)sys * 64 + e];
        mem[(64 + e) * 32 + tid] = d_psd_s[(size_t)sys * 64 + e];
    }
    float tr = 0.f;
    for (int i = 0; i < 8; i++) tr += ANm(i, i).x;
    float lam = 1e-6f * tr / 8.0f + 1e-8f;
    for (int i = 0; i < 8; i++) ANm(i, i).x += lam;
    for (int p = 0; p < 8; p++) {
        float2 piv = ANm(p, p);
        float dinv = 1.0f / (piv.x * piv.x + piv.y * piv.y);
        float2 ip = make_float2(piv.x * dinv, -piv.y * dinv);
        for (int j = 0; j < 8; j++) {
            ANm(p, j) = cmulf(ANm(p, j), ip);
            ASm(p, j) = cmulf(ASm(p, j), ip);
        }
        for (int r = 0; r < 8; r++) {
            if (r == p) continue;
            float2 fct = ANm(r, p);
            for (int j = 0; j < 8; j++) {
                float2 t1 = cmulf(fct, ANm(p, j));
                float2 t2 = cmulf(fct, ASm(p, j));
                ANm(r, j).x -= t1.x; ANm(r, j).y -= t1.y;
                ASm(r, j).x -= t2.x; ASm(r, j).y -= t2.y;
            }
        }
    }
    float2 tr2 = make_float2(1e-8f, 0.f);
    for (int i = 0; i < 8; i++) {
        tr2.x += ASm(i, i).x;
        tr2.y += ASm(i, i).y;
    }
    float dinv = 1.0f / (tr2.x * tr2.x + tr2.y * tr2.y);
    float2 itr = make_float2(tr2.x * dinv, -tr2.y * dinv);
    for (int c = 0; c < 8; c++) {
        float2 wv = cmulf(ASm(c, 0), itr);
        d_wbeam[(size_t)sys * 8 + c] = make_float2(wv.x, -wv.y);   // store conj(w)
    }
}

// ---------------- beamform: block per (b,f), coalesced over t ----------------
__global__ void __launch_bounds__(256)
beam_k()
{
    int bf = blockIdx.x;
    int b = bf / Fq, f = bf - b * Fq;
    const float2* w = d_wbeam + (size_t)bf * 8;
    float2 wc[8];
#pragma unroll
    for (int c = 0; c < 8; c++) wc[c] = w[c];
    const float* sre = d_specT + (size_t)f * ROWS;
    const float* sim = d_specT + (size_t)(Fq + f) * ROWS;
    for (int t = threadIdx.x; t < Tt; t += 256) {
        float2 acc = make_float2(0.f, 0.f);
#pragma unroll
        for (int c = 0; c < 8; c++) {
            size_t row = (size_t)(b * 8 + c) * Tt + t;
            float2 s = make_float2(sre[row], sim[row]);
            acc.x += wc[c].x * s.x - wc[c].y * s.y;
            acc.y += wc[c].x * s.y + wc[c].y * s.x;
        }
        d_enhT[(size_t)f * BT + b * Tt + t]        = acc.x;
        d_enhT[(size_t)(Fq + f) * BT + b * Tt + t] = acc.y;
    }
}

// ---------------- overlap-add + normalization + crop ----------------
__global__ void k_ola(float* __restrict__ out)
{
    int idx = blockIdx.x * blockDim.x + threadIdx.x;
    if (idx >= Bb * Ll) return;
    int b = idx / Ll, l = idx - b * Ll;
    int p = l + 256;
    int tmin = (p >= Nfft) ? (p - Nfft) / Hop + 1 : 0;
    int tmax = p / Hop; if (tmax > Tt - 1) tmax = Tt - 1;
    float acc = 0.f, wsq = 0.f;
    for (int t = tmin; t <= tmax; t++) {
        int n = p - t * Hop;
        float wv = d_win[n];
        acc += d_fout[((size_t)b * Tt + t) * Nfft + n];
        wsq += wv * wv;
    }
    out[idx] = acc / fmaxf(wsq, 1e-11f);
}

// ---------------- launch ----------------
extern "C" void kernel_launch(void* const* d_in, const int* in_sizes, int n_in,
                              void* d_out, int out_size)
{
    const float* x    = (const float*)d_in[0];
    const float* W_ih = (const float*)d_in[1];
    const float* W_hh = (const float*)d_in[2];
    const float* b_ih = (const float*)d_in[3];
    const float* b_hh = (const float*)d_in[4];
    const float* W1   = (const float*)d_in[5];
    const float* b1   = (const float*)d_in[6];
    const float* W2   = (const float*)d_in[7];
    const float* b2   = (const float*)d_in[8];
    float* out = (float*)d_out;

    cudaFuncSetAttribute(lstm_k, cudaFuncAttributeMaxDynamicSharedMemorySize, 131072);
    const int GS = 64 * 129 * 4;   // 33024 B dyn smem for sgemm (>= 32768 mainloop)

    float *pBspec, *pBW, *pWihT, *pBiasxw, *pWmask, *pBmask, *pEmat;
    float *pFrames, *pSpecT, *pXw, *pH, *pMasksT, *pEnhT, *pFout;
    cudaGetSymbolAddress((void**)&pBspec,  d_Bspec);
    cudaGetSymbolAddress((void**)&pBW,     d_BW);
    cudaGetSymbolAddress((void**)&pWihT,   d_WihT);
    cudaGetSymbolAddress((void**)&pBiasxw, d_biasxw);
    cudaGetSymbolAddress((void**)&pWmask,  d_Wmask);
    cudaGetSymbolAddress((void**)&pBmask,  d_bmask);
    cudaGetSymbolAddress((void**)&pEmat,   d_Emat);
    cudaGetSymbolAddress((void**)&pFrames, d_frames);
    cudaGetSymbolAddress((void**)&pSpecT,  d_specT);
    cudaGetSymbolAddress((void**)&pXw,     d_xw);
    cudaGetSymbolAddress((void**)&pH,      d_h);
    cudaGetSymbolAddress((void**)&pMasksT, d_masksT);
    cudaGetSymbolAddress((void**)&pEnhT,   d_enhT);
    cudaGetSymbolAddress((void**)&pFout,   d_fout);

    {   // input transpose
        dim3 grid(Ll / 256, Bb);
        k_xpose<<<grid, 256>>>(x);
    }
    k_frames<<<ROWS, KF>>>();
    k_bspec<<<KF, DD>>>();
    // GEMM1a: specT[514][ROWS] = (frames @ Bspec)^T   (ncu capture slot)
    sgemm_t<0, 1><<<pgrid(ROWS, DD), 256, GS>>>(ROWS, DD, KF, pFrames, KF, pBspec, DDp, pSpecT, ROWS, nullptr);
    k_pack_wih<<<(DD * GG + 255) / 256, 256>>>(W_ih, b_ih, b_hh);
    // GEMM0: BW[320,512] = Bspec[320,514] @ WihT[514,512]
    sgemm_t<0, 0><<<pgrid(KF, GG), 256, GS>>>(KF, GG, DD, pBspec, DDp, pWihT, GG, pBW, GG, nullptr);
    // GEMM1b: xw[ROWS][512] = frames @ BW + bias
    sgemm_t<0, 0><<<pgrid(ROWS, GG), 256, GS>>>(ROWS, GG, KF, pFrames, KF, pBW, GG, pXw, GG, pBiasxw);
    lstm_k<<<NS, 512, 131072>>>(W_hh);
    k_win<<<1, Nfft>>>();
    k_pack_wmask<<<NM, HH>>>(W1, b1, W2, b2);
    // GEMM2: masksT[1028][ROWS] = (h @ Wmask + bmask)^T
    sgemm_t<0, 1><<<pgrid(ROWS, NM), 256, GS>>>(ROWS, NM, HH, pH, HH, pWmask, NM, pMasksT, ROWS, pBmask);
    k_emat<<<DD, Nfft>>>();
    psd_k<<<Bb * Fq, 256>>>();
    solve_k<<<(Bb * Fq + 31) / 32, 32>>>();
    beam_k<<<Bb * Fq, 256>>>();
    // GEMM3: fout[4808,512] = enhT^T[4808,514] @ Emat[514,512]
    sgemm_t<1, 0><<<pgrid(BT, Nfft), 256, GS>>>(BT, Nfft, DD, pEnhT, BT, pEmat, Nfft, pFout, Nfft, nullptr);
    k_ola<<<(Bb * Ll + 255) / 256, 256>>>(out);
}

// round 14
// speedup vs baseline: 1.1239x; 1.0032x over previous
#include <cuda_runtime.h>
#include <math.h>
#include <stdint.h>

// ---------------- problem constants ----------------
#define Bb   8
#define Cc   8
#define Ll   96000
#define Nfft 512
#define Winl 320
#define Hop  160
#define Fq   257
#define Tt   601
#define NS   64            // B*C sequences
#define ROWS (NS*Tt)       // 38464
#define KF   320           // nonzero window support
#define DD   514           // 2F
#define DDp  516           // padded (16B-aligned rows)
#define GG   512           // 4H
#define HH   128
#define NM   1028          // 2*DD     (mask1|mask2)
#define BT   (Bb*Tt)       // 4808
#define TWO_PI 6.28318530717958647692f
#define MAXCTA 296         // 148 SMs x 2 CTAs

typedef unsigned long long u64;

// ---------------- device scratch ----------------
__device__ float  d_win[Nfft];
__device__ float  d_xT[(size_t)Bb * Cc * Ll];   // channel-major input
__device__ float  d_Bspec[KF * DDp];            // windowed DFT matrix [320][514(+2)]
__device__ float  d_BW[KF * GG];                // Bspec @ W_ih^T  [320][512]
__device__ float  d_WihT[DD * GG];
__device__ float  d_biasxw[GG];
__device__ float  d_Wmask[HH * NM];
__device__ float  d_bmask[NM];
__device__ float  d_Emat[DD * Nfft];
__device__ float  d_frames[(size_t)ROWS * KF];
__device__ float  d_specT[(size_t)DD * ROWS];   // f-major spectra
__device__ float  d_xw[(size_t)ROWS * GG];      // LSTM input projections
__device__ float  d_h[(size_t)ROWS * HH];
__device__ float  d_masksT[(size_t)NM * ROWS];  // f-major masks
__device__ float2 d_psd_s[Bb * Fq * 64];
__device__ float2 d_psd_n[Bb * Fq * 64];
__device__ float2 d_wbeam[Bb * Fq * Cc];
__device__ float  d_enhT[(size_t)DD * BT];      // f-major beamformed spectrum
__device__ float  d_fout[(size_t)BT * Nfft];

__device__ __forceinline__ float2 cmulf(float2 a, float2 b) {
    return make_float2(a.x * b.x - a.y * b.y, a.x * b.y + a.y * b.x);
}
__device__ __forceinline__ float sigmf(float x) { return 1.0f / (1.0f + expf(-x)); }

// packed f32x2 helpers (sm_103a FFMA2 path)
__device__ __forceinline__ u64 pk2(float lo, float hi) {
    u64 r; asm("mov.b64 %0, {%1, %2};" : "=l"(r) : "f"(lo), "f"(hi)); return r;
}
__device__ __forceinline__ u64 fma2(u64 a, u64 b, u64 c) {
    u64 d; asm("fma.rn.f32x2 %0, %1, %2, %3;" : "=l"(d) : "l"(a), "l"(b), "l"(c)); return d;
}
__device__ __forceinline__ void upk2(u64 v, float& lo, float& hi) {
    asm("mov.b64 {%0, %1}, %2;" : "=f"(lo), "=f"(hi) : "l"(v));
}
union F4U { float4 f; u64 u[2]; };

// ---------------- input transpose: x[b][l][c] -> xT[b][c][l] ----------------
__global__ void __launch_bounds__(256)
k_xpose(const float* __restrict__ x)
{
    __shared__ float tile[8][257];
    int b = blockIdx.y;
    int l0 = blockIdx.x * 256;
    int tid = threadIdx.x;
    const float* p = x + ((size_t)b * Ll + l0 + tid) * Cc;
    float4 v0 = *(const float4*)p;
    float4 v1 = *(const float4*)(p + 4);
    tile[0][tid] = v0.x; tile[1][tid] = v0.y; tile[2][tid] = v0.z; tile[3][tid] = v0.w;
    tile[4][tid] = v1.x; tile[5][tid] = v1.y; tile[6][tid] = v1.z; tile[7][tid] = v1.w;
    __syncthreads();
#pragma unroll
    for (int c = 0; c < 8; c++)
        d_xT[((size_t)b * Cc + c) * Ll + l0 + tid] = tile[c][tid];
}

// ---------------- frame gather (reflect pad), coalesced from xT -------------
__global__ void k_frames()
{
    int m = blockIdx.x;           // n*T + t
    int n = m / Tt, t = m - n * Tt;
    int r = threadIdx.x;          // 0..319
    int q = t * Hop + r - 160;    // sample index before reflect
    if (q < 0) q = -q;
    else if (q >= Ll) q = 2 * Ll - 2 - q;
    d_frames[(size_t)m * KF + r] = d_xT[(size_t)n * Ll + q];
}

// Bspec: windowed DFT (window computed inline)
__global__ void k_bspec() {
    int r = blockIdx.x;         // 0..319
    int c = threadIdx.x;        // 0..513
    if (c >= DD) return;
    int n = 96 + r;
    float w = 0.5f - 0.5f * cosf(TWO_PI * (float)r / (float)Winl);
    int k = (c < Fq) ? c : c - Fq;
    int m = (n * k) & (Nfft - 1);
    float th = (float)m * (TWO_PI / (float)Nfft);
    d_Bspec[r * DDp + c] = (c < Fq) ? w * cosf(th) : -w * sinf(th);
}

__global__ void k_win() {
    int i = threadIdx.x;
    float v = 0.f;
    if (i >= 96 && i < 96 + Winl)
        v = 0.5f - 0.5f * cosf(TWO_PI * (float)(i - 96) / (float)Winl);
    d_win[i] = v;
}

__global__ void k_pack_wih(const float* __restrict__ W_ih,
                           const float* __restrict__ b_ih,
                           const float* __restrict__ b_hh) {
    int idx = blockIdx.x * blockDim.x + threadIdx.x;
    if (idx < GG) d_biasxw[idx] = b_ih[idx] + b_hh[idx];
    if (idx >= DD * GG) return;
    int d = idx >> 9, g = idx & 511;
    d_WihT[idx] = W_ih[g * DD + d];
}

__global__ void k_pack_wmask(const float* __restrict__ W1, const float* __restrict__ b1,
                             const float* __restrict__ W2, const float* __restrict__ b2) {
    int j = blockIdx.x;    // 0..1027
    int k = threadIdx.x;   // 0..127
    float v = (j < DD) ? W1[j * HH + k] : W2[(j - DD) * HH + k];
    d_Wmask[k * NM + j] = v;
    if (k == 0) d_bmask[j] = (j < DD) ? b1[j] : b2[j - DD];
}

// iRFFT matrix with synthesis window folded in. imag of DC/Nyquist ignored (c2r).
__global__ void k_emat() {
    int row = blockIdx.x;   // 0..513
    int n   = threadIdx.x;  // 0..511
    float w = d_win[n];
    float val;
    if (row < Fq) {
        int k = row;
        float ck = (k == 0 || k == Nfft / 2) ? 1.0f : 2.0f;
        int m = (k * n) & (Nfft - 1);
        val = ck * (1.0f / (float)Nfft) * cosf((float)m * (TWO_PI / (float)Nfft)) * w;
    } else {
        int k = row - Fq;
        if (k == 0 || k == Nfft / 2) val = 0.f;
        else {
            int m = (k * n) & (Nfft - 1);
            val = -(2.0f / (float)Nfft) * sinf((float)m * (TWO_PI / (float)Nfft)) * w;
        }
    }
    d_Emat[row * Nfft + n] = val;
}

// ---------------- SGEMM: 128x128 tile, double-buffered, FFMA2, persistent ----
// TA=0: A[M][K] lda=k-stride.  TA=1: A stored [K][M], lda=m-stride.
// TC=0: C[M][N] row-major.     TC=1: C stored [N][M] (C^T), ldc=m-stride.
struct Frag { float4 a[2]; float4 b[2]; };

template <int TA>
__device__ __forceinline__ void gload(Frag& f, int tid, int M, int N, int K,
                                      const float* __restrict__ A, int lda,
                                      const float* __restrict__ B, int ldb,
                                      int by, int bx, int k0)
{
#pragma unroll
    for (int l = 0; l < 2; l++) {
        int idx = tid + l * 256;
        if (TA == 0) {
            int arow = idx & 127, ak = (idx >> 7) << 2;
            int gr = by * 128 + arow, gk = k0 + ak;
            const float* pA = A + (size_t)gr * lda + gk;
            if (gr < M && gk + 3 < K) {
                f.a[l] = *(const float4*)pA;
            } else {
                f.a[l].x = (gr < M && gk     < K) ? pA[0] : 0.f;
                f.a[l].y = (gr < M && gk + 1 < K) ? pA[1] : 0.f;
                f.a[l].z = (gr < M && gk + 2 < K) ? pA[2] : 0.f;
                f.a[l].w = (gr < M && gk + 3 < K) ? pA[3] : 0.f;
            }
        } else {
            int ak = idx >> 5, ar4 = (idx & 31) << 2;
            int gk = k0 + ak, gr = by * 128 + ar4;
            const float* pA = A + (size_t)gk * lda + gr;
            if (gk < K && gr + 3 < M) {
                f.a[l] = *(const float4*)pA;
            } else {
                f.a[l].x = (gk < K && gr     < M) ? pA[0] : 0.f;
                f.a[l].y = (gk < K && gr + 1 < M) ? pA[1] : 0.f;
                f.a[l].z = (gk < K && gr + 2 < M) ? pA[2] : 0.f;
                f.a[l].w = (gk < K && gr + 3 < M) ? pA[3] : 0.f;
            }
        }
        int bkk = idx >> 5, bc = (idx & 31) << 2;
        int gc = bx * 128 + bc, gkb = k0 + bkk;
        const float* pB = B + (size_t)gkb * ldb + gc;
        if (gkb < K && gc + 3 < N) {
            f.b[l] = *(const float4*)pB;
        } else {
            f.b[l].x = (gkb < K && gc     < N) ? pB[0] : 0.f;
            f.b[l].y = (gkb < K && gc + 1 < N) ? pB[1] : 0.f;
            f.b[l].z = (gkb < K && gc + 2 < N) ? pB[2] : 0.f;
            f.b[l].w = (gkb < K && gc + 3 < N) ? pB[3] : 0.f;
        }
    }
}

template <int TA>
__device__ __forceinline__ void sstore(const Frag& f, int tid, int buf,
                                       float (*As)[16][128], float (*Bs)[16][128])
{
#pragma unroll
    for (int l = 0; l < 2; l++) {
        int idx = tid + l * 256;
        if (TA == 0) {
            int arow = idx & 127, ak = (idx >> 7) << 2;
            As[buf][ak + 0][arow] = f.a[l].x;
            As[buf][ak + 1][arow] = f.a[l].y;
            As[buf][ak + 2][arow] = f.a[l].z;
            As[buf][ak + 3][arow] = f.a[l].w;
        } else {
            int ak = idx >> 5, ar4 = (idx & 31) << 2;
            *(float4*)&As[buf][ak][ar4] = f.a[l];
        }
        int bkk = idx >> 5, bc = (idx & 31) << 2;
        *(float4*)&Bs[buf][bkk][bc] = f.b[l];
    }
}

template <int TA, int TC>
__global__ void __launch_bounds__(256, 2)
sgemm_t(int M, int N, int K,
        const float* __restrict__ A, int lda,
        const float* __restrict__ B, int ldb,
        float* __restrict__ C, int ldc,
        const float* __restrict__ bias)
{
    extern __shared__ float smembuf[];
    float (*As)[16][128] = (float(*)[16][128])smembuf;
    float (*Bs)[16][128] = (float(*)[16][128])(smembuf + 4096);
    int tid = threadIdx.x;
    int tx = tid & 15, ty = tid >> 4;

    int ntx = (N + 127) >> 7, nty = (M + 127) >> 7;
    int ntiles = ntx * nty;
    int nk = (K + 15) >> 4;

    for (int tile = blockIdx.x; tile < ntiles; tile += gridDim.x) {
        int bx = tile % ntx, by = tile / ntx;
        __syncthreads();   // protect smem reuse across tiles

        u64 acc[8][4];
#pragma unroll
        for (int a = 0; a < 8; a++)
#pragma unroll
            for (int j = 0; j < 4; j++) acc[a][j] = pk2(0.f, 0.f);

        Frag f;
        gload<TA>(f, tid, M, N, K, A, lda, B, ldb, by, bx, 0);
        sstore<TA>(f, tid, 0, As, Bs);
        __syncthreads();

        for (int kt = 0; kt < nk; kt++) {
            int cur = kt & 1;
            if (kt + 1 < nk)
                gload<TA>(f, tid, M, N, K, A, lda, B, ldb, by, bx, (kt + 1) << 4);
#pragma unroll
            for (int k = 0; k < 16; k++) {
                float4 a0 = *(const float4*)&As[cur][k][ty * 4];
                float4 a1 = *(const float4*)&As[cur][k][64 + ty * 4];
                F4U B0, B1;
                B0.f = *(const float4*)&Bs[cur][k][tx * 4];
                B1.f = *(const float4*)&Bs[cur][k][64 + tx * 4];
                float av[8] = {a0.x, a0.y, a0.z, a0.w, a1.x, a1.y, a1.z, a1.w};
#pragma unroll
                for (int a = 0; a < 8; a++) {
                    u64 pa = pk2(av[a], av[a]);
                    acc[a][0] = fma2(pa, B0.u[0], acc[a][0]);
                    acc[a][1] = fma2(pa, B0.u[1], acc[a][1]);
                    acc[a][2] = fma2(pa, B1.u[0], acc[a][2]);
                    acc[a][3] = fma2(pa, B1.u[1], acc[a][3]);
                }
            }
            if (kt + 1 < nk) {
                int nxt = 1 - cur;
                sstore<TA>(f, tid, nxt, As, Bs);
                __syncthreads();
            }
        }

        if (TC == 0) {
#pragma unroll
            for (int a = 0; a < 8; a++) {
                int row = by * 128 + ((a & 4) << 4) + ty * 4 + (a & 3);
                if (row >= M) continue;
#pragma unroll
                for (int j = 0; j < 4; j++) {
                    float lo, hi;
                    upk2(acc[a][j], lo, hi);
                    int colb = bx * 128 + ((j >= 2) ? 64 : 0) + tx * 4 + (j & 1) * 2;
                    if (colb < N)     C[(size_t)row * ldc + colb]     = lo + (bias ? bias[colb]     : 0.f);
                    if (colb + 1 < N) C[(size_t)row * ldc + colb + 1] = hi + (bias ? bias[colb + 1] : 0.f);
                }
            }
        } else {
            // transposed-C epilogue: stage 128x64 halves (pitch 132), float4 out
            float* S = smembuf;   // 64*132 floats
            __syncthreads();
#pragma unroll
            for (int hh = 0; hh < 2; hh++) {
#pragma unroll
                for (int a = 0; a < 8; a++) {
                    int row = ((a & 4) << 4) + ty * 4 + (a & 3);
#pragma unroll
                    for (int jj = 0; jj < 2; jj++) {
                        int j = hh * 2 + jj;
                        float lo, hi;
                        upk2(acc[a][j], lo, hi);
                        int col = tx * 4 + jj * 2;
                        S[col * 132 + row]       = lo;
                        S[(col + 1) * 132 + row] = hi;
                    }
                }
                __syncthreads();
#pragma unroll
                for (int u = 0; u < 8; u++) {
                    int unit = tid + u * 256;        // 0..2047
                    int col = unit >> 5;             // 0..63
                    int r4 = (unit & 31) << 2;       // 0..124
                    int gcol = bx * 128 + hh * 64 + col;
                    int grow = by * 128 + r4;
                    if (gcol >= N) continue;
                    float bb = bias ? bias[gcol] : 0.f;
                    if (grow + 3 < M) {
                        float4 v = *(const float4*)&S[col * 132 + r4];
                        v.x += bb; v.y += bb; v.z += bb; v.w += bb;
                        *(float4*)&C[(size_t)gcol * ldc + grow] = v;
                    } else {
#pragma unroll
                        for (int q = 0; q < 4; q++)
                            if (grow + q < M)
                                C[(size_t)gcol * ldc + grow + q] = S[col * 132 + r4 + q] + bb;
                    }
                }
                __syncthreads();
            }
        }
    }
}

static inline int pgrid(int M, int N) {
    int t = ((M + 127) >> 7) * ((N + 127) >> 7);
    return t < MAXCTA ? t : MAXCTA;
}

// ---------------- LSTM: 64 persistent blocks, 512 threads, FFMA2 -------------
__global__ void __launch_bounds__(512, 1)
lstm_k(const float* __restrict__ W_hh)
{
    extern __shared__ float4 Wv2[];
    __shared__ __align__(16) float h_s[128];
    __shared__ float g_s[512];
    int n = blockIdx.x, g = threadIdx.x;

    u64 wp[32];
#pragma unroll
    for (int i = 0; i < 16; i++) {
        float4 w4 = *(const float4*)(W_hh + (size_t)g * 128 + 4 * i);
        wp[2 * i]     = pk2(w4.x, w4.y);
        wp[2 * i + 1] = pk2(w4.z, w4.w);
    }
    for (int j = g; j < 16 * 512; j += 512) {
        int i = j >> 9, gg = j & 511;
        Wv2[j] = *(const float4*)(W_hh + (size_t)gg * 128 + 64 + 4 * i);
    }
    float cst = 0.f;
    if (g < 128) h_s[g] = 0.f;
    __syncthreads();

    const float* xwb  = d_xw + (size_t)n * Tt * GG;
    float*       hout = d_h  + (size_t)n * Tt * HH;
    const u64*   h2   = (const u64*)h_s;
    const u64*   wv2u = (const u64*)Wv2;

    float xnext = xwb[g];
    for (int t = 0; t < Tt; t++) {
        float xcur = xnext;
        if (t + 1 < Tt) xnext = xwb[(size_t)(t + 1) * GG + g];
        u64 c0 = pk2(xcur, 0.f);
        u64 c1 = pk2(0.f, 0.f), c2 = pk2(0.f, 0.f), c3 = pk2(0.f, 0.f);
#pragma unroll
        for (int i = 0; i < 32; i += 4) {
            c0 = fma2(wp[i],     h2[i],     c0);
            c1 = fma2(wp[i + 1], h2[i + 1], c1);
            c2 = fma2(wp[i + 2], h2[i + 2], c2);
            c3 = fma2(wp[i + 3], h2[i + 3], c3);
        }
#pragma unroll
        for (int i = 0; i < 16; i += 2) {
            c0 = fma2(wv2u[2 * (i * 512 + g)],           h2[32 + 2 * i],     c0);
            c1 = fma2(wv2u[2 * (i * 512 + g) + 1],       h2[32 + 2 * i + 1], c1);
            c2 = fma2(wv2u[2 * ((i + 1) * 512 + g)],     h2[32 + 2 * i + 2], c2);
            c3 = fma2(wv2u[2 * ((i + 1) * 512 + g) + 1], h2[32 + 2 * i + 3], c3);
        }
        float s0, s1, s2, s3, s4, s5, s6, s7;
        upk2(c0, s0, s1); upk2(c1, s2, s3); upk2(c2, s4, s5); upk2(c3, s6, s7);
        g_s[g] = ((s0 + s1) + (s2 + s3)) + ((s4 + s5) + (s6 + s7));
        __syncthreads();
        if (g < 128) {
            float iv = sigmf(g_s[g]);
            float fv = sigmf(g_s[128 + g]);
            float gv = tanhf(g_s[256 + g]);
            float ov = sigmf(g_s[384 + g]);
            cst = fv * cst + iv * gv;
            float hv = ov * tanhf(cst);
            h_s[g] = hv;
            hout[(size_t)t * HH + g] = hv;
        }
        __syncthreads();
    }
}

// ---------------- PSD: one block per (b,f), f-major coalesced loads ----------
__global__ void __launch_bounds__(256)
psd_k()
{
    int bf = blockIdx.x;
    int b = bf / Fq, f = bf - b * Fq;
    __shared__ float2 sv[8][33];
    __shared__ float2 nv[8][33];
    int tid = threadIdx.x;
    int cl = tid >> 5, ts = tid & 31;
    int p = tid >> 2, sub = tid & 3;
    int cc = p >> 3, ee = p & 7;
    float2 as = make_float2(0.f, 0.f), an = make_float2(0.f, 0.f);

    const float* sre  = d_specT  + (size_t)f * ROWS;
    const float* sim  = d_specT  + (size_t)(Fq + f) * ROWS;
    const float* m1re = d_masksT + (size_t)f * ROWS;
    const float* m1im = d_masksT + (size_t)(Fq + f) * ROWS;
    const float* m2re = d_masksT + (size_t)(DD + f) * ROWS;
    const float* m2im = d_masksT + (size_t)(DD + Fq + f) * ROWS;

    for (int t0 = 0; t0 < Tt; t0 += 32) {
        int t = t0 + ts;
        float2 svv = make_float2(0.f, 0.f), nvv = make_float2(0.f, 0.f);
        if (t < Tt) {
            size_t row = (size_t)(b * 8 + cl) * Tt + t;
            float2 s  = make_float2(sre[row],  sim[row]);
            float2 m1 = make_float2(m1re[row], m1im[row]);
            float2 m2 = make_float2(m2re[row], m2im[row]);
            svv = cmulf(m1, s);
            nvv = cmulf(m2, s);
        }
        sv[cl][ts] = svv;
        nv[cl][ts] = nvv;
        __syncthreads();
#pragma unroll
        for (int j = 0; j < 8; j++) {
            int q = sub * 8 + j;
            float2 a = sv[cc][q], bq = sv[ee][q];
            as.x += a.x * bq.x + a.y * bq.y;
            as.y += a.y * bq.x - a.x * bq.y;
            a = nv[cc][q]; bq = nv[ee][q];
            an.x += a.x * bq.x + a.y * bq.y;
            an.y += a.y * bq.x - a.x * bq.y;
        }
        __syncthreads();
    }
#pragma unroll
    for (int o = 2; o >= 1; o >>= 1) {
        as.x += __shfl_down_sync(0xffffffffu, as.x, o);
        as.y += __shfl_down_sync(0xffffffffu, as.y, o);
        an.x += __shfl_down_sync(0xffffffffu, an.x, o);
        an.y += __shfl_down_sync(0xffffffffu, an.y, o);
    }
    if (sub == 0) {
        float invT = 1.0f / (float)Tt;
        d_psd_s[(size_t)bf * 64 + p] = make_float2(as.x * invT, as.y * invT);
        d_psd_n[(size_t)bf * 64 + p] = make_float2(an.x * invT, an.y * invT);
    }
}

// ---------------- solve: 8x8 complex Gauss-Jordan, 32 systems/block ----------
#define ANm(i,j) mem[((i)*8+(j))*32 + tid]
#define ASm(i,j) mem[(64+(i)*8+(j))*32 + tid]
__global__ void __launch_bounds__(32)
solve_k()
{
    __shared__ float2 mem[128 * 32];
    int tid = threadIdx.x;
    int sys = blockIdx.x * 32 + tid;
    if (sys >= Bb * Fq) return;

    for (int e = 0; e < 64; e++) {
        mem[e * 32 + tid]        = d_psd_n[(size_t)sys * 64 + e];
        mem[(64 + e) * 32 + tid] = d_psd_s[(size_t)sys * 64 + e];
    }
    float tr = 0.f;
    for (int i = 0; i < 8; i++) tr += ANm(i, i).x;
    float lam = 1e-6f * tr / 8.0f + 1e-8f;
    for (int i = 0; i < 8; i++) ANm(i, i).x += lam;
    for (int p = 0; p < 8; p++) {
        float2 piv = ANm(p, p);
        float dinv = 1.0f / (piv.x * piv.x + piv.y * piv.y);
        float2 ip = make_float2(piv.x * dinv, -piv.y * dinv);
        for (int j = 0; j < 8; j++) {
            ANm(p, j) = cmulf(ANm(p, j), ip);
            ASm(p, j) = cmulf(ASm(p, j), ip);
        }
        for (int r = 0; r < 8; r++) {
            if (r == p) continue;
            float2 fct = ANm(r, p);
            for (int j = 0; j < 8; j++) {
                float2 t1 = cmulf(fct, ANm(p, j));
                float2 t2 = cmulf(fct, ASm(p, j));
                ANm(r, j).x -= t1.x; ANm(r, j).y -= t1.y;
                ASm(r, j).x -= t2.x; ASm(r, j).y -= t2.y;
            }
        }
    }
    float2 tr2 = make_float2(1e-8f, 0.f);
    for (int i = 0; i < 8; i++) {
        tr2.x += ASm(i, i).x;
        tr2.y += ASm(i, i).y;
    }
    float dinv = 1.0f / (tr2.x * tr2.x + tr2.y * tr2.y);
    float2 itr = make_float2(tr2.x * dinv, -tr2.y * dinv);
    for (int c = 0; c < 8; c++) {
        float2 wv = cmulf(ASm(c, 0), itr);
        d_wbeam[(size_t)sys * 8 + c] = make_float2(wv.x, -wv.y);   // store conj(w)
    }
}

// ---------------- beamform: block per (b,f), coalesced over t ----------------
__global__ void __launch_bounds__(256)
beam_k()
{
    int bf = blockIdx.x;
    int b = bf / Fq, f = bf - b * Fq;
    const float2* w = d_wbeam + (size_t)bf * 8;
    float2 wc[8];
#pragma unroll
    for (int c = 0; c < 8; c++) wc[c] = w[c];
    const float* sre = d_specT + (size_t)f * ROWS;
    const float* sim = d_specT + (size_t)(Fq + f) * ROWS;
    for (int t = threadIdx.x; t < Tt; t += 256) {
        float2 acc = make_float2(0.f, 0.f);
#pragma unroll
        for (int c = 0; c < 8; c++) {
            size_t row = (size_t)(b * 8 + c) * Tt + t;
            float2 s = make_float2(sre[row], sim[row]);
            acc.x += wc[c].x * s.x - wc[c].y * s.y;
            acc.y += wc[c].x * s.y + wc[c].y * s.x;
        }
        d_enhT[(size_t)f * BT + b * Tt + t]        = acc.x;
        d_enhT[(size_t)(Fq + f) * BT + b * Tt + t] = acc.y;
    }
}

// ---------------- overlap-add + normalization + crop ----------------
__global__ void k_ola(float* __restrict__ out)
{
    int idx = blockIdx.x * blockDim.x + threadIdx.x;
    if (idx >= Bb * Ll) return;
    int b = idx / Ll, l = idx - b * Ll;
    int p = l + 256;
    int tmin = (p >= Nfft) ? (p - Nfft) / Hop + 1 : 0;
    int tmax = p / Hop; if (tmax > Tt - 1) tmax = Tt - 1;
    float acc = 0.f, wsq = 0.f;
    for (int t = tmin; t <= tmax; t++) {
        int n = p - t * Hop;
        float wv = d_win[n];
        acc += d_fout[((size_t)b * Tt + t) * Nfft + n];
        wsq += wv * wv;
    }
    out[idx] = acc / fmaxf(wsq, 1e-11f);
}

// ---------------- launch ----------------
extern "C" void kernel_launch(void* const* d_in, const int* in_sizes, int n_in,
                              void* d_out, int out_size)
{
    const float* x    = (const float*)d_in[0];
    const float* W_ih = (const float*)d_in[1];
    const float* W_hh = (const float*)d_in[2];
    const float* b_ih = (const float*)d_in[3];
    const float* b_hh = (const float*)d_in[4];
    const float* W1   = (const float*)d_in[5];
    const float* b1   = (const float*)d_in[6];
    const float* W2   = (const float*)d_in[7];
    const float* b2   = (const float*)d_in[8];
    float* out = (float*)d_out;

    cudaFuncSetAttribute(lstm_k, cudaFuncAttributeMaxDynamicSharedMemorySize, 131072);
    const int GS = 64 * 132 * 4;   // 33792 B dyn smem (mainloop 32768; TC=1 stage 33792)

    float *pBspec, *pBW, *pWihT, *pBiasxw, *pWmask, *pBmask, *pEmat;
    float *pFrames, *pSpecT, *pXw, *pH, *pMasksT, *pEnhT, *pFout;
    cudaGetSymbolAddress((void**)&pBspec,  d_Bspec);
    cudaGetSymbolAddress((void**)&pBW,     d_BW);
    cudaGetSymbolAddress((void**)&pWihT,   d_WihT);
    cudaGetSymbolAddress((void**)&pBiasxw, d_biasxw);
    cudaGetSymbolAddress((void**)&pWmask,  d_Wmask);
    cudaGetSymbolAddress((void**)&pBmask,  d_bmask);
    cudaGetSymbolAddress((void**)&pEmat,   d_Emat);
    cudaGetSymbolAddress((void**)&pFrames, d_frames);
    cudaGetSymbolAddress((void**)&pSpecT,  d_specT);
    cudaGetSymbolAddress((void**)&pXw,     d_xw);
    cudaGetSymbolAddress((void**)&pH,      d_h);
    cudaGetSymbolAddress((void**)&pMasksT, d_masksT);
    cudaGetSymbolAddress((void**)&pEnhT,   d_enhT);
    cudaGetSymbolAddress((void**)&pFout,   d_fout);

    // side stream + events for the LSTM/GEMM1a overlap fork (host objects;
    // created fresh every call — deterministic, no device allocations)
    cudaStream_t s2;
    cudaStreamCreateWithFlags(&s2, cudaStreamNonBlocking);
    cudaEvent_t e1, e2;
    cudaEventCreateWithFlags(&e1, cudaEventDisableTiming);
    cudaEventCreateWithFlags(&e2, cudaEventDisableTiming);

    {   // input transpose
        dim3 grid(Ll / 256, Bb);
        k_xpose<<<grid, 256>>>(x);
    }
    k_frames<<<ROWS, KF>>>();
    k_bspec<<<KF, DD>>>();
    k_pack_wih<<<(DD * GG + 255) / 256, 256>>>(W_ih, b_ih, b_hh);
    // GEMM0: BW[320,512] = Bspec[320,514] @ WihT[514,512]
    sgemm_t<0, 0><<<pgrid(KF, GG), 256, GS>>>(KF, GG, DD, pBspec, DDp, pWihT, GG, pBW, GG, nullptr);
    // GEMM1b: xw[ROWS][512] = frames @ BW + bias
    sgemm_t<0, 0><<<pgrid(ROWS, GG), 256, GS>>>(ROWS, GG, KF, pFrames, KF, pBW, GG, pXw, GG, pBiasxw);

    // ---- fork: branch B (s2) = GEMM1a + win + emat, concurrent with LSTM ----
    cudaEventRecord(e1, 0);
    cudaStreamWaitEvent(s2, e1, 0);
    sgemm_t<0, 1><<<pgrid(ROWS, DD), 256, GS, s2>>>(ROWS, DD, KF, pFrames, KF, pBspec, DDp, pSpecT, ROWS, nullptr);
    k_win<<<1, Nfft, 0, s2>>>();
    k_emat<<<DD, Nfft, 0, s2>>>();
    cudaEventRecord(e2, s2);

    // ---- branch A (default stream): LSTM -> mask GEMM ----
    lstm_k<<<NS, 512, 131072>>>(W_hh);
    k_pack_wmask<<<NM, HH>>>(W1, b1, W2, b2);
    sgemm_t<0, 1><<<pgrid(ROWS, NM), 256, GS>>>(ROWS, NM, HH, pH, HH, pWmask, NM, pMasksT, ROWS, pBmask);

    // ---- join: psd needs specT (branch B) + masksT (branch A) ----
    cudaStreamWaitEvent(0, e2, 0);
    psd_k<<<Bb * Fq, 256>>>();
    solve_k<<<(Bb * Fq + 31) / 32, 32>>>();
    beam_k<<<Bb * Fq, 256>>>();
    // GEMM3: fout[4808,512] = enhT^T[4808,514] @ Emat[514,512]
    sgemm_t<1, 0><<<pgrid(BT, Nfft), 256, GS>>>(BT, Nfft, DD, pEnhT, BT, pEmat, Nfft, pFout, Nfft, nullptr);
    k_ola<<<(Bb * Ll + 255) / 256, 256>>>(out);
}

// round 15
// speedup vs baseline: 1.1483x; 1.0216x over previous
#include <cuda_runtime.h>
#include <math.h>
#include <stdint.h>

// ---------------- problem constants ----------------
#define Bb   8
#define Cc   8
#define Ll   96000
#define Nfft 512
#define Winl 320
#define Hop  160
#define Fq   257
#define Tt   601
#define NS   64            // B*C sequences
#define ROWS (NS*Tt)       // 38464
#define KF   320           // nonzero window support
#define DD   514           // 2F
#define DDp  516           // padded (16B-aligned rows)
#define GG   512           // 4H
#define HH   128
#define NM   1028          // 2*DD     (mask1|mask2)
#define BT   (Bb*Tt)       // 4808
#define TWO_PI 6.28318530717958647692f
#define MAXCTA 296         // 148 SMs x 2 CTAs

typedef unsigned long long u64;

// ---------------- device scratch ----------------
__device__ float  d_win[Nfft];
__device__ float  d_xT[(size_t)Bb * Cc * Ll];   // channel-major input
__device__ float  d_Bspec[KF * DDp];            // windowed DFT matrix [320][514(+2)]
__device__ float  d_BW[KF * GG];                // Bspec @ W_ih^T  [320][512]
__device__ float  d_WihT[DD * GG];
__device__ float  d_biasxw[GG];
__device__ float  d_Wmask[HH * NM];
__device__ float  d_bmask[NM];
__device__ float  d_Emat[DD * Nfft];
__device__ float  d_frames[(size_t)ROWS * KF];
__device__ float  d_specT[(size_t)DD * ROWS];   // f-major spectra
__device__ float  d_xw[(size_t)ROWS * GG];      // LSTM input projections
__device__ float  d_h[(size_t)ROWS * HH];
__device__ float  d_masksT[(size_t)NM * ROWS];  // f-major masks
__device__ float2 d_psd_s[Bb * Fq * 64];
__device__ float2 d_psd_n[Bb * Fq * 64];
__device__ float2 d_wbeam[Bb * Fq * Cc];
__device__ float  d_enhT[(size_t)DD * BT];      // f-major beamformed spectrum
__device__ float  d_fout[(size_t)BT * Nfft];

__device__ __forceinline__ float2 cmulf(float2 a, float2 b) {
    return make_float2(a.x * b.x - a.y * b.y, a.x * b.y + a.y * b.x);
}
__device__ __forceinline__ float sigmf(float x) { return 1.0f / (1.0f + expf(-x)); }

// packed f32x2 helpers (sm_103a FFMA2 path)
__device__ __forceinline__ u64 pk2(float lo, float hi) {
    u64 r; asm("mov.b64 %0, {%1, %2};" : "=l"(r) : "f"(lo), "f"(hi)); return r;
}
__device__ __forceinline__ u64 fma2(u64 a, u64 b, u64 c) {
    u64 d; asm("fma.rn.f32x2 %0, %1, %2, %3;" : "=l"(d) : "l"(a), "l"(b), "l"(c)); return d;
}
__device__ __forceinline__ void upk2(u64 v, float& lo, float& hi) {
    asm("mov.b64 {%0, %1}, %2;" : "=f"(lo), "=f"(hi) : "l"(v));
}
union F4U { float4 f; u64 u[2]; };

// ---------------- input transpose: x[b][l][c] -> xT[b][c][l] ----------------
__global__ void __launch_bounds__(256)
k_xpose(const float* __restrict__ x)
{
    __shared__ float tile[8][257];
    int b = blockIdx.y;
    int l0 = blockIdx.x * 256;
    int tid = threadIdx.x;
    const float* p = x + ((size_t)b * Ll + l0 + tid) * Cc;
    float4 v0 = *(const float4*)p;
    float4 v1 = *(const float4*)(p + 4);
    tile[0][tid] = v0.x; tile[1][tid] = v0.y; tile[2][tid] = v0.z; tile[3][tid] = v0.w;
    tile[4][tid] = v1.x; tile[5][tid] = v1.y; tile[6][tid] = v1.z; tile[7][tid] = v1.w;
    __syncthreads();
#pragma unroll
    for (int c = 0; c < 8; c++)
        d_xT[((size_t)b * Cc + c) * Ll + l0 + tid] = tile[c][tid];
}

// ---------------- frame gather (reflect pad), coalesced from xT -------------
__global__ void k_frames()
{
    int m = blockIdx.x;           // n*T + t
    int n = m / Tt, t = m - n * Tt;
    int r = threadIdx.x;          // 0..319
    int q = t * Hop + r - 160;    // sample index before reflect
    if (q < 0) q = -q;
    else if (q >= Ll) q = 2 * Ll - 2 - q;
    d_frames[(size_t)m * KF + r] = d_xT[(size_t)n * Ll + q];
}

// Bspec: windowed DFT (window computed inline)
__global__ void k_bspec() {
    int r = blockIdx.x;         // 0..319
    int c = threadIdx.x;        // 0..513
    if (c >= DD) return;
    int n = 96 + r;
    float w = 0.5f - 0.5f * cosf(TWO_PI * (float)r / (float)Winl);
    int k = (c < Fq) ? c : c - Fq;
    int m = (n * k) & (Nfft - 1);
    float th = (float)m * (TWO_PI / (float)Nfft);
    d_Bspec[r * DDp + c] = (c < Fq) ? w * cosf(th) : -w * sinf(th);
}

__global__ void k_win() {
    int i = threadIdx.x;
    float v = 0.f;
    if (i >= 96 && i < 96 + Winl)
        v = 0.5f - 0.5f * cosf(TWO_PI * (float)(i - 96) / (float)Winl);
    d_win[i] = v;
}

__global__ void k_pack_wih(const float* __restrict__ W_ih,
                           const float* __restrict__ b_ih,
                           const float* __restrict__ b_hh) {
    int idx = blockIdx.x * blockDim.x + threadIdx.x;
    if (idx < GG) d_biasxw[idx] = b_ih[idx] + b_hh[idx];
    if (idx >= DD * GG) return;
    int d = idx >> 9, g = idx & 511;
    d_WihT[idx] = W_ih[g * DD + d];
}

__global__ void k_pack_wmask(const float* __restrict__ W1, const float* __restrict__ b1,
                             const float* __restrict__ W2, const float* __restrict__ b2) {
    int j = blockIdx.x;    // 0..1027
    int k = threadIdx.x;   // 0..127
    float v = (j < DD) ? W1[j * HH + k] : W2[(j - DD) * HH + k];
    d_Wmask[k * NM + j] = v;
    if (k == 0) d_bmask[j] = (j < DD) ? b1[j] : b2[j - DD];
}

// iRFFT matrix with synthesis window folded in. imag of DC/Nyquist ignored (c2r).
__global__ void k_emat() {
    int row = blockIdx.x;   // 0..513
    int n   = threadIdx.x;  // 0..511
    float w = d_win[n];
    float val;
    if (row < Fq) {
        int k = row;
        float ck = (k == 0 || k == Nfft / 2) ? 1.0f : 2.0f;
        int m = (k * n) & (Nfft - 1);
        val = ck * (1.0f / (float)Nfft) * cosf((float)m * (TWO_PI / (float)Nfft)) * w;
    } else {
        int k = row - Fq;
        if (k == 0 || k == Nfft / 2) val = 0.f;
        else {
            int m = (k * n) & (Nfft - 1);
            val = -(2.0f / (float)Nfft) * sinf((float)m * (TWO_PI / (float)Nfft)) * w;
        }
    }
    d_Emat[row * Nfft + n] = val;
}

// ---------------- SGEMM: 128x128 tile, double-buffered, FFMA2 ----------------
// TA=0: A[M][K] lda=k-stride.  TA=1: A stored [K][M], lda=m-stride.
// TC=0: C[M][N] row-major.     TC=1: C stored [N][M] (C^T), ldc=m-stride.
struct Frag { float4 a[2]; float4 b[2]; };

template <int TA>
__device__ __forceinline__ void gload(Frag& f, int tid, int M, int N, int K,
                                      const float* __restrict__ A, int lda,
                                      const float* __restrict__ B, int ldb,
                                      int by, int bx, int k0)
{
#pragma unroll
    for (int l = 0; l < 2; l++) {
        int idx = tid + l * 256;
        if (TA == 0) {
            int arow = idx & 127, ak = (idx >> 7) << 2;
            int gr = by * 128 + arow, gk = k0 + ak;
            const float* pA = A + (size_t)gr * lda + gk;
            if (gr < M && gk + 3 < K) {
                f.a[l] = *(const float4*)pA;
            } else {
                f.a[l].x = (gr < M && gk     < K) ? pA[0] : 0.f;
                f.a[l].y = (gr < M && gk + 1 < K) ? pA[1] : 0.f;
                f.a[l].z = (gr < M && gk + 2 < K) ? pA[2] : 0.f;
                f.a[l].w = (gr < M && gk + 3 < K) ? pA[3] : 0.f;
            }
        } else {
            int ak = idx >> 5, ar4 = (idx & 31) << 2;
            int gk = k0 + ak, gr = by * 128 + ar4;
            const float* pA = A + (size_t)gk * lda + gr;
            if (gk < K && gr + 3 < M) {
                f.a[l] = *(const float4*)pA;
            } else {
                f.a[l].x = (gk < K && gr     < M) ? pA[0] : 0.f;
                f.a[l].y = (gk < K && gr + 1 < M) ? pA[1] : 0.f;
                f.a[l].z = (gk < K && gr + 2 < M) ? pA[2] : 0.f;
                f.a[l].w = (gk < K && gr + 3 < M) ? pA[3] : 0.f;
            }
        }
        int bkk = idx >> 5, bc = (idx & 31) << 2;
        int gc = bx * 128 + bc, gkb = k0 + bkk;
        const float* pB = B + (size_t)gkb * ldb + gc;
        if (gkb < K && gc + 3 < N) {
            f.b[l] = *(const float4*)pB;
        } else {
            f.b[l].x = (gkb < K && gc     < N) ? pB[0] : 0.f;
            f.b[l].y = (gkb < K && gc + 1 < N) ? pB[1] : 0.f;
            f.b[l].z = (gkb < K && gc + 2 < N) ? pB[2] : 0.f;
            f.b[l].w = (gkb < K && gc + 3 < N) ? pB[3] : 0.f;
        }
    }
}

template <int TA>
__device__ __forceinline__ void sstore(const Frag& f, int tid, int buf,
                                       float (*As)[16][128], float (*Bs)[16][128])
{
#pragma unroll
    for (int l = 0; l < 2; l++) {
        int idx = tid + l * 256;
        if (TA == 0) {
            int arow = idx & 127, ak = (idx >> 7) << 2;
            As[buf][ak + 0][arow] = f.a[l].x;
            As[buf][ak + 1][arow] = f.a[l].y;
            As[buf][ak + 2][arow] = f.a[l].z;
            As[buf][ak + 3][arow] = f.a[l].w;
        } else {
            int ak = idx >> 5, ar4 = (idx & 31) << 2;
            *(float4*)&As[buf][ak][ar4] = f.a[l];
        }
        int bkk = idx >> 5, bc = (idx & 31) << 2;
        *(float4*)&Bs[buf][bkk][bc] = f.b[l];
    }
}

template <int TA, int TC>
__global__ void __launch_bounds__(256, 2)
sgemm_t(int M, int N, int K,
        const float* __restrict__ A, int lda,
        const float* __restrict__ B, int ldb,
        float* __restrict__ C, int ldc,
        const float* __restrict__ bias)
{
    extern __shared__ float smembuf[];
    float (*As)[16][128] = (float(*)[16][128])smembuf;
    float (*Bs)[16][128] = (float(*)[16][128])(smembuf + 4096);
    int tid = threadIdx.x;
    int tx = tid & 15, ty = tid >> 4;

    int ntx = (N + 127) >> 7, nty = (M + 127) >> 7;
    int ntiles = ntx * nty;
    int nk = (K + 15) >> 4;

    for (int tile = blockIdx.x; tile < ntiles; tile += gridDim.x) {
        int bx = tile % ntx, by = tile / ntx;
        __syncthreads();   // protect smem reuse across tiles

        u64 acc[8][4];
#pragma unroll
        for (int a = 0; a < 8; a++)
#pragma unroll
            for (int j = 0; j < 4; j++) acc[a][j] = pk2(0.f, 0.f);

        Frag f;
        gload<TA>(f, tid, M, N, K, A, lda, B, ldb, by, bx, 0);
        sstore<TA>(f, tid, 0, As, Bs);
        __syncthreads();

        for (int kt = 0; kt < nk; kt++) {
            int cur = kt & 1;
            if (kt + 1 < nk)
                gload<TA>(f, tid, M, N, K, A, lda, B, ldb, by, bx, (kt + 1) << 4);
#pragma unroll
            for (int k = 0; k < 16; k++) {
                float4 a0 = *(const float4*)&As[cur][k][ty * 4];
                float4 a1 = *(const float4*)&As[cur][k][64 + ty * 4];
                F4U B0, B1;
                B0.f = *(const float4*)&Bs[cur][k][tx * 4];
                B1.f = *(const float4*)&Bs[cur][k][64 + tx * 4];
                float av[8] = {a0.x, a0.y, a0.z, a0.w, a1.x, a1.y, a1.z, a1.w};
#pragma unroll
                for (int a = 0; a < 8; a++) {
                    u64 pa = pk2(av[a], av[a]);
                    acc[a][0] = fma2(pa, B0.u[0], acc[a][0]);
                    acc[a][1] = fma2(pa, B0.u[1], acc[a][1]);
                    acc[a][2] = fma2(pa, B1.u[0], acc[a][2]);
                    acc[a][3] = fma2(pa, B1.u[1], acc[a][3]);
                }
            }
            if (kt + 1 < nk) {
                int nxt = 1 - cur;
                sstore<TA>(f, tid, nxt, As, Bs);
                __syncthreads();
            }
        }

        if (TC == 0) {
#pragma unroll
            for (int a = 0; a < 8; a++) {
                int row = by * 128 + ((a & 4) << 4) + ty * 4 + (a & 3);
                if (row >= M) continue;
#pragma unroll
                for (int j = 0; j < 4; j++) {
                    float lo, hi;
                    upk2(acc[a][j], lo, hi);
                    int colb = bx * 128 + ((j >= 2) ? 64 : 0) + tx * 4 + (j & 1) * 2;
                    if (colb < N)     C[(size_t)row * ldc + colb]     = lo + (bias ? bias[colb]     : 0.f);
                    if (colb + 1 < N) C[(size_t)row * ldc + colb + 1] = hi + (bias ? bias[colb + 1] : 0.f);
                }
            }
        } else {
            // transposed-C epilogue: stage 128x64 halves (pitch 132), float4 out
            float* S = smembuf;   // 64*132 floats
            __syncthreads();
#pragma unroll
            for (int hh = 0; hh < 2; hh++) {
#pragma unroll
                for (int a = 0; a < 8; a++) {
                    int row = ((a & 4) << 4) + ty * 4 + (a & 3);
#pragma unroll
                    for (int jj = 0; jj < 2; jj++) {
                        int j = hh * 2 + jj;
                        float lo, hi;
                        upk2(acc[a][j], lo, hi);
                        int col = tx * 4 + jj * 2;
                        S[col * 132 + row]       = lo;
                        S[(col + 1) * 132 + row] = hi;
                    }
                }
                __syncthreads();
#pragma unroll
                for (int u = 0; u < 8; u++) {
                    int unit = tid + u * 256;        // 0..2047
                    int col = unit >> 5;             // 0..63
                    int r4 = (unit & 31) << 2;       // 0..124
                    int gcol = bx * 128 + hh * 64 + col;
                    int grow = by * 128 + r4;
                    if (gcol >= N) continue;
                    float bb = bias ? bias[gcol] : 0.f;
                    if (grow + 3 < M) {
                        float4 v = *(const float4*)&S[col * 132 + r4];
                        v.x += bb; v.y += bb; v.z += bb; v.w += bb;
                        *(float4*)&C[(size_t)gcol * ldc + grow] = v;
                    } else {
#pragma unroll
                        for (int q = 0; q < 4; q++)
                            if (grow + q < M)
                                C[(size_t)gcol * ldc + grow + q] = S[col * 132 + r4 + q] + bb;
                    }
                }
                __syncthreads();
            }
        }
    }
}

static inline int pgrid(int M, int N) {
    int t = ((M + 127) >> 7) * ((N + 127) >> 7);
    return t < MAXCTA ? t : MAXCTA;
}
// full tile grid (non-persistent): lets HW backfill SMs during concurrency
static inline int fgrid(int M, int N) {
    return ((M + 127) >> 7) * ((N + 127) >> 7);
}

// ---------------- LSTM: 64 persistent blocks, 512 threads, FFMA2 -------------
__global__ void __launch_bounds__(512, 1)
lstm_k(const float* __restrict__ W_hh)
{
    extern __shared__ float4 Wv2[];
    __shared__ __align__(16) float h_s[128];
    __shared__ float g_s[512];
    int n = blockIdx.x, g = threadIdx.x;

    u64 wp[32];
#pragma unroll
    for (int i = 0; i < 16; i++) {
        float4 w4 = *(const float4*)(W_hh + (size_t)g * 128 + 4 * i);
        wp[2 * i]     = pk2(w4.x, w4.y);
        wp[2 * i + 1] = pk2(w4.z, w4.w);
    }
    for (int j = g; j < 16 * 512; j += 512) {
        int i = j >> 9, gg = j & 511;
        Wv2[j] = *(const float4*)(W_hh + (size_t)gg * 128 + 64 + 4 * i);
    }
    float cst = 0.f;
    if (g < 128) h_s[g] = 0.f;
    __syncthreads();

    const float* xwb  = d_xw + (size_t)n * Tt * GG;
    float*       hout = d_h  + (size_t)n * Tt * HH;
    const u64*   h2   = (const u64*)h_s;
    const u64*   wv2u = (const u64*)Wv2;

    float xnext = xwb[g];
    for (int t = 0; t < Tt; t++) {
        float xcur = xnext;
        if (t + 1 < Tt) xnext = xwb[(size_t)(t + 1) * GG + g];
        u64 c0 = pk2(xcur, 0.f);
        u64 c1 = pk2(0.f, 0.f), c2 = pk2(0.f, 0.f), c3 = pk2(0.f, 0.f);
#pragma unroll
        for (int i = 0; i < 32; i += 4) {
            c0 = fma2(wp[i],     h2[i],     c0);
            c1 = fma2(wp[i + 1], h2[i + 1], c1);
            c2 = fma2(wp[i + 2], h2[i + 2], c2);
            c3 = fma2(wp[i + 3], h2[i + 3], c3);
        }
#pragma unroll
        for (int i = 0; i < 16; i += 2) {
            c0 = fma2(wv2u[2 * (i * 512 + g)],           h2[32 + 2 * i],     c0);
            c1 = fma2(wv2u[2 * (i * 512 + g) + 1],       h2[32 + 2 * i + 1], c1);
            c2 = fma2(wv2u[2 * ((i + 1) * 512 + g)],     h2[32 + 2 * i + 2], c2);
            c3 = fma2(wv2u[2 * ((i + 1) * 512 + g) + 1], h2[32 + 2 * i + 3], c3);
        }
        float s0, s1, s2, s3, s4, s5, s6, s7;
        upk2(c0, s0, s1); upk2(c1, s2, s3); upk2(c2, s4, s5); upk2(c3, s6, s7);
        g_s[g] = ((s0 + s1) + (s2 + s3)) + ((s4 + s5) + (s6 + s7));
        __syncthreads();
        if (g < 128) {
            float iv = sigmf(g_s[g]);
            float fv = sigmf(g_s[128 + g]);
            float gv = tanhf(g_s[256 + g]);
            float ov = sigmf(g_s[384 + g]);
            cst = fv * cst + iv * gv;
            float hv = ov * tanhf(cst);
            h_s[g] = hv;
            hout[(size_t)t * HH + g] = hv;
        }
        __syncthreads();
    }
}

// ---------------- PSD: one block per (b,f), f-major coalesced loads ----------
__global__ void __launch_bounds__(256)
psd_k()
{
    int bf = blockIdx.x;
    int b = bf / Fq, f = bf - b * Fq;
    __shared__ float2 sv[8][33];
    __shared__ float2 nv[8][33];
    int tid = threadIdx.x;
    int cl = tid >> 5, ts = tid & 31;
    int p = tid >> 2, sub = tid & 3;
    int cc = p >> 3, ee = p & 7;
    float2 as = make_float2(0.f, 0.f), an = make_float2(0.f, 0.f);

    const float* sre  = d_specT  + (size_t)f * ROWS;
    const float* sim  = d_specT  + (size_t)(Fq + f) * ROWS;
    const float* m1re = d_masksT + (size_t)f * ROWS;
    const float* m1im = d_masksT + (size_t)(Fq + f) * ROWS;
    const float* m2re = d_masksT + (size_t)(DD + f) * ROWS;
    const float* m2im = d_masksT + (size_t)(DD + Fq + f) * ROWS;

    for (int t0 = 0; t0 < Tt; t0 += 32) {
        int t = t0 + ts;
        float2 svv = make_float2(0.f, 0.f), nvv = make_float2(0.f, 0.f);
        if (t < Tt) {
            size_t row = (size_t)(b * 8 + cl) * Tt + t;
            float2 s  = make_float2(sre[row],  sim[row]);
            float2 m1 = make_float2(m1re[row], m1im[row]);
            float2 m2 = make_float2(m2re[row], m2im[row]);
            svv = cmulf(m1, s);
            nvv = cmulf(m2, s);
        }
        sv[cl][ts] = svv;
        nv[cl][ts] = nvv;
        __syncthreads();
#pragma unroll
        for (int j = 0; j < 8; j++) {
            int q = sub * 8 + j;
            float2 a = sv[cc][q], bq = sv[ee][q];
            as.x += a.x * bq.x + a.y * bq.y;
            as.y += a.y * bq.x - a.x * bq.y;
            a = nv[cc][q]; bq = nv[ee][q];
            an.x += a.x * bq.x + a.y * bq.y;
            an.y += a.y * bq.x - a.x * bq.y;
        }
        __syncthreads();
    }
#pragma unroll
    for (int o = 2; o >= 1; o >>= 1) {
        as.x += __shfl_down_sync(0xffffffffu, as.x, o);
        as.y += __shfl_down_sync(0xffffffffu, as.y, o);
        an.x += __shfl_down_sync(0xffffffffu, an.x, o);
        an.y += __shfl_down_sync(0xffffffffu, an.y, o);
    }
    if (sub == 0) {
        float invT = 1.0f / (float)Tt;
        d_psd_s[(size_t)bf * 64 + p] = make_float2(as.x * invT, as.y * invT);
        d_psd_n[(size_t)bf * 64 + p] = make_float2(an.x * invT, an.y * invT);
    }
}

// ---------------- solve: 8x8 complex Gauss-Jordan, 32 systems/block ----------
#define ANm(i,j) mem[((i)*8+(j))*32 + tid]
#define ASm(i,j) mem[(64+(i)*8+(j))*32 + tid]
__global__ void __launch_bounds__(32)
solve_k()
{
    __shared__ float2 mem[128 * 32];
    int tid = threadIdx.x;
    int sys = blockIdx.x * 32 + tid;
    if (sys >= Bb * Fq) return;

    for (int e = 0; e < 64; e++) {
        mem[e * 32 + tid]        = d_psd_n[(size_t)sys * 64 + e];
        mem[(64 + e) * 32 + tid] = d_psd_s[(size_t)sys * 64 + e];
    }
    float tr = 0.f;
    for (int i = 0; i < 8; i++) tr += ANm(i, i).x;
    float lam = 1e-6f * tr / 8.0f + 1e-8f;
    for (int i = 0; i < 8; i++) ANm(i, i).x += lam;
    for (int p = 0; p < 8; p++) {
        float2 piv = ANm(p, p);
        float dinv = 1.0f / (piv.x * piv.x + piv.y * piv.y);
        float2 ip = make_float2(piv.x * dinv, -piv.y * dinv);
        for (int j = 0; j < 8; j++) {
            ANm(p, j) = cmulf(ANm(p, j), ip);
            ASm(p, j) = cmulf(ASm(p, j), ip);
        }
        for (int r = 0; r < 8; r++) {
            if (r == p) continue;
            float2 fct = ANm(r, p);
            for (int j = 0; j < 8; j++) {
                float2 t1 = cmulf(fct, ANm(p, j));
                float2 t2 = cmulf(fct, ASm(p, j));
                ANm(r, j).x -= t1.x; ANm(r, j).y -= t1.y;
                ASm(r, j).x -= t2.x; ASm(r, j).y -= t2.y;
            }
        }
    }
    float2 tr2 = make_float2(1e-8f, 0.f);
    for (int i = 0; i < 8; i++) {
        tr2.x += ASm(i, i).x;
        tr2.y += ASm(i, i).y;
    }
    float dinv = 1.0f / (tr2.x * tr2.x + tr2.y * tr2.y);
    float2 itr = make_float2(tr2.x * dinv, -tr2.y * dinv);
    for (int c = 0; c < 8; c++) {
        float2 wv = cmulf(ASm(c, 0), itr);
        d_wbeam[(size_t)sys * 8 + c] = make_float2(wv.x, -wv.y);   // store conj(w)
    }
}

// ---------------- beamform: block per (b,f), coalesced over t ----------------
__global__ void __launch_bounds__(256)
beam_k()
{
    int bf = blockIdx.x;
    int b = bf / Fq, f = bf - b * Fq;
    const float2* w = d_wbeam + (size_t)bf * 8;
    float2 wc[8];
#pragma unroll
    for (int c = 0; c < 8; c++) wc[c] = w[c];
    const float* sre = d_specT + (size_t)f * ROWS;
    const float* sim = d_specT + (size_t)(Fq + f) * ROWS;
    for (int t = threadIdx.x; t < Tt; t += 256) {
        float2 acc = make_float2(0.f, 0.f);
#pragma unroll
        for (int c = 0; c < 8; c++) {
            size_t row = (size_t)(b * 8 + c) * Tt + t;
            float2 s = make_float2(sre[row], sim[row]);
            acc.x += wc[c].x * s.x - wc[c].y * s.y;
            acc.y += wc[c].x * s.y + wc[c].y * s.x;
        }
        d_enhT[(size_t)f * BT + b * Tt + t]        = acc.x;
        d_enhT[(size_t)(Fq + f) * BT + b * Tt + t] = acc.y;
    }
}

// ---------------- overlap-add + normalization + crop ----------------
__global__ void k_ola(float* __restrict__ out)
{
    int idx = blockIdx.x * blockDim.x + threadIdx.x;
    if (idx >= Bb * Ll) return;
    int b = idx / Ll, l = idx - b * Ll;
    int p = l + 256;
    int tmin = (p >= Nfft) ? (p - Nfft) / Hop + 1 : 0;
    int tmax = p / Hop; if (tmax > Tt - 1) tmax = Tt - 1;
    float acc = 0.f, wsq = 0.f;
    for (int t = tmin; t <= tmax; t++) {
        int n = p - t * Hop;
        float wv = d_win[n];
        acc += d_fout[((size_t)b * Tt + t) * Nfft + n];
        wsq += wv * wv;
    }
    out[idx] = acc / fmaxf(wsq, 1e-11f);
}

// ---------------- launch ----------------
extern "C" void kernel_launch(void* const* d_in, const int* in_sizes, int n_in,
                              void* d_out, int out_size)
{
    const float* x    = (const float*)d_in[0];
    const float* W_ih = (const float*)d_in[1];
    const float* W_hh = (const float*)d_in[2];
    const float* b_ih = (const float*)d_in[3];
    const float* b_hh = (const float*)d_in[4];
    const float* W1   = (const float*)d_in[5];
    const float* b1   = (const float*)d_in[6];
    const float* W2   = (const float*)d_in[7];
    const float* b2   = (const float*)d_in[8];
    float* out = (float*)d_out;

    cudaFuncSetAttribute(lstm_k, cudaFuncAttributeMaxDynamicSharedMemorySize, 131072);
    const int GS = 64 * 132 * 4;   // 33792 B dyn smem

    float *pBspec, *pBW, *pWihT, *pBiasxw, *pWmask, *pBmask, *pEmat;
    float *pFrames, *pSpecT, *pXw, *pH, *pMasksT, *pEnhT, *pFout;
    cudaGetSymbolAddress((void**)&pBspec,  d_Bspec);
    cudaGetSymbolAddress((void**)&pBW,     d_BW);
    cudaGetSymbolAddress((void**)&pWihT,   d_WihT);
    cudaGetSymbolAddress((void**)&pBiasxw, d_biasxw);
    cudaGetSymbolAddress((void**)&pWmask,  d_Wmask);
    cudaGetSymbolAddress((void**)&pBmask,  d_bmask);
    cudaGetSymbolAddress((void**)&pEmat,   d_Emat);
    cudaGetSymbolAddress((void**)&pFrames, d_frames);
    cudaGetSymbolAddress((void**)&pSpecT,  d_specT);
    cudaGetSymbolAddress((void**)&pXw,     d_xw);
    cudaGetSymbolAddress((void**)&pH,      d_h);
    cudaGetSymbolAddress((void**)&pMasksT, d_masksT);
    cudaGetSymbolAddress((void**)&pEnhT,   d_enhT);
    cudaGetSymbolAddress((void**)&pFout,   d_fout);

    cudaStream_t s2;
    cudaStreamCreateWithFlags(&s2, cudaStreamNonBlocking);
    cudaEvent_t e1, e2;
    cudaEventCreateWithFlags(&e1, cudaEventDisableTiming);
    cudaEventCreateWithFlags(&e2, cudaEventDisableTiming);

    {   // input transpose
        dim3 grid(Ll / 256, Bb);
        k_xpose<<<grid, 256>>>(x);
    }
    k_frames<<<ROWS, KF>>>();
    k_bspec<<<KF, DD>>>();
    k_pack_wih<<<(DD * GG + 255) / 256, 256>>>(W_ih, b_ih, b_hh);
    // GEMM0: BW[320,512] = Bspec[320,514] @ WihT[514,512]
    sgemm_t<0, 0><<<pgrid(KF, GG), 256, GS>>>(KF, GG, DD, pBspec, DDp, pWihT, GG, pBW, GG, nullptr);
    // GEMM1b: xw[ROWS][512] = frames @ BW + bias
    sgemm_t<0, 0><<<pgrid(ROWS, GG), 256, GS>>>(ROWS, GG, KF, pFrames, KF, pBW, GG, pXw, GG, pBiasxw);

    // ---- fork: branch B (s2) = GEMM1a (NON-persistent: one tile per CTA so the
    //      HW scheduler backfills SMs as the LSTM runs/drains) + win + emat ----
    cudaEventRecord(e1, 0);
    cudaStreamWaitEvent(s2, e1, 0);
    sgemm_t<0, 1><<<fgrid(ROWS, DD), 256, GS, s2>>>(ROWS, DD, KF, pFrames, KF, pBspec, DDp, pSpecT, ROWS, nullptr);
    k_win<<<1, Nfft, 0, s2>>>();
    k_emat<<<DD, Nfft, 0, s2>>>();
    cudaEventRecord(e2, s2);

    // ---- branch A (default stream): LSTM -> mask GEMM (also non-persistent) ----
    lstm_k<<<NS, 512, 131072>>>(W_hh);
    k_pack_wmask<<<NM, HH>>>(W1, b1, W2, b2);
    sgemm_t<0, 1><<<fgrid(ROWS, NM), 256, GS>>>(ROWS, NM, HH, pH, HH, pWmask, NM, pMasksT, ROWS, pBmask);

    // ---- join: psd needs specT (branch B) + masksT (branch A) ----
    cudaStreamWaitEvent(0, e2, 0);
    psd_k<<<Bb * Fq, 256>>>();
    solve_k<<<(Bb * Fq + 31) / 32, 32>>>();
    beam_k<<<Bb * Fq, 256>>>();
    // GEMM3: fout[4808,512] = enhT^T[4808,514] @ Emat[514,512]
    sgemm_t<1, 0><<<pgrid(BT, Nfft), 256, GS>>>(BT, Nfft, DD, pEnhT, BT, pEmat, Nfft, pFout, Nfft, nullptr);
    k_ola<<<(Bb * Ll + 255) / 256, 256>>>(out);
}

// round 16
// speedup vs baseline: 1.2805x; 1.1151x over previous
#include <cuda_runtime.h>
#include <math.h>
#include <stdint.h>

// ---------------- problem constants ----------------
#define Bb   8
#define Cc   8
#define Ll   96000
#define Nfft 512
#define Winl 320
#define Hop  160
#define Fq   257
#define Tt   601
#define NS   64            // B*C sequences
#define ROWS (NS*Tt)       // 38464
#define KF   320           // nonzero window support
#define DD   514           // 2F
#define DDp  516           // padded (16B-aligned rows)
#define GG   512           // 4H
#define HH   128
#define NM   1028          // 2*DD     (mask1|mask2)
#define BT   (Bb*Tt)       // 4808
#define TWO_PI 6.28318530717958647692f
#define MAXCTA 296         // 148 SMs x 2 CTAs

typedef unsigned long long u64;

// ---------------- device scratch ----------------
__device__ float  d_win[Nfft];
__device__ float  d_xT[(size_t)Bb * Cc * Ll];   // channel-major input
__device__ float  d_Bspec[KF * DDp];            // windowed DFT matrix [320][514(+2)]
__device__ float  d_BW[KF * GG];                // Bspec @ W_ih^T  [320][512]
__device__ float  d_WihT[DD * GG];
__device__ float  d_biasxw[GG];
__device__ float  d_Wmask[HH * NM];
__device__ float  d_bmask[NM];
__device__ float  d_Emat[DD * Nfft];
__device__ float  d_frames[(size_t)ROWS * KF];
__device__ float  d_specT[(size_t)DD * ROWS];   // f-major spectra
__device__ float  d_xw[(size_t)ROWS * GG];      // LSTM input projections
__device__ float  d_h[(size_t)ROWS * HH];
__device__ float  d_masksT[(size_t)NM * ROWS];  // f-major masks
__device__ float2 d_psd_s[Bb * Fq * 64];
__device__ float2 d_psd_n[Bb * Fq * 64];
__device__ float2 d_wbeam[Bb * Fq * Cc];
__device__ float  d_enhT[(size_t)DD * BT];      // f-major beamformed spectrum
__device__ float  d_fout[(size_t)BT * Nfft];

__device__ __forceinline__ float2 cmulf(float2 a, float2 b) {
    return make_float2(a.x * b.x - a.y * b.y, a.x * b.y + a.y * b.x);
}
__device__ __forceinline__ float sigmf(float x) { return 1.0f / (1.0f + expf(-x)); }

// packed f32x2 helpers (sm_103a FFMA2 path)
__device__ __forceinline__ u64 pk2(float lo, float hi) {
    u64 r; asm("mov.b64 %0, {%1, %2};" : "=l"(r) : "f"(lo), "f"(hi)); return r;
}
__device__ __forceinline__ u64 fma2(u64 a, u64 b, u64 c) {
    u64 d; asm("fma.rn.f32x2 %0, %1, %2, %3;" : "=l"(d) : "l"(a), "l"(b), "l"(c)); return d;
}
__device__ __forceinline__ void upk2(u64 v, float& lo, float& hi) {
    asm("mov.b64 {%0, %1}, %2;" : "=f"(lo), "=f"(hi) : "l"(v));
}
union F4U { float4 f; u64 u[2]; };

// ---------------- input transpose: x[b][l][c] -> xT[b][c][l] ----------------
__global__ void __launch_bounds__(256)
k_xpose(const float* __restrict__ x)
{
    __shared__ float tile[8][257];
    int b = blockIdx.y;
    int l0 = blockIdx.x * 256;
    int tid = threadIdx.x;
    const float* p = x + ((size_t)b * Ll + l0 + tid) * Cc;
    float4 v0 = *(const float4*)p;
    float4 v1 = *(const float4*)(p + 4);
    tile[0][tid] = v0.x; tile[1][tid] = v0.y; tile[2][tid] = v0.z; tile[3][tid] = v0.w;
    tile[4][tid] = v1.x; tile[5][tid] = v1.y; tile[6][tid] = v1.z; tile[7][tid] = v1.w;
    __syncthreads();
#pragma unroll
    for (int c = 0; c < 8; c++)
        d_xT[((size_t)b * Cc + c) * Ll + l0 + tid] = tile[c][tid];
}

// ---------------- frame gather (reflect pad), coalesced from xT -------------
__global__ void k_frames()
{
    int m = blockIdx.x;           // n*T + t
    int n = m / Tt, t = m - n * Tt;
    int r = threadIdx.x;          // 0..319
    int q = t * Hop + r - 160;    // sample index before reflect
    if (q < 0) q = -q;
    else if (q >= Ll) q = 2 * Ll - 2 - q;
    d_frames[(size_t)m * KF + r] = d_xT[(size_t)n * Ll + q];
}

// Bspec: windowed DFT (window computed inline)
__global__ void k_bspec() {
    int r = blockIdx.x;         // 0..319
    int c = threadIdx.x;        // 0..513
    if (c >= DD) return;
    int n = 96 + r;
    float w = 0.5f - 0.5f * cosf(TWO_PI * (float)r / (float)Winl);
    int k = (c < Fq) ? c : c - Fq;
    int m = (n * k) & (Nfft - 1);
    float th = (float)m * (TWO_PI / (float)Nfft);
    d_Bspec[r * DDp + c] = (c < Fq) ? w * cosf(th) : -w * sinf(th);
}

__global__ void k_win() {
    int i = threadIdx.x;
    float v = 0.f;
    if (i >= 96 && i < 96 + Winl)
        v = 0.5f - 0.5f * cosf(TWO_PI * (float)(i - 96) / (float)Winl);
    d_win[i] = v;
}

__global__ void k_pack_wih(const float* __restrict__ W_ih,
                           const float* __restrict__ b_ih,
                           const float* __restrict__ b_hh) {
    int idx = blockIdx.x * blockDim.x + threadIdx.x;
    if (idx < GG) d_biasxw[idx] = b_ih[idx] + b_hh[idx];
    if (idx >= DD * GG) return;
    int d = idx >> 9, g = idx & 511;
    d_WihT[idx] = W_ih[g * DD + d];
}

__global__ void k_pack_wmask(const float* __restrict__ W1, const float* __restrict__ b1,
                             const float* __restrict__ W2, const float* __restrict__ b2) {
    int j = blockIdx.x;    // 0..1027
    int k = threadIdx.x;   // 0..127
    float v = (j < DD) ? W1[j * HH + k] : W2[(j - DD) * HH + k];
    d_Wmask[k * NM + j] = v;
    if (k == 0) d_bmask[j] = (j < DD) ? b1[j] : b2[j - DD];
}

// iRFFT matrix with synthesis window folded in. imag of DC/Nyquist ignored (c2r).
__global__ void k_emat() {
    int row = blockIdx.x;   // 0..513
    int n   = threadIdx.x;  // 0..511
    float w = d_win[n];
    float val;
    if (row < Fq) {
        int k = row;
        float ck = (k == 0 || k == Nfft / 2) ? 1.0f : 2.0f;
        int m = (k * n) & (Nfft - 1);
        val = ck * (1.0f / (float)Nfft) * cosf((float)m * (TWO_PI / (float)Nfft)) * w;
    } else {
        int k = row - Fq;
        if (k == 0 || k == Nfft / 2) val = 0.f;
        else {
            int m = (k * n) & (Nfft - 1);
            val = -(2.0f / (float)Nfft) * sinf((float)m * (TWO_PI / (float)Nfft)) * w;
        }
    }
    d_Emat[row * Nfft + n] = val;
}

// ---------------- SGEMM: 128x128 tile, double-buffered, FFMA2 ----------------
// TA=0: A[M][K] lda=k-stride.  TA=1: A stored [K][M], lda=m-stride.
// TC=0: C[M][N] row-major.     TC=1: C stored [N][M] (C^T), ldc=m-stride.
struct Frag { float4 a[2]; float4 b[2]; };

template <int TA>
__device__ __forceinline__ void gload(Frag& f, int tid, int M, int N, int K,
                                      const float* __restrict__ A, int lda,
                                      const float* __restrict__ B, int ldb,
                                      int by, int bx, int k0)
{
#pragma unroll
    for (int l = 0; l < 2; l++) {
        int idx = tid + l * 256;
        if (TA == 0) {
            int arow = idx & 127, ak = (idx >> 7) << 2;
            int gr = by * 128 + arow, gk = k0 + ak;
            const float* pA = A + (size_t)gr * lda + gk;
            if (gr < M && gk + 3 < K) {
                f.a[l] = *(const float4*)pA;
            } else {
                f.a[l].x = (gr < M && gk     < K) ? pA[0] : 0.f;
                f.a[l].y = (gr < M && gk + 1 < K) ? pA[1] : 0.f;
                f.a[l].z = (gr < M && gk + 2 < K) ? pA[2] : 0.f;
                f.a[l].w = (gr < M && gk + 3 < K) ? pA[3] : 0.f;
            }
        } else {
            int ak = idx >> 5, ar4 = (idx & 31) << 2;
            int gk = k0 + ak, gr = by * 128 + ar4;
            const float* pA = A + (size_t)gk * lda + gr;
            if (gk < K && gr + 3 < M) {
                f.a[l] = *(const float4*)pA;
            } else {
                f.a[l].x = (gk < K && gr     < M) ? pA[0] : 0.f;
                f.a[l].y = (gk < K && gr + 1 < M) ? pA[1] : 0.f;
                f.a[l].z = (gk < K && gr + 2 < M) ? pA[2] : 0.f;
                f.a[l].w = (gk < K && gr + 3 < M) ? pA[3] : 0.f;
            }
        }
        int bkk = idx >> 5, bc = (idx & 31) << 2;
        int gc = bx * 128 + bc, gkb = k0 + bkk;
        const float* pB = B + (size_t)gkb * ldb + gc;
        if (gkb < K && gc + 3 < N) {
            f.b[l] = *(const float4*)pB;
        } else {
            f.b[l].x = (gkb < K && gc     < N) ? pB[0] : 0.f;
            f.b[l].y = (gkb < K && gc + 1 < N) ? pB[1] : 0.f;
            f.b[l].z = (gkb < K && gc + 2 < N) ? pB[2] : 0.f;
            f.b[l].w = (gkb < K && gc + 3 < N) ? pB[3] : 0.f;
        }
    }
}

template <int TA>
__device__ __forceinline__ void sstore(const Frag& f, int tid, int buf,
                                       float (*As)[16][128], float (*Bs)[16][128])
{
#pragma unroll
    for (int l = 0; l < 2; l++) {
        int idx = tid + l * 256;
        if (TA == 0) {
            int arow = idx & 127, ak = (idx >> 7) << 2;
            As[buf][ak + 0][arow] = f.a[l].x;
            As[buf][ak + 1][arow] = f.a[l].y;
            As[buf][ak + 2][arow] = f.a[l].z;
            As[buf][ak + 3][arow] = f.a[l].w;
        } else {
            int ak = idx >> 5, ar4 = (idx & 31) << 2;
            *(float4*)&As[buf][ak][ar4] = f.a[l];
        }
        int bkk = idx >> 5, bc = (idx & 31) << 2;
        *(float4*)&Bs[buf][bkk][bc] = f.b[l];
    }
}

template <int TA, int TC>
__global__ void __launch_bounds__(256, 2)
sgemm_t(int M, int N, int K,
        const float* __restrict__ A, int lda,
        const float* __restrict__ B, int ldb,
        float* __restrict__ C, int ldc,
        const float* __restrict__ bias)
{
    extern __shared__ float smembuf[];
    float (*As)[16][128] = (float(*)[16][128])smembuf;
    float (*Bs)[16][128] = (float(*)[16][128])(smembuf + 4096);
    int tid = threadIdx.x;
    int tx = tid & 15, ty = tid >> 4;

    int ntx = (N + 127) >> 7, nty = (M + 127) >> 7;
    int ntiles = ntx * nty;
    int nk = (K + 15) >> 4;

    for (int tile = blockIdx.x; tile < ntiles; tile += gridDim.x) {
        int bx = tile % ntx, by = tile / ntx;
        __syncthreads();   // protect smem reuse across tiles

        u64 acc[8][4];
#pragma unroll
        for (int a = 0; a < 8; a++)
#pragma unroll
            for (int j = 0; j < 4; j++) acc[a][j] = pk2(0.f, 0.f);

        Frag f;
        gload<TA>(f, tid, M, N, K, A, lda, B, ldb, by, bx, 0);
        sstore<TA>(f, tid, 0, As, Bs);
        __syncthreads();

        for (int kt = 0; kt < nk; kt++) {
            int cur = kt & 1;
            if (kt + 1 < nk)
                gload<TA>(f, tid, M, N, K, A, lda, B, ldb, by, bx, (kt + 1) << 4);
#pragma unroll
            for (int k = 0; k < 16; k++) {
                float4 a0 = *(const float4*)&As[cur][k][ty * 4];
                float4 a1 = *(const float4*)&As[cur][k][64 + ty * 4];
                F4U B0, B1;
                B0.f = *(const float4*)&Bs[cur][k][tx * 4];
                B1.f = *(const float4*)&Bs[cur][k][64 + tx * 4];
                float av[8] = {a0.x, a0.y, a0.z, a0.w, a1.x, a1.y, a1.z, a1.w};
#pragma unroll
                for (int a = 0; a < 8; a++) {
                    u64 pa = pk2(av[a], av[a]);
                    acc[a][0] = fma2(pa, B0.u[0], acc[a][0]);
                    acc[a][1] = fma2(pa, B0.u[1], acc[a][1]);
                    acc[a][2] = fma2(pa, B1.u[0], acc[a][2]);
                    acc[a][3] = fma2(pa, B1.u[1], acc[a][3]);
                }
            }
            if (kt + 1 < nk) {
                int nxt = 1 - cur;
                sstore<TA>(f, tid, nxt, As, Bs);
                __syncthreads();
            }
        }

        if (TC == 0) {
#pragma unroll
            for (int a = 0; a < 8; a++) {
                int row = by * 128 + ((a & 4) << 4) + ty * 4 + (a & 3);
                if (row >= M) continue;
#pragma unroll
                for (int j = 0; j < 4; j++) {
                    float lo, hi;
                    upk2(acc[a][j], lo, hi);
                    int colb = bx * 128 + ((j >= 2) ? 64 : 0) + tx * 4 + (j & 1) * 2;
                    if (colb < N)     C[(size_t)row * ldc + colb]     = lo + (bias ? bias[colb]     : 0.f);
                    if (colb + 1 < N) C[(size_t)row * ldc + colb + 1] = hi + (bias ? bias[colb + 1] : 0.f);
                }
            }
        } else {
            // transposed-C epilogue: stage 128x64 halves (pitch 132), float4 out
            float* S = smembuf;   // 64*132 floats
            __syncthreads();
#pragma unroll
            for (int hh = 0; hh < 2; hh++) {
#pragma unroll
                for (int a = 0; a < 8; a++) {
                    int row = ((a & 4) << 4) + ty * 4 + (a & 3);
#pragma unroll
                    for (int jj = 0; jj < 2; jj++) {
                        int j = hh * 2 + jj;
                        float lo, hi;
                        upk2(acc[a][j], lo, hi);
                        int col = tx * 4 + jj * 2;
                        S[col * 132 + row]       = lo;
                        S[(col + 1) * 132 + row] = hi;
                    }
                }
                __syncthreads();
#pragma unroll
                for (int u = 0; u < 8; u++) {
                    int unit = tid + u * 256;        // 0..2047
                    int col = unit >> 5;             // 0..63
                    int r4 = (unit & 31) << 2;       // 0..124
                    int gcol = bx * 128 + hh * 64 + col;
                    int grow = by * 128 + r4;
                    if (gcol >= N) continue;
                    float bb = bias ? bias[gcol] : 0.f;
                    if (grow + 3 < M) {
                        float4 v = *(const float4*)&S[col * 132 + r4];
                        v.x += bb; v.y += bb; v.z += bb; v.w += bb;
                        *(float4*)&C[(size_t)gcol * ldc + grow] = v;
                    } else {
#pragma unroll
                        for (int q = 0; q < 4; q++)
                            if (grow + q < M)
                                C[(size_t)gcol * ldc + grow + q] = S[col * 132 + r4 + q] + bb;
                    }
                }
                __syncthreads();
            }
        }
    }
}

static inline int pgrid(int M, int N) {
    int t = ((M + 127) >> 7) * ((N + 127) >> 7);
    return t < MAXCTA ? t : MAXCTA;
}
// full tile grid (non-persistent): lets HW backfill SMs during concurrency
static inline int fgrid(int M, int N) {
    return ((M + 127) >> 7) * ((N + 127) >> 7);
}

// ---------------- LSTM: 64 persistent blocks, 512 threads, FFMA2 -------------
// 96 of 128 h-dims register-resident (wp[48]); 32 dims in smem -> halved
// crossbar traffic per step vs the 64/64 split.
__global__ void __launch_bounds__(512, 1)
lstm_k(const float* __restrict__ W_hh)
{
    extern __shared__ float4 Wv2[];   // [8][512]: Wv2[i*512+g] = W_hh[g][96+4i..]
    __shared__ __align__(16) float h_s[128];
    __shared__ float g_s[512];
    int n = blockIdx.x, g = threadIdx.x;

    u64 wp[48];
#pragma unroll
    for (int i = 0; i < 24; i++) {
        float4 w4 = *(const float4*)(W_hh + (size_t)g * 128 + 4 * i);
        wp[2 * i]     = pk2(w4.x, w4.y);
        wp[2 * i + 1] = pk2(w4.z, w4.w);
    }
    for (int j = g; j < 8 * 512; j += 512) {
        int i = j >> 9, gg = j & 511;
        Wv2[j] = *(const float4*)(W_hh + (size_t)gg * 128 + 96 + 4 * i);
    }
    float cst = 0.f;
    if (g < 128) h_s[g] = 0.f;
    __syncthreads();

    const float* xwb  = d_xw + (size_t)n * Tt * GG;
    float*       hout = d_h  + (size_t)n * Tt * HH;
    const u64*   h2   = (const u64*)h_s;
    const u64*   wv2u = (const u64*)Wv2;

    float xnext = xwb[g];
    for (int t = 0; t < Tt; t++) {
        float xcur = xnext;
        if (t + 1 < Tt) xnext = xwb[(size_t)(t + 1) * GG + g];
        u64 c0 = pk2(xcur, 0.f);
        u64 c1 = pk2(0.f, 0.f), c2 = pk2(0.f, 0.f), c3 = pk2(0.f, 0.f);
#pragma unroll
        for (int i = 0; i < 48; i += 4) {
            c0 = fma2(wp[i],     h2[i],     c0);
            c1 = fma2(wp[i + 1], h2[i + 1], c1);
            c2 = fma2(wp[i + 2], h2[i + 2], c2);
            c3 = fma2(wp[i + 3], h2[i + 3], c3);
        }
#pragma unroll
        for (int i = 0; i < 8; i += 2) {
            c0 = fma2(wv2u[2 * (i * 512 + g)],           h2[48 + 2 * i],     c0);
            c1 = fma2(wv2u[2 * (i * 512 + g) + 1],       h2[48 + 2 * i + 1], c1);
            c2 = fma2(wv2u[2 * ((i + 1) * 512 + g)],     h2[48 + 2 * i + 2], c2);
            c3 = fma2(wv2u[2 * ((i + 1) * 512 + g) + 1], h2[48 + 2 * i + 3], c3);
        }
        float s0, s1, s2, s3, s4, s5, s6, s7;
        upk2(c0, s0, s1); upk2(c1, s2, s3); upk2(c2, s4, s5); upk2(c3, s6, s7);
        g_s[g] = ((s0 + s1) + (s2 + s3)) + ((s4 + s5) + (s6 + s7));
        __syncthreads();
        if (g < 128) {
            float iv = sigmf(g_s[g]);
            float fv = sigmf(g_s[128 + g]);
            float gv = tanhf(g_s[256 + g]);
            float ov = sigmf(g_s[384 + g]);
            cst = fv * cst + iv * gv;
            float hv = ov * tanhf(cst);
            h_s[g] = hv;
            hout[(size_t)t * HH + g] = hv;
        }
        __syncthreads();
    }
}

// ---------------- PSD: one block per (b,f), f-major coalesced loads ----------
__global__ void __launch_bounds__(256)
psd_k()
{
    int bf = blockIdx.x;
    int b = bf / Fq, f = bf - b * Fq;
    __shared__ float2 sv[8][33];
    __shared__ float2 nv[8][33];
    int tid = threadIdx.x;
    int cl = tid >> 5, ts = tid & 31;
    int p = tid >> 2, sub = tid & 3;
    int cc = p >> 3, ee = p & 7;
    float2 as = make_float2(0.f, 0.f), an = make_float2(0.f, 0.f);

    const float* sre  = d_specT  + (size_t)f * ROWS;
    const float* sim  = d_specT  + (size_t)(Fq + f) * ROWS;
    const float* m1re = d_masksT + (size_t)f * ROWS;
    const float* m1im = d_masksT + (size_t)(Fq + f) * ROWS;
    const float* m2re = d_masksT + (size_t)(DD + f) * ROWS;
    const float* m2im = d_masksT + (size_t)(DD + Fq + f) * ROWS;

    for (int t0 = 0; t0 < Tt; t0 += 32) {
        int t = t0 + ts;
        float2 svv = make_float2(0.f, 0.f), nvv = make_float2(0.f, 0.f);
        if (t < Tt) {
            size_t row = (size_t)(b * 8 + cl) * Tt + t;
            float2 s  = make_float2(sre[row],  sim[row]);
            float2 m1 = make_float2(m1re[row], m1im[row]);
            float2 m2 = make_float2(m2re[row], m2im[row]);
            svv = cmulf(m1, s);
            nvv = cmulf(m2, s);
        }
        sv[cl][ts] = svv;
        nv[cl][ts] = nvv;
        __syncthreads();
#pragma unroll
        for (int j = 0; j < 8; j++) {
            int q = sub * 8 + j;
            float2 a = sv[cc][q], bq = sv[ee][q];
            as.x += a.x * bq.x + a.y * bq.y;
            as.y += a.y * bq.x - a.x * bq.y;
            a = nv[cc][q]; bq = nv[ee][q];
            an.x += a.x * bq.x + a.y * bq.y;
            an.y += a.y * bq.x - a.x * bq.y;
        }
        __syncthreads();
    }
#pragma unroll
    for (int o = 2; o >= 1; o >>= 1) {
        as.x += __shfl_down_sync(0xffffffffu, as.x, o);
        as.y += __shfl_down_sync(0xffffffffu, as.y, o);
        an.x += __shfl_down_sync(0xffffffffu, an.x, o);
        an.y += __shfl_down_sync(0xffffffffu, an.y, o);
    }
    if (sub == 0) {
        float invT = 1.0f / (float)Tt;
        d_psd_s[(size_t)bf * 64 + p] = make_float2(as.x * invT, as.y * invT);
        d_psd_n[(size_t)bf * 64 + p] = make_float2(an.x * invT, an.y * invT);
    }
}

// ---------------- solve: 8x8 complex Gauss-Jordan, 32 systems/block ----------
#define ANm(i,j) mem[((i)*8+(j))*32 + tid]
#define ASm(i,j) mem[(64+(i)*8+(j))*32 + tid]
__global__ void __launch_bounds__(32)
solve_k()
{
    __shared__ float2 mem[128 * 32];
    int tid = threadIdx.x;
    int sys = blockIdx.x * 32 + tid;
    if (sys >= Bb * Fq) return;

    for (int e = 0; e < 64; e++) {
        mem[e * 32 + tid]        = d_psd_n[(size_t)sys * 64 + e];
        mem[(64 + e) * 32 + tid] = d_psd_s[(size_t)sys * 64 + e];
    }
    float tr = 0.f;
    for (int i = 0; i < 8; i++) tr += ANm(i, i).x;
    float lam = 1e-6f * tr / 8.0f + 1e-8f;
    for (int i = 0; i < 8; i++) ANm(i, i).x += lam;
    for (int p = 0; p < 8; p++) {
        float2 piv = ANm(p, p);
        float dinv = 1.0f / (piv.x * piv.x + piv.y * piv.y);
        float2 ip = make_float2(piv.x * dinv, -piv.y * dinv);
        for (int j = 0; j < 8; j++) {
            ANm(p, j) = cmulf(ANm(p, j), ip);
            ASm(p, j) = cmulf(ASm(p, j), ip);
        }
        for (int r = 0; r < 8; r++) {
            if (r == p) continue;
            float2 fct = ANm(r, p);
            for (int j = 0; j < 8; j++) {
                float2 t1 = cmulf(fct, ANm(p, j));
                float2 t2 = cmulf(fct, ASm(p, j));
                ANm(r, j).x -= t1.x; ANm(r, j).y -= t1.y;
                ASm(r, j).x -= t2.x; ASm(r, j).y -= t2.y;
            }
        }
    }
    float2 tr2 = make_float2(1e-8f, 0.f);
    for (int i = 0; i < 8; i++) {
        tr2.x += ASm(i, i).x;
        tr2.y += ASm(i, i).y;
    }
    float dinv = 1.0f / (tr2.x * tr2.x + tr2.y * tr2.y);
    float2 itr = make_float2(tr2.x * dinv, -tr2.y * dinv);
    for (int c = 0; c < 8; c++) {
        float2 wv = cmulf(ASm(c, 0), itr);
        d_wbeam[(size_t)sys * 8 + c] = make_float2(wv.x, -wv.y);   // store conj(w)
    }
}

// ---------------- beamform: block per (b,f), coalesced over t ----------------
__global__ void __launch_bounds__(256)
beam_k()
{
    int bf = blockIdx.x;
    int b = bf / Fq, f = bf - b * Fq;
    const float2* w = d_wbeam + (size_t)bf * 8;
    float2 wc[8];
#pragma unroll
    for (int c = 0; c < 8; c++) wc[c] = w[c];
    const float* sre = d_specT + (size_t)f * ROWS;
    const float* sim = d_specT + (size_t)(Fq + f) * ROWS;
    for (int t = threadIdx.x; t < Tt; t += 256) {
        float2 acc = make_float2(0.f, 0.f);
#pragma unroll
        for (int c = 0; c < 8; c++) {
            size_t row = (size_t)(b * 8 + c) * Tt + t;
            float2 s = make_float2(sre[row], sim[row]);
            acc.x += wc[c].x * s.x - wc[c].y * s.y;
            acc.y += wc[c].x * s.y + wc[c].y * s.x;
        }
        d_enhT[(size_t)f * BT + b * Tt + t]        = acc.x;
        d_enhT[(size_t)(Fq + f) * BT + b * Tt + t] = acc.y;
    }
}

// ---------------- overlap-add + normalization + crop ----------------
__global__ void k_ola(float* __restrict__ out)
{
    int idx = blockIdx.x * blockDim.x + threadIdx.x;
    if (idx >= Bb * Ll) return;
    int b = idx / Ll, l = idx - b * Ll;
    int p = l + 256;
    int tmin = (p >= Nfft) ? (p - Nfft) / Hop + 1 : 0;
    int tmax = p / Hop; if (tmax > Tt - 1) tmax = Tt - 1;
    float acc = 0.f, wsq = 0.f;
    for (int t = tmin; t <= tmax; t++) {
        int n = p - t * Hop;
        float wv = d_win[n];
        acc += d_fout[((size_t)b * Tt + t) * Nfft + n];
        wsq += wv * wv;
    }
    out[idx] = acc / fmaxf(wsq, 1e-11f);
}

// ---------------- launch ----------------
extern "C" void kernel_launch(void* const* d_in, const int* in_sizes, int n_in,
                              void* d_out, int out_size)
{
    const float* x    = (const float*)d_in[0];
    const float* W_ih = (const float*)d_in[1];
    const float* W_hh = (const float*)d_in[2];
    const float* b_ih = (const float*)d_in[3];
    const float* b_hh = (const float*)d_in[4];
    const float* W1   = (const float*)d_in[5];
    const float* b1   = (const float*)d_in[6];
    const float* W2   = (const float*)d_in[7];
    const float* b2   = (const float*)d_in[8];
    float* out = (float*)d_out;

    cudaFuncSetAttribute(lstm_k, cudaFuncAttributeMaxDynamicSharedMemorySize, 131072);
    const int GS = 64 * 132 * 4;   // 33792 B dyn smem
    const int LSMEM = 8 * 512 * 16; // 64 KB Wv2

    float *pBspec, *pBW, *pWihT, *pBiasxw, *pWmask, *pBmask, *pEmat;
    float *pFrames, *pSpecT, *pXw, *pH, *pMasksT, *pEnhT, *pFout;
    cudaGetSymbolAddress((void**)&pBspec,  d_Bspec);
    cudaGetSymbolAddress((void**)&pBW,     d_BW);
    cudaGetSymbolAddress((void**)&pWihT,   d_WihT);
    cudaGetSymbolAddress((void**)&pBiasxw, d_biasxw);
    cudaGetSymbolAddress((void**)&pWmask,  d_Wmask);
    cudaGetSymbolAddress((void**)&pBmask,  d_bmask);
    cudaGetSymbolAddress((void**)&pEmat,   d_Emat);
    cudaGetSymbolAddress((void**)&pFrames, d_frames);
    cudaGetSymbolAddress((void**)&pSpecT,  d_specT);
    cudaGetSymbolAddress((void**)&pXw,     d_xw);
    cudaGetSymbolAddress((void**)&pH,      d_h);
    cudaGetSymbolAddress((void**)&pMasksT, d_masksT);
    cudaGetSymbolAddress((void**)&pEnhT,   d_enhT);
    cudaGetSymbolAddress((void**)&pFout,   d_fout);

    cudaStream_t s2;
    cudaStreamCreateWithFlags(&s2, cudaStreamNonBlocking);
    cudaEvent_t e1, e2;
    cudaEventCreateWithFlags(&e1, cudaEventDisableTiming);
    cudaEventCreateWithFlags(&e2, cudaEventDisableTiming);

    {   // input transpose
        dim3 grid(Ll / 256, Bb);
        k_xpose<<<grid, 256>>>(x);
    }
    k_frames<<<ROWS, KF>>>();
    k_bspec<<<KF, DD>>>();

    // ---- fork EARLY: branch B (s2) = GEMM1a (non-persistent) + win + emat.
    //      Needs only frames+Bspec; overlaps pack_wih, GEMM0, GEMM1b, LSTM. ----
    cudaEventRecord(e1, 0);
    cudaStreamWaitEvent(s2, e1, 0);
    sgemm_t<0, 1><<<fgrid(ROWS, DD), 256, GS, s2>>>(ROWS, DD, KF, pFrames, KF, pBspec, DDp, pSpecT, ROWS, nullptr);
    k_win<<<1, Nfft, 0, s2>>>();
    k_emat<<<DD, Nfft, 0, s2>>>();
    cudaEventRecord(e2, s2);

    // ---- branch A (default stream): critical LSTM chain ----
    k_pack_wih<<<(DD * GG + 255) / 256, 256>>>(W_ih, b_ih, b_hh);
    // GEMM0: BW[320,512] = Bspec[320,514] @ WihT[514,512]  (12 tiles)
    sgemm_t<0, 0><<<pgrid(KF, GG), 256, GS>>>(KF, GG, DD, pBspec, DDp, pWihT, GG, pBW, GG, nullptr);
    // GEMM1b: xw[ROWS][512] = frames @ BW + bias
    sgemm_t<0, 0><<<fgrid(ROWS, GG), 256, GS>>>(ROWS, GG, KF, pFrames, KF, pBW, GG, pXw, GG, pBiasxw);
    lstm_k<<<NS, 512, LSMEM>>>(W_hh);
    k_pack_wmask<<<NM, HH>>>(W1, b1, W2, b2);
    sgemm_t<0, 1><<<fgrid(ROWS, NM), 256, GS>>>(ROWS, NM, HH, pH, HH, pWmask, NM, pMasksT, ROWS, pBmask);

    // ---- join: psd needs specT (branch B) + masksT (branch A) ----
    cudaStreamWaitEvent(0, e2, 0);
    psd_k<<<Bb * Fq, 256>>>();
    solve_k<<<(Bb * Fq + 31) / 32, 32>>>();
    beam_k<<<Bb * Fq, 256>>>();
    // GEMM3: fout[4808,512] = enhT^T[4808,514] @ Emat[514,512]
    sgemm_t<1, 0><<<pgrid(BT, Nfft), 256, GS>>>(BT, Nfft, DD, pEnhT, BT, pEmat, Nfft, pFout, Nfft, nullptr);
    k_ola<<<(Bb * Ll + 255) / 256, 256>>>(out);
}

// round 17
// speedup vs baseline: 1.3460x; 1.0512x over previous
#include <cuda_runtime.h>
#include <math.h>
#include <stdint.h>

// ---------------- problem constants ----------------
#define Bb   8
#define Cc   8
#define Ll   96000
#define Nfft 512
#define Winl 320
#define Hop  160
#define Fq   257
#define Tt   601
#define NS   64            // B*C sequences
#define ROWS (NS*Tt)       // 38464
#define KF   320           // nonzero window support
#define DD   514           // 2F
#define DDp  516           // padded (16B-aligned rows)
#define GG   512           // 4H
#define HH   128
#define NM   1028          // 2*DD     (mask1|mask2)
#define BT   (Bb*Tt)       // 4808
#define TWO_PI 6.28318530717958647692f
#define MAXCTA 296         // 148 SMs x 2 CTAs

typedef unsigned long long u64;

// ---------------- device scratch ----------------
__device__ float  d_win[Nfft];
__device__ float  d_xT[(size_t)Bb * Cc * Ll];   // channel-major input
__device__ float  d_Bspec[KF * DDp];            // windowed DFT matrix [320][514(+2)]
__device__ float  d_BW[KF * GG];                // Bspec @ W_ih^T  [320][512]
__device__ float  d_WihT[DD * GG];
__device__ float  d_biasxw[GG];
__device__ float  d_Wmask[HH * NM];
__device__ float  d_bmask[NM];
__device__ float  d_Emat[DD * Nfft];
__device__ float  d_frames[(size_t)ROWS * KF];
__device__ float  d_specT[(size_t)DD * ROWS];   // f-major spectra
__device__ float  d_xw[(size_t)ROWS * GG];      // LSTM input projections
__device__ float  d_h[(size_t)ROWS * HH];
__device__ float  d_masksT[(size_t)NM * ROWS];  // f-major masks
__device__ float2 d_psd_s[Bb * Fq * 64];
__device__ float2 d_psd_n[Bb * Fq * 64];
__device__ float2 d_wbeam[Bb * Fq * Cc];
__device__ float  d_enhT[(size_t)DD * BT];      // f-major beamformed spectrum
__device__ float  d_fout[(size_t)BT * Nfft];

__device__ __forceinline__ float2 cmulf(float2 a, float2 b) {
    return make_float2(a.x * b.x - a.y * b.y, a.x * b.y + a.y * b.x);
}
// fast-math gate nonlinearities (MUFU-based; huge rel-err headroom vs 1e-3)
__device__ __forceinline__ float fsigm(float x) {
    return __fdividef(1.0f, 1.0f + __expf(-x));
}
__device__ __forceinline__ float ftanh(float x) {
    float xc = fminf(fmaxf(x, -12.0f), 12.0f);
    float ex = __expf(2.0f * xc);
    return __fdividef(ex - 1.0f, ex + 1.0f);
}

// packed f32x2 helpers (sm_103a FFMA2 path)
__device__ __forceinline__ u64 pk2(float lo, float hi) {
    u64 r; asm("mov.b64 %0, {%1, %2};" : "=l"(r) : "f"(lo), "f"(hi)); return r;
}
__device__ __forceinline__ u64 fma2(u64 a, u64 b, u64 c) {
    u64 d; asm("fma.rn.f32x2 %0, %1, %2, %3;" : "=l"(d) : "l"(a), "l"(b), "l"(c)); return d;
}
__device__ __forceinline__ void upk2(u64 v, float& lo, float& hi) {
    asm("mov.b64 {%0, %1}, %2;" : "=f"(lo), "=f"(hi) : "l"(v));
}
union F4U { float4 f; u64 u[2]; };

// ---------------- input transpose: x[b][l][c] -> xT[b][c][l] ----------------
__global__ void __launch_bounds__(256)
k_xpose(const float* __restrict__ x)
{
    __shared__ float tile[8][257];
    int b = blockIdx.y;
    int l0 = blockIdx.x * 256;
    int tid = threadIdx.x;
    const float* p = x + ((size_t)b * Ll + l0 + tid) * Cc;
    float4 v0 = *(const float4*)p;
    float4 v1 = *(const float4*)(p + 4);
    tile[0][tid] = v0.x; tile[1][tid] = v0.y; tile[2][tid] = v0.z; tile[3][tid] = v0.w;
    tile[4][tid] = v1.x; tile[5][tid] = v1.y; tile[6][tid] = v1.z; tile[7][tid] = v1.w;
    __syncthreads();
#pragma unroll
    for (int c = 0; c < 8; c++)
        d_xT[((size_t)b * Cc + c) * Ll + l0 + tid] = tile[c][tid];
}

// ---------------- frame gather (reflect pad), coalesced from xT -------------
__global__ void k_frames()
{
    int m = blockIdx.x;           // n*T + t
    int n = m / Tt, t = m - n * Tt;
    int r = threadIdx.x;          // 0..319
    int q = t * Hop + r - 160;    // sample index before reflect
    if (q < 0) q = -q;
    else if (q >= Ll) q = 2 * Ll - 2 - q;
    d_frames[(size_t)m * KF + r] = d_xT[(size_t)n * Ll + q];
}

// Bspec: windowed DFT (window computed inline)
__global__ void k_bspec() {
    int r = blockIdx.x;         // 0..319
    int c = threadIdx.x;        // 0..513
    if (c >= DD) return;
    int n = 96 + r;
    float w = 0.5f - 0.5f * cosf(TWO_PI * (float)r / (float)Winl);
    int k = (c < Fq) ? c : c - Fq;
    int m = (n * k) & (Nfft - 1);
    float th = (float)m * (TWO_PI / (float)Nfft);
    d_Bspec[r * DDp + c] = (c < Fq) ? w * cosf(th) : -w * sinf(th);
}

__global__ void k_win() {
    int i = threadIdx.x;
    float v = 0.f;
    if (i >= 96 && i < 96 + Winl)
        v = 0.5f - 0.5f * cosf(TWO_PI * (float)(i - 96) / (float)Winl);
    d_win[i] = v;
}

__global__ void k_pack_wih(const float* __restrict__ W_ih,
                           const float* __restrict__ b_ih,
                           const float* __restrict__ b_hh) {
    int idx = blockIdx.x * blockDim.x + threadIdx.x;
    if (idx < GG) d_biasxw[idx] = b_ih[idx] + b_hh[idx];
    if (idx >= DD * GG) return;
    int d = idx >> 9, g = idx & 511;
    d_WihT[idx] = W_ih[g * DD + d];
}

__global__ void k_pack_wmask(const float* __restrict__ W1, const float* __restrict__ b1,
                             const float* __restrict__ W2, const float* __restrict__ b2) {
    int j = blockIdx.x;    // 0..1027
    int k = threadIdx.x;   // 0..127
    float v = (j < DD) ? W1[j * HH + k] : W2[(j - DD) * HH + k];
    d_Wmask[k * NM + j] = v;
    if (k == 0) d_bmask[j] = (j < DD) ? b1[j] : b2[j - DD];
}

// iRFFT matrix with synthesis window folded in. imag of DC/Nyquist ignored (c2r).
__global__ void k_emat() {
    int row = blockIdx.x;   // 0..513
    int n   = threadIdx.x;  // 0..511
    float w = d_win[n];
    float val;
    if (row < Fq) {
        int k = row;
        float ck = (k == 0 || k == Nfft / 2) ? 1.0f : 2.0f;
        int m = (k * n) & (Nfft - 1);
        val = ck * (1.0f / (float)Nfft) * cosf((float)m * (TWO_PI / (float)Nfft)) * w;
    } else {
        int k = row - Fq;
        if (k == 0 || k == Nfft / 2) val = 0.f;
        else {
            int m = (k * n) & (Nfft - 1);
            val = -(2.0f / (float)Nfft) * sinf((float)m * (TWO_PI / (float)Nfft)) * w;
        }
    }
    d_Emat[row * Nfft + n] = val;
}

// ---------------- SGEMM: 128x128 tile, double-buffered, FFMA2 ----------------
// TA=0: A[M][K] lda=k-stride.  TA=1: A stored [K][M], lda=m-stride.
// TC=0: C[M][N] row-major.     TC=1: C stored [N][M] (C^T), ldc=m-stride.
struct Frag { float4 a[2]; float4 b[2]; };

template <int TA>
__device__ __forceinline__ void gload(Frag& f, int tid, int M, int N, int K,
                                      const float* __restrict__ A, int lda,
                                      const float* __restrict__ B, int ldb,
                                      int by, int bx, int k0)
{
#pragma unroll
    for (int l = 0; l < 2; l++) {
        int idx = tid + l * 256;
        if (TA == 0) {
            int arow = idx & 127, ak = (idx >> 7) << 2;
            int gr = by * 128 + arow, gk = k0 + ak;
            const float* pA = A + (size_t)gr * lda + gk;
            if (gr < M && gk + 3 < K) {
                f.a[l] = *(const float4*)pA;
            } else {
                f.a[l].x = (gr < M && gk     < K) ? pA[0] : 0.f;
                f.a[l].y = (gr < M && gk + 1 < K) ? pA[1] : 0.f;
                f.a[l].z = (gr < M && gk + 2 < K) ? pA[2] : 0.f;
                f.a[l].w = (gr < M && gk + 3 < K) ? pA[3] : 0.f;
            }
        } else {
            int ak = idx >> 5, ar4 = (idx & 31) << 2;
            int gk = k0 + ak, gr = by * 128 + ar4;
            const float* pA = A + (size_t)gk * lda + gr;
            if (gk < K && gr + 3 < M) {
                f.a[l] = *(const float4*)pA;
            } else {
                f.a[l].x = (gk < K && gr     < M) ? pA[0] : 0.f;
                f.a[l].y = (gk < K && gr + 1 < M) ? pA[1] : 0.f;
                f.a[l].z = (gk < K && gr + 2 < M) ? pA[2] : 0.f;
                f.a[l].w = (gk < K && gr + 3 < M) ? pA[3] : 0.f;
            }
        }
        int bkk = idx >> 5, bc = (idx & 31) << 2;
        int gc = bx * 128 + bc, gkb = k0 + bkk;
        const float* pB = B + (size_t)gkb * ldb + gc;
        if (gkb < K && gc + 3 < N) {
            f.b[l] = *(const float4*)pB;
        } else {
            f.b[l].x = (gkb < K && gc     < N) ? pB[0] : 0.f;
            f.b[l].y = (gkb < K && gc + 1 < N) ? pB[1] : 0.f;
            f.b[l].z = (gkb < K && gc + 2 < N) ? pB[2] : 0.f;
            f.b[l].w = (gkb < K && gc + 3 < N) ? pB[3] : 0.f;
        }
    }
}

template <int TA>
__device__ __forceinline__ void sstore(const Frag& f, int tid, int buf,
                                       float (*As)[16][128], float (*Bs)[16][128])
{
#pragma unroll
    for (int l = 0; l < 2; l++) {
        int idx = tid + l * 256;
        if (TA == 0) {
            int arow = idx & 127, ak = (idx >> 7) << 2;
            As[buf][ak + 0][arow] = f.a[l].x;
            As[buf][ak + 1][arow] = f.a[l].y;
            As[buf][ak + 2][arow] = f.a[l].z;
            As[buf][ak + 3][arow] = f.a[l].w;
        } else {
            int ak = idx >> 5, ar4 = (idx & 31) << 2;
            *(float4*)&As[buf][ak][ar4] = f.a[l];
        }
        int bkk = idx >> 5, bc = (idx & 31) << 2;
        *(float4*)&Bs[buf][bkk][bc] = f.b[l];
    }
}

template <int TA, int TC>
__global__ void __launch_bounds__(256, 2)
sgemm_t(int M, int N, int K,
        const float* __restrict__ A, int lda,
        const float* __restrict__ B, int ldb,
        float* __restrict__ C, int ldc,
        const float* __restrict__ bias)
{
    extern __shared__ float smembuf[];
    float (*As)[16][128] = (float(*)[16][128])smembuf;
    float (*Bs)[16][128] = (float(*)[16][128])(smembuf + 4096);
    int tid = threadIdx.x;
    int tx = tid & 15, ty = tid >> 4;

    int ntx = (N + 127) >> 7, nty = (M + 127) >> 7;
    int ntiles = ntx * nty;
    int nk = (K + 15) >> 4;

    for (int tile = blockIdx.x; tile < ntiles; tile += gridDim.x) {
        int bx = tile % ntx, by = tile / ntx;
        __syncthreads();   // protect smem reuse across tiles

        u64 acc[8][4];
#pragma unroll
        for (int a = 0; a < 8; a++)
#pragma unroll
            for (int j = 0; j < 4; j++) acc[a][j] = pk2(0.f, 0.f);

        Frag f;
        gload<TA>(f, tid, M, N, K, A, lda, B, ldb, by, bx, 0);
        sstore<TA>(f, tid, 0, As, Bs);
        __syncthreads();

        for (int kt = 0; kt < nk; kt++) {
            int cur = kt & 1;
            if (kt + 1 < nk)
                gload<TA>(f, tid, M, N, K, A, lda, B, ldb, by, bx, (kt + 1) << 4);
#pragma unroll
            for (int k = 0; k < 16; k++) {
                float4 a0 = *(const float4*)&As[cur][k][ty * 4];
                float4 a1 = *(const float4*)&As[cur][k][64 + ty * 4];
                F4U B0, B1;
                B0.f = *(const float4*)&Bs[cur][k][tx * 4];
                B1.f = *(const float4*)&Bs[cur][k][64 + tx * 4];
                float av[8] = {a0.x, a0.y, a0.z, a0.w, a1.x, a1.y, a1.z, a1.w};
#pragma unroll
                for (int a = 0; a < 8; a++) {
                    u64 pa = pk2(av[a], av[a]);
                    acc[a][0] = fma2(pa, B0.u[0], acc[a][0]);
                    acc[a][1] = fma2(pa, B0.u[1], acc[a][1]);
                    acc[a][2] = fma2(pa, B1.u[0], acc[a][2]);
                    acc[a][3] = fma2(pa, B1.u[1], acc[a][3]);
                }
            }
            if (kt + 1 < nk) {
                int nxt = 1 - cur;
                sstore<TA>(f, tid, nxt, As, Bs);
                __syncthreads();
            }
        }

        if (TC == 0) {
#pragma unroll
            for (int a = 0; a < 8; a++) {
                int row = by * 128 + ((a & 4) << 4) + ty * 4 + (a & 3);
                if (row >= M) continue;
#pragma unroll
                for (int j = 0; j < 4; j++) {
                    float lo, hi;
                    upk2(acc[a][j], lo, hi);
                    int colb = bx * 128 + ((j >= 2) ? 64 : 0) + tx * 4 + (j & 1) * 2;
                    if (colb < N)     C[(size_t)row * ldc + colb]     = lo + (bias ? bias[colb]     : 0.f);
                    if (colb + 1 < N) C[(size_t)row * ldc + colb + 1] = hi + (bias ? bias[colb + 1] : 0.f);
                }
            }
        } else {
            // transposed-C epilogue: stage 128x64 halves (pitch 132), float4 out
            float* S = smembuf;   // 64*132 floats
            __syncthreads();
#pragma unroll
            for (int hh = 0; hh < 2; hh++) {
#pragma unroll
                for (int a = 0; a < 8; a++) {
                    int row = ((a & 4) << 4) + ty * 4 + (a & 3);
#pragma unroll
                    for (int jj = 0; jj < 2; jj++) {
                        int j = hh * 2 + jj;
                        float lo, hi;
                        upk2(acc[a][j], lo, hi);
                        int col = tx * 4 + jj * 2;
                        S[col * 132 + row]       = lo;
                        S[(col + 1) * 132 + row] = hi;
                    }
                }
                __syncthreads();
#pragma unroll
                for (int u = 0; u < 8; u++) {
                    int unit = tid + u * 256;        // 0..2047
                    int col = unit >> 5;             // 0..63
                    int r4 = (unit & 31) << 2;       // 0..124
                    int gcol = bx * 128 + hh * 64 + col;
                    int grow = by * 128 + r4;
                    if (gcol >= N) continue;
                    float bb = bias ? bias[gcol] : 0.f;
                    if (grow + 3 < M) {
                        float4 v = *(const float4*)&S[col * 132 + r4];
                        v.x += bb; v.y += bb; v.z += bb; v.w += bb;
                        *(float4*)&C[(size_t)gcol * ldc + grow] = v;
                    } else {
#pragma unroll
                        for (int q = 0; q < 4; q++)
                            if (grow + q < M)
                                C[(size_t)gcol * ldc + grow + q] = S[col * 132 + r4 + q] + bb;
                    }
                }
                __syncthreads();
            }
        }
    }
}

static inline int pgrid(int M, int N) {
    int t = ((M + 127) >> 7) * ((N + 127) >> 7);
    return t < MAXCTA ? t : MAXCTA;
}
// full tile grid (non-persistent): lets HW backfill SMs during concurrency
static inline int fgrid(int M, int N) {
    return ((M + 127) >> 7) * ((N + 127) >> 7);
}

// ---------------- LSTM: 64 persistent blocks, 512 threads, FFMA2 -------------
// 96/32 reg/smem weight split; gate nonlinearities spread over all 512 threads
// with fast-math MUFU sigmoid/tanh.
__global__ void __launch_bounds__(512, 1)
lstm_k(const float* __restrict__ W_hh)
{
    extern __shared__ float4 Wv2[];   // [8][512]: Wv2[i*512+g] = W_hh[g][96+4i..]
    __shared__ __align__(16) float h_s[128];
    __shared__ float g_s[512];
    int n = blockIdx.x, g = threadIdx.x;

    u64 wp[48];
#pragma unroll
    for (int i = 0; i < 24; i++) {
        float4 w4 = *(const float4*)(W_hh + (size_t)g * 128 + 4 * i);
        wp[2 * i]     = pk2(w4.x, w4.y);
        wp[2 * i + 1] = pk2(w4.z, w4.w);
    }
    for (int j = g; j < 8 * 512; j += 512) {
        int i = j >> 9, gg = j & 511;
        Wv2[j] = *(const float4*)(W_hh + (size_t)gg * 128 + 96 + 4 * i);
    }
    float cst = 0.f;
    if (g < 128) h_s[g] = 0.f;
    __syncthreads();

    const float* xwb  = d_xw + (size_t)n * Tt * GG;
    float*       hout = d_h  + (size_t)n * Tt * HH;
    const u64*   h2   = (const u64*)h_s;
    const u64*   wv2u = (const u64*)Wv2;
    int gq = g >> 7;                 // which gate this thread's row belongs to

    float xnext = xwb[g];
    for (int t = 0; t < Tt; t++) {
        float xcur = xnext;
        if (t + 1 < Tt) xnext = xwb[(size_t)(t + 1) * GG + g];
        u64 c0 = pk2(xcur, 0.f);
        u64 c1 = pk2(0.f, 0.f), c2 = pk2(0.f, 0.f), c3 = pk2(0.f, 0.f);
#pragma unroll
        for (int i = 0; i < 48; i += 4) {
            c0 = fma2(wp[i],     h2[i],     c0);
            c1 = fma2(wp[i + 1], h2[i + 1], c1);
            c2 = fma2(wp[i + 2], h2[i + 2], c2);
            c3 = fma2(wp[i + 3], h2[i + 3], c3);
        }
#pragma unroll
        for (int i = 0; i < 8; i += 2) {
            c0 = fma2(wv2u[2 * (i * 512 + g)],           h2[48 + 2 * i],     c0);
            c1 = fma2(wv2u[2 * (i * 512 + g) + 1],       h2[48 + 2 * i + 1], c1);
            c2 = fma2(wv2u[2 * ((i + 1) * 512 + g)],     h2[48 + 2 * i + 2], c2);
            c3 = fma2(wv2u[2 * ((i + 1) * 512 + g) + 1], h2[48 + 2 * i + 3], c3);
        }
        float s0, s1, s2, s3, s4, s5, s6, s7;
        upk2(c0, s0, s1); upk2(c1, s2, s3); upk2(c2, s4, s5); upk2(c3, s6, s7);
        float acc = ((s0 + s1) + (s2 + s3)) + ((s4 + s5) + (s6 + s7));
        // apply this gate's nonlinearity in-thread (spread across all 512)
        g_s[g] = (gq == 2) ? ftanh(acc) : fsigm(acc);
        __syncthreads();
        if (g < 128) {
            float iv = g_s[g];
            float fv = g_s[128 + g];
            float gv = g_s[256 + g];
            float ov = g_s[384 + g];
            cst = fv * cst + iv * gv;
            float hv = ov * ftanh(cst);
            h_s[g] = hv;
            hout[(size_t)t * HH + g] = hv;
        }
        __syncthreads();
    }
}

// ---------------- PSD: one block per (b,f), f-major coalesced loads ----------
__global__ void __launch_bounds__(256)
psd_k()
{
    int bf = blockIdx.x;
    int b = bf / Fq, f = bf - b * Fq;
    __shared__ float2 sv[8][33];
    __shared__ float2 nv[8][33];
    int tid = threadIdx.x;
    int cl = tid >> 5, ts = tid & 31;
    int p = tid >> 2, sub = tid & 3;
    int cc = p >> 3, ee = p & 7;
    float2 as = make_float2(0.f, 0.f), an = make_float2(0.f, 0.f);

    const float* sre  = d_specT  + (size_t)f * ROWS;
    const float* sim  = d_specT  + (size_t)(Fq + f) * ROWS;
    const float* m1re = d_masksT + (size_t)f * ROWS;
    const float* m1im = d_masksT + (size_t)(Fq + f) * ROWS;
    const float* m2re = d_masksT + (size_t)(DD + f) * ROWS;
    const float* m2im = d_masksT + (size_t)(DD + Fq + f) * ROWS;

    for (int t0 = 0; t0 < Tt; t0 += 32) {
        int t = t0 + ts;
        float2 svv = make_float2(0.f, 0.f), nvv = make_float2(0.f, 0.f);
        if (t < Tt) {
            size_t row = (size_t)(b * 8 + cl) * Tt + t;
            float2 s  = make_float2(sre[row],  sim[row]);
            float2 m1 = make_float2(m1re[row], m1im[row]);
            float2 m2 = make_float2(m2re[row], m2im[row]);
            svv = cmulf(m1, s);
            nvv = cmulf(m2, s);
        }
        sv[cl][ts] = svv;
        nv[cl][ts] = nvv;
        __syncthreads();
#pragma unroll
        for (int j = 0; j < 8; j++) {
            int q = sub * 8 + j;
            float2 a = sv[cc][q], bq = sv[ee][q];
            as.x += a.x * bq.x + a.y * bq.y;
            as.y += a.y * bq.x - a.x * bq.y;
            a = nv[cc][q]; bq = nv[ee][q];
            an.x += a.x * bq.x + a.y * bq.y;
            an.y += a.y * bq.x - a.x * bq.y;
        }
        __syncthreads();
    }
#pragma unroll
    for (int o = 2; o >= 1; o >>= 1) {
        as.x += __shfl_down_sync(0xffffffffu, as.x, o);
        as.y += __shfl_down_sync(0xffffffffu, as.y, o);
        an.x += __shfl_down_sync(0xffffffffu, an.x, o);
        an.y += __shfl_down_sync(0xffffffffu, an.y, o);
    }
    if (sub == 0) {
        float invT = 1.0f / (float)Tt;
        d_psd_s[(size_t)bf * 64 + p] = make_float2(as.x * invT, as.y * invT);
        d_psd_n[(size_t)bf * 64 + p] = make_float2(an.x * invT, an.y * invT);
    }
}

// ---------------- solve: 8x8 complex Gauss-Jordan, 32 systems/block ----------
#define ANm(i,j) mem[((i)*8+(j))*32 + tid]
#define ASm(i,j) mem[(64+(i)*8+(j))*32 + tid]
__global__ void __launch_bounds__(32)
solve_k()
{
    __shared__ float2 mem[128 * 32];
    int tid = threadIdx.x;
    int sys = blockIdx.x * 32 + tid;
    if (sys >= Bb * Fq) return;

    for (int e = 0; e < 64; e++) {
        mem[e * 32 + tid]        = d_psd_n[(size_t)sys * 64 + e];
        mem[(64 + e) * 32 + tid] = d_psd_s[(size_t)sys * 64 + e];
    }
    float tr = 0.f;
    for (int i = 0; i < 8; i++) tr += ANm(i, i).x;
    float lam = 1e-6f * tr / 8.0f + 1e-8f;
    for (int i = 0; i < 8; i++) ANm(i, i).x += lam;
    for (int p = 0; p < 8; p++) {
        float2 piv = ANm(p, p);
        float dinv = 1.0f / (piv.x * piv.x + piv.y * piv.y);
        float2 ip = make_float2(piv.x * dinv, -piv.y * dinv);
        for (int j = 0; j < 8; j++) {
            ANm(p, j) = cmulf(ANm(p, j), ip);
            ASm(p, j) = cmulf(ASm(p, j), ip);
        }
        for (int r = 0; r < 8; r++) {
            if (r == p) continue;
            float2 fct = ANm(r, p);
            for (int j = 0; j < 8; j++) {
                float2 t1 = cmulf(fct, ANm(p, j));
                float2 t2 = cmulf(fct, ASm(p, j));
                ANm(r, j).x -= t1.x; ANm(r, j).y -= t1.y;
                ASm(r, j).x -= t2.x; ASm(r, j).y -= t2.y;
            }
        }
    }
    float2 tr2 = make_float2(1e-8f, 0.f);
    for (int i = 0; i < 8; i++) {
        tr2.x += ASm(i, i).x;
        tr2.y += ASm(i, i).y;
    }
    float dinv = 1.0f / (tr2.x * tr2.x + tr2.y * tr2.y);
    float2 itr = make_float2(tr2.x * dinv, -tr2.y * dinv);
    for (int c = 0; c < 8; c++) {
        float2 wv = cmulf(ASm(c, 0), itr);
        d_wbeam[(size_t)sys * 8 + c] = make_float2(wv.x, -wv.y);   // store conj(w)
    }
}

// ---------------- beamform: block per (b,f), coalesced over t ----------------
__global__ void __launch_bounds__(256)
beam_k()
{
    int bf = blockIdx.x;
    int b = bf / Fq, f = bf - b * Fq;
    const float2* w = d_wbeam + (size_t)bf * 8;
    float2 wc[8];
#pragma unroll
    for (int c = 0; c < 8; c++) wc[c] = w[c];
    const float* sre = d_specT + (size_t)f * ROWS;
    const float* sim = d_specT + (size_t)(Fq + f) * ROWS;
    for (int t = threadIdx.x; t < Tt; t += 256) {
        float2 acc = make_float2(0.f, 0.f);
#pragma unroll
        for (int c = 0; c < 8; c++) {
            size_t row = (size_t)(b * 8 + c) * Tt + t;
            float2 s = make_float2(sre[row], sim[row]);
            acc.x += wc[c].x * s.x - wc[c].y * s.y;
            acc.y += wc[c].x * s.y + wc[c].y * s.x;
        }
        d_enhT[(size_t)f * BT + b * Tt + t]        = acc.x;
        d_enhT[(size_t)(Fq + f) * BT + b * Tt + t] = acc.y;
    }
}

// ---------------- overlap-add + normalization + crop ----------------
__global__ void k_ola(float* __restrict__ out)
{
    int idx = blockIdx.x * blockDim.x + threadIdx.x;
    if (idx >= Bb * Ll) return;
    int b = idx / Ll, l = idx - b * Ll;
    int p = l + 256;
    int tmin = (p >= Nfft) ? (p - Nfft) / Hop + 1 : 0;
    int tmax = p / Hop; if (tmax > Tt - 1) tmax = Tt - 1;
    float acc = 0.f, wsq = 0.f;
    for (int t = tmin; t <= tmax; t++) {
        int n = p - t * Hop;
        float wv = d_win[n];
        acc += d_fout[((size_t)b * Tt + t) * Nfft + n];
        wsq += wv * wv;
    }
    out[idx] = acc / fmaxf(wsq, 1e-11f);
}

// ---------------- launch ----------------
extern "C" void kernel_launch(void* const* d_in, const int* in_sizes, int n_in,
                              void* d_out, int out_size)
{
    const float* x    = (const float*)d_in[0];
    const float* W_ih = (const float*)d_in[1];
    const float* W_hh = (const float*)d_in[2];
    const float* b_ih = (const float*)d_in[3];
    const float* b_hh = (const float*)d_in[4];
    const float* W1   = (const float*)d_in[5];
    const float* b1   = (const float*)d_in[6];
    const float* W2   = (const float*)d_in[7];
    const float* b2   = (const float*)d_in[8];
    float* out = (float*)d_out;

    cudaFuncSetAttribute(lstm_k, cudaFuncAttributeMaxDynamicSharedMemorySize, 131072);
    const int GS = 64 * 132 * 4;   // 33792 B dyn smem
    const int LSMEM = 8 * 512 * 16; // 64 KB Wv2

    float *pBspec, *pBW, *pWihT, *pBiasxw, *pWmask, *pBmask, *pEmat;
    float *pFrames, *pSpecT, *pXw, *pH, *pMasksT, *pEnhT, *pFout;
    cudaGetSymbolAddress((void**)&pBspec,  d_Bspec);
    cudaGetSymbolAddress((void**)&pBW,     d_BW);
    cudaGetSymbolAddress((void**)&pWihT,   d_WihT);
    cudaGetSymbolAddress((void**)&pBiasxw, d_biasxw);
    cudaGetSymbolAddress((void**)&pWmask,  d_Wmask);
    cudaGetSymbolAddress((void**)&pBmask,  d_bmask);
    cudaGetSymbolAddress((void**)&pEmat,   d_Emat);
    cudaGetSymbolAddress((void**)&pFrames, d_frames);
    cudaGetSymbolAddress((void**)&pSpecT,  d_specT);
    cudaGetSymbolAddress((void**)&pXw,     d_xw);
    cudaGetSymbolAddress((void**)&pH,      d_h);
    cudaGetSymbolAddress((void**)&pMasksT, d_masksT);
    cudaGetSymbolAddress((void**)&pEnhT,   d_enhT);
    cudaGetSymbolAddress((void**)&pFout,   d_fout);

    // low-priority side stream: branch-A CTAs dispatch first, GEMM1a backfills
    int loPri = 0, hiPri = 0;
    cudaDeviceGetStreamPriorityRange(&loPri, &hiPri);
    cudaStream_t s2;
    cudaStreamCreateWithPriority(&s2, cudaStreamNonBlocking, loPri);
    cudaEvent_t e1, e2;
    cudaEventCreateWithFlags(&e1, cudaEventDisableTiming);
    cudaEventCreateWithFlags(&e2, cudaEventDisableTiming);

    {   // input transpose
        dim3 grid(Ll / 256, Bb);
        k_xpose<<<grid, 256>>>(x);
    }
    k_frames<<<ROWS, KF>>>();
    k_bspec<<<KF, DD>>>();

    // ---- fork EARLY: branch B (s2, LOW priority) = GEMM1a + win + emat.
    //      Branch A keeps dispatch priority; GEMM1a soaks up leftover SMs,
    //      especially the 84 SMs idle during the LSTM. ----
    cudaEventRecord(e1, 0);
    cudaStreamWaitEvent(s2, e1, 0);
    sgemm_t<0, 1><<<fgrid(ROWS, DD), 256, GS, s2>>>(ROWS, DD, KF, pFrames, KF, pBspec, DDp, pSpecT, ROWS, nullptr);
    k_win<<<1, Nfft, 0, s2>>>();
    k_emat<<<DD, Nfft, 0, s2>>>();
    cudaEventRecord(e2, s2);

    // ---- branch A (default stream): critical LSTM chain ----
    k_pack_wih<<<(DD * GG + 255) / 256, 256>>>(W_ih, b_ih, b_hh);
    // GEMM0: BW[320,512] = Bspec[320,514] @ WihT[514,512]  (12 tiles)
    sgemm_t<0, 0><<<pgrid(KF, GG), 256, GS>>>(KF, GG, DD, pBspec, DDp, pWihT, GG, pBW, GG, nullptr);
    // GEMM1b: xw[ROWS][512] = frames @ BW + bias
    sgemm_t<0, 0><<<fgrid(ROWS, GG), 256, GS>>>(ROWS, GG, KF, pFrames, KF, pBW, GG, pXw, GG, pBiasxw);
    lstm_k<<<NS, 512, LSMEM>>>(W_hh);
    k_pack_wmask<<<NM, HH>>>(W1, b1, W2, b2);
    sgemm_t<0, 1><<<fgrid(ROWS, NM), 256, GS>>>(ROWS, NM, HH, pH, HH, pWmask, NM, pMasksT, ROWS, pBmask);

    // ---- join: psd needs specT (branch B) + masksT (branch A) ----
    cudaStreamWaitEvent(0, e2, 0);
    psd_k<<<Bb * Fq, 256>>>();
    solve_k<<<(Bb * Fq + 31) / 32, 32>>>();
    beam_k<<<Bb * Fq, 256>>>();
    // GEMM3: fout[4808,512] = enhT^T[4808,514] @ Emat[514,512]
    sgemm_t<1, 0><<<pgrid(BT, Nfft), 256, GS>>>(BT, Nfft, DD, pEnhT, BT, pEmat, Nfft, pFout, Nfft, nullptr);
    k_ola<<<(Bb * Ll + 255) / 256, 256>>>(out);
}